// round 1
// baseline (speedup 1.0000x reference)
#include <cuda_runtime.h>
#include <math.h>

// ---------------- problem constants (fixed shape) ----------------
#define S_LEN 2048
#define NH    16
#define DH    64
#define DM    1024
#define DFF   4096
#define BATCH 2
#define ROWS  (BATCH * S_LEN)   // 4096

// ---------------- scratch (static device globals; no allocation) ----------------
__device__ float g_X [ROWS * DM];                     // LN outputs (reused)
__device__ float g_Q [BATCH * NH * S_LEN * DH];
__device__ float g_K [BATCH * NH * S_LEN * DH];
__device__ float g_V [BATCH * NH * S_LEN * DH];
__device__ float g_SC[134217728];                     // B*H*S*S scores/attn (536 MB)
__device__ float g_AT[BATCH * NH * S_LEN * DH];
__device__ float g_MG[ROWS * DM];                     // merged heads
__device__ float g_H1[ROWS * DM];                     // post-attention residual
__device__ float g_FF[ROWS * DFF];                    // FFN intermediate
__device__ float g_BT[NH * S_LEN];                    // per-head bias vs distance

// ---------------- relative-position bias table ----------------
// tab[h][d] = rel_bias[bucket(d)][h] for d = i-j in [0, S)
__global__ void biastab_kernel(const float* __restrict__ rel_bias,
                               float* __restrict__ tab) {
    int idx = blockIdx.x * blockDim.x + threadIdx.x;
    if (idx >= NH * S_LEN) return;
    int h = idx / S_LEN;
    int d = idx % S_LEN;
    int bucket;
    if (d < 16) {
        bucket = d;
    } else {
        // log(d/16)/log(128/16) * 16, truncated (d >= 16 so ratio >= 0)
        float ratio = logf((float)d * (1.0f / 16.0f)) / logf(8.0f);
        int large = 16 + (int)(ratio * 16.0f);
        bucket = large < 31 ? large : 31;
    }
    tab[h * S_LEN + d] = rel_bias[bucket * NH + h];
}

// ---------------- layernorm (one block per row, 1024 cols) ----------------
__global__ __launch_bounds__(256) void ln_kernel(const float* __restrict__ x,
                                                 const float* __restrict__ g,
                                                 const float* __restrict__ bta,
                                                 float* __restrict__ y) {
    int row = blockIdx.x;
    int t = threadIdx.x;
    const float4* xr = (const float4*)(x + (size_t)row * DM);
    float4 v = xr[t];
    float s  = v.x + v.y + v.z + v.w;
    float ss = v.x * v.x + v.y * v.y + v.z * v.z + v.w * v.w;
    __shared__ float sh_s[256], sh_q[256];
    sh_s[t] = s; sh_q[t] = ss;
    __syncthreads();
    for (int o = 128; o > 0; o >>= 1) {
        if (t < o) { sh_s[t] += sh_s[t + o]; sh_q[t] += sh_q[t + o]; }
        __syncthreads();
    }
    float mean = sh_s[0] * (1.0f / DM);
    float var  = sh_q[0] * (1.0f / DM) - mean * mean;
    float rstd = rsqrtf(var + 1e-5f);
    float4 gv = ((const float4*)g)[t];
    float4 bv = ((const float4*)bta)[t];
    float4 o4;
    o4.x = (v.x - mean) * rstd * gv.x + bv.x;
    o4.y = (v.y - mean) * rstd * gv.y + bv.y;
    o4.z = (v.z - mean) * rstd * gv.z + bv.z;
    o4.w = (v.w - mean) * rstd * gv.w + bv.w;
    ((float4*)(y + (size_t)row * DM))[t] = o4;
}

// ---------------- generic tiled SGEMM with fused epilogues ----------------
// C[M,N] = A[M,K] * op(B) (+ epilogue). 128x128 tile, Ktile=8, 256 threads, 8x8/thread.
// M always multiple of 128, K multiple of 8; N may be < tile (guarded).
enum { EPI_BIAS = 0, EPI_QKV = 1, EPI_NONE = 2, EPI_OPROJ = 3, EPI_GELU = 4, EPI_FINAL = 5 };

template <int TRANSB, int EPI>
__global__ __launch_bounds__(256) void sgemm(
    const float* __restrict__ A, const float* __restrict__ Bm,
    const float* __restrict__ bias, float* __restrict__ C,
    int M, int N, int K, int lda, int ldb, int ldc,
    long long sA, long long sB, long long sC,
    const float* __restrict__ aux1, const int* __restrict__ auxm,
    int causal_skip, int causal_klim) {
    int z = blockIdx.z;
    A  += (long long)z * sA;
    Bm += (long long)z * sB;
    C  += (long long)z * sC;
    int bn = blockIdx.x * 128;
    int bm = blockIdx.y * 128;
    if (causal_skip && bn >= bm + 128) return;   // strictly-upper tile: never read
    int Keff = K;
    if (causal_klim) { int kl = bm + 128; Keff = (K < kl) ? K : kl; }  // attn zeros beyond diag

    __shared__ float As[8][128];
    __shared__ float Bs[8][128];
    int tid = threadIdx.x;
    int tx = tid & 15, ty = tid >> 4;

    float acc[8][8];
#pragma unroll
    for (int i = 0; i < 8; i++)
#pragma unroll
        for (int j = 0; j < 8; j++) acc[i][j] = 0.0f;

    int arow = tid >> 1, akk = (tid & 1) * 4;       // A (and transposed-B) loader coords
    int brow = tid >> 5, bcol = (tid & 31) * 4;     // NN-B loader coords

    const float* Aptr = A + (size_t)(bm + arow) * lda + akk;

    for (int k0 = 0; k0 < Keff; k0 += 8) {
        float4 av = *(const float4*)(Aptr + k0);
        float4 bv;
        if (TRANSB) {
            bv = *(const float4*)(Bm + (size_t)(bn + arow) * ldb + k0 + akk);
        } else {
            if (bn + bcol < N) bv = *(const float4*)(Bm + (size_t)(k0 + brow) * ldb + bn + bcol);
            else               bv = make_float4(0.f, 0.f, 0.f, 0.f);
        }
        __syncthreads();
        As[akk + 0][arow] = av.x; As[akk + 1][arow] = av.y;
        As[akk + 2][arow] = av.z; As[akk + 3][arow] = av.w;
        if (TRANSB) {
            Bs[akk + 0][arow] = bv.x; Bs[akk + 1][arow] = bv.y;
            Bs[akk + 2][arow] = bv.z; Bs[akk + 3][arow] = bv.w;
        } else {
            *(float4*)&Bs[brow][bcol] = bv;
        }
        __syncthreads();
#pragma unroll
        for (int kk = 0; kk < 8; kk++) {
            float4 a0 = *(const float4*)&As[kk][ty * 8];
            float4 a1 = *(const float4*)&As[kk][ty * 8 + 4];
            float4 b0 = *(const float4*)&Bs[kk][tx * 8];
            float4 b1 = *(const float4*)&Bs[kk][tx * 8 + 4];
            float ar[8] = {a0.x, a0.y, a0.z, a0.w, a1.x, a1.y, a1.z, a1.w};
            float br[8] = {b0.x, b0.y, b0.z, b0.w, b1.x, b1.y, b1.z, b1.w};
#pragma unroll
            for (int i = 0; i < 8; i++)
#pragma unroll
                for (int j = 0; j < 8; j++) acc[i][j] += ar[i] * br[j];
        }
    }

#pragma unroll
    for (int i = 0; i < 8; i++) {
        int gm = bm + ty * 8 + i;
#pragma unroll
        for (int j = 0; j < 8; j++) {
            int gn = bn + tx * 8 + j;
            if (gn >= N) continue;
            float v = acc[i][j];
            if (EPI == EPI_BIAS) {
                C[(size_t)gm * ldc + gn] = v + bias[gn];
            } else if (EPI == EPI_NONE) {
                C[(size_t)gm * ldc + gn] = v;
            } else if (EPI == EPI_QKV) {
                // scatter [ROWS, DM] -> [B, H, S, DH]
                int b = gm >> 11, s = gm & (S_LEN - 1);
                int h = gn >> 6,  dh = gn & 63;
                C[(((size_t)(b * NH + h) * S_LEN + s) << 6) + dh] = v + bias[gn];
            } else if (EPI == EPI_OPROJ) {
                float mk = (float)auxm[gm];       // attention_mask[b, s], gm = b*S+s
                C[(size_t)gm * ldc + gn] = aux1[(size_t)gm * ldc + gn] + (v + bias[gn]) * mk;
            } else if (EPI == EPI_GELU) {
                float u = v + bias[gn];
                C[(size_t)gm * ldc + gn] = 0.5f * u * (1.0f + erff(u * 0.70710678118654752f));
            } else if (EPI == EPI_FINAL) {
                float mk = (float)auxm[gm];
                C[(size_t)gm * ldc + gn] = (aux1[(size_t)gm * ldc + gn] + v + bias[gn]) * mk;
            }
        }
    }
}

// ---------------- fused scale + rel-bias + causal + pad-mask softmax ----------------
__global__ __launch_bounds__(256) void softmax_kernel(float* __restrict__ sc,
                                                      const float* __restrict__ bt,
                                                      const int* __restrict__ mask) {
    int row = blockIdx.x;                     // b*H*S + h*S + q
    int q = row & (S_LEN - 1);
    int h = (row >> 11) & (NH - 1);
    int b = row >> 15;
    float* sp = sc + (size_t)row * S_LEN;
    const float* btr = bt + h * S_LEN;
    const int* mr = mask + b * S_LEN;
    int t = threadIdx.x;
    const float scale = 0.125f;               // 64^-0.5

    float mx = __int_as_float(0xff800000);    // -inf
    for (int k = t; k <= q; k += 256) {
        if (mr[k]) {
            float v = sp[k] * scale + btr[q - k];
            mx = fmaxf(mx, v);
        }
    }
    __shared__ float sh[256];
    sh[t] = mx;
    __syncthreads();
    for (int o = 128; o > 0; o >>= 1) {
        if (t < o) sh[t] = fmaxf(sh[t], sh[t + o]);
        __syncthreads();
    }
    mx = sh[0];
    __syncthreads();

    float sum = 0.0f;
    for (int k = t; k <= q; k += 256) {
        float e = 0.0f;
        if (mr[k]) e = expf(sp[k] * scale + btr[q - k] - mx);
        sp[k] = e;
        sum += e;
    }
    sh[t] = sum;
    __syncthreads();
    for (int o = 128; o > 0; o >>= 1) {
        if (t < o) sh[t] += sh[t + o];
        __syncthreads();
    }
    float tot = sh[0];
    float inv = (tot > 0.0f) ? 1.0f / tot : 0.0f;   // nan_to_num for fully masked rows
    for (int k = t; k < S_LEN; k += 256) {
        float v = (k <= q) ? sp[k] * inv : 0.0f;    // exact zeros above diagonal
        sp[k] = v;
    }
}

// ---------------- [B,H,S,DH] -> [B,S,H*DH] merge ----------------
__global__ __launch_bounds__(256) void merge_kernel(const float* __restrict__ att,
                                                    float* __restrict__ out) {
    int idx = blockIdx.x * 256 + threadIdx.x;       // float4 index over ROWS*DM/4
    int m = idx >> 8;                               // row in [0, ROWS)
    int c = (idx & 255) * 4;                        // col in [0, DM)
    int b = m >> 11, s = m & (S_LEN - 1);
    int h = c >> 6,  dh = c & 63;
    ((float4*)out)[idx] =
        ((const float4*)(att + (((size_t)(b * NH + h) * S_LEN + s) << 6)))[dh >> 2];
}

// ---------------- launch ----------------
extern "C" void kernel_launch(void* const* d_in, const int* in_sizes, int n_in,
                              void* d_out, int out_size) {
    const float* hidden = (const float*)d_in[0];
    const int*   mask   = (const int*)d_in[1];
    const float* wq = (const float*)d_in[2];  const float* bq = (const float*)d_in[3];
    const float* wk = (const float*)d_in[4];  const float* bk = (const float*)d_in[5];
    const float* wv = (const float*)d_in[6];  const float* bv = (const float*)d_in[7];
    const float* wo = (const float*)d_in[8];  const float* bo = (const float*)d_in[9];
    const float* rb = (const float*)d_in[10];
    const float* ln1g = (const float*)d_in[11]; const float* ln1b = (const float*)d_in[12];
    const float* ln2g = (const float*)d_in[13]; const float* ln2b = (const float*)d_in[14];
    const float* w1 = (const float*)d_in[15]; const float* b1 = (const float*)d_in[16];
    const float* w2 = (const float*)d_in[17]; const float* b2 = (const float*)d_in[18];
    float* out = (float*)d_out;

    float *X, *Q, *K, *V, *SC, *AT, *MG, *H1, *FFb, *BT;
    cudaGetSymbolAddress((void**)&X,  g_X);
    cudaGetSymbolAddress((void**)&Q,  g_Q);
    cudaGetSymbolAddress((void**)&K,  g_K);
    cudaGetSymbolAddress((void**)&V,  g_V);
    cudaGetSymbolAddress((void**)&SC, g_SC);
    cudaGetSymbolAddress((void**)&AT, g_AT);
    cudaGetSymbolAddress((void**)&MG, g_MG);
    cudaGetSymbolAddress((void**)&H1, g_H1);
    cudaGetSymbolAddress((void**)&FFb, g_FF);
    cudaGetSymbolAddress((void**)&BT, g_BT);

    // 0) relative-position bias table
    biastab_kernel<<<(NH * S_LEN + 255) / 256, 256>>>(rb, BT);
    // 1) LN1
    ln_kernel<<<ROWS, 256>>>(hidden, ln1g, ln1b, X);

    // 2) QKV projections (scatter into [B,H,S,DH])
    dim3 gProj(DM / 128, ROWS / 128, 1);
    sgemm<0, EPI_QKV><<<gProj, 256>>>(X, wq, bq, Q, ROWS, DM, DM, DM, DM, 0,
                                      0, 0, 0, nullptr, nullptr, 0, 0);
    sgemm<0, EPI_QKV><<<gProj, 256>>>(X, wk, bk, K, ROWS, DM, DM, DM, DM, 0,
                                      0, 0, 0, nullptr, nullptr, 0, 0);
    sgemm<0, EPI_QKV><<<gProj, 256>>>(X, wv, bv, V, ROWS, DM, DM, DM, DM, 0,
                                      0, 0, 0, nullptr, nullptr, 0, 0);

    // 3) scores = Q @ K^T per (b,h); skip strictly-upper tiles (causal)
    dim3 gSc(S_LEN / 128, S_LEN / 128, BATCH * NH);
    sgemm<1, EPI_NONE><<<gSc, 256>>>(Q, K, nullptr, SC, S_LEN, S_LEN, DH, DH, DH, S_LEN,
                                     (long long)S_LEN * DH, (long long)S_LEN * DH,
                                     (long long)S_LEN * S_LEN, nullptr, nullptr, 1, 0);

    // 4) fused scale + bias + causal + pad-mask softmax (writes zeros above diag)
    softmax_kernel<<<BATCH * NH * S_LEN, 256>>>(SC, BT, mask);

    // 5) attended = attn @ V; K truncated to diagonal tile (zeros beyond)
    dim3 gPV(1, S_LEN / 128, BATCH * NH);
    sgemm<0, EPI_NONE><<<gPV, 256>>>(SC, V, nullptr, AT, S_LEN, DH, S_LEN, S_LEN, DH, DH,
                                     (long long)S_LEN * S_LEN, (long long)S_LEN * DH,
                                     (long long)S_LEN * DH, nullptr, nullptr, 0, 1);

    // 6) merge heads
    merge_kernel<<<ROWS * DM / 1024, 256>>>(AT, MG);

    // 7) O projection + mask + residual -> h1
    sgemm<0, EPI_OPROJ><<<gProj, 256>>>(MG, wo, bo, H1, ROWS, DM, DM, DM, DM, DM,
                                        0, 0, 0, hidden, mask, 0, 0);

    // 8) LN2
    ln_kernel<<<ROWS, 256>>>(H1, ln2g, ln2b, X);

    // 9) FFN up + exact GELU
    dim3 gF1(DFF / 128, ROWS / 128, 1);
    sgemm<0, EPI_GELU><<<gF1, 256>>>(X, w1, b1, FFb, ROWS, DFF, DM, DM, DFF, DFF,
                                     0, 0, 0, nullptr, nullptr, 0, 0);

    // 10) FFN down + residual + mask -> out
    sgemm<0, EPI_FINAL><<<gProj, 256>>>(FFb, w2, b2, out, ROWS, DM, DFF, DFF, DM, DM,
                                        0, 0, 0, H1, mask, 0, 0);
}

// round 2
// speedup vs baseline: 2.6014x; 2.6014x over previous
#include <cuda_runtime.h>
#include <math.h>
#include <stdint.h>

// ---------------- problem constants (fixed shape) ----------------
#define S_LEN 2048
#define NH    16
#define DH    64
#define DM    1024
#define DFF   4096
#define BATCH 2
#define ROWS  (BATCH * S_LEN)   // 4096

// ---------------- scratch (static device globals; no allocation) ----------------
__device__ float g_X [ROWS * DM];
__device__ float g_Q [BATCH * NH * S_LEN * DH];
__device__ float g_K [BATCH * NH * S_LEN * DH];
__device__ float g_V [BATCH * NH * S_LEN * DH];
__device__ float g_SC[134217728];                     // B*H*S*S scores/attn
__device__ float g_AT[BATCH * NH * S_LEN * DH];
__device__ float g_MG[ROWS * DM];
__device__ float g_H1[ROWS * DM];
__device__ float g_FF[ROWS * DFF];
__device__ float g_BT[NH * S_LEN];

// ---------------- helpers ----------------
__device__ __forceinline__ uint32_t f2tf(float f) {
    uint32_t u;
    asm("cvt.rna.tf32.f32 %0, %1;" : "=r"(u) : "f"(f));
    return u;
}

__device__ __forceinline__ void mma_tf32(float* d, const uint32_t* a, const uint32_t* b) {
    asm volatile(
        "mma.sync.aligned.m16n8k8.row.col.f32.tf32.tf32.f32 "
        "{%0,%1,%2,%3}, {%4,%5,%6,%7}, {%8,%9}, {%0,%1,%2,%3};"
        : "+f"(d[0]), "+f"(d[1]), "+f"(d[2]), "+f"(d[3])
        : "r"(a[0]), "r"(a[1]), "r"(a[2]), "r"(a[3]), "r"(b[0]), "r"(b[1]));
}

// ---------------- relative-position bias table ----------------
__global__ void biastab_kernel(const float* __restrict__ rel_bias,
                               float* __restrict__ tab) {
    int idx = blockIdx.x * blockDim.x + threadIdx.x;
    if (idx >= NH * S_LEN) return;
    int h = idx / S_LEN;
    int d = idx % S_LEN;
    int bucket;
    if (d < 16) {
        bucket = d;
    } else {
        float ratio = logf((float)d * (1.0f / 16.0f)) / logf(8.0f);
        int large = 16 + (int)(ratio * 16.0f);
        bucket = large < 31 ? large : 31;
    }
    tab[h * S_LEN + d] = rel_bias[bucket * NH + h];
}

// ---------------- layernorm ----------------
__global__ __launch_bounds__(256) void ln_kernel(const float* __restrict__ x,
                                                 const float* __restrict__ g,
                                                 const float* __restrict__ bta,
                                                 float* __restrict__ y) {
    int row = blockIdx.x;
    int t = threadIdx.x;
    const float4* xr = (const float4*)(x + (size_t)row * DM);
    float4 v = xr[t];
    float s  = v.x + v.y + v.z + v.w;
    float ss = v.x * v.x + v.y * v.y + v.z * v.z + v.w * v.w;
    __shared__ float sh_s[256], sh_q[256];
    sh_s[t] = s; sh_q[t] = ss;
    __syncthreads();
    for (int o = 128; o > 0; o >>= 1) {
        if (t < o) { sh_s[t] += sh_s[t + o]; sh_q[t] += sh_q[t + o]; }
        __syncthreads();
    }
    float mean = sh_s[0] * (1.0f / DM);
    float var  = sh_q[0] * (1.0f / DM) - mean * mean;
    float rstd = rsqrtf(var + 1e-5f);
    float4 gv = ((const float4*)g)[t];
    float4 bv = ((const float4*)bta)[t];
    float4 o4;
    o4.x = (v.x - mean) * rstd * gv.x + bv.x;
    o4.y = (v.y - mean) * rstd * gv.y + bv.y;
    o4.z = (v.z - mean) * rstd * gv.z + bv.z;
    o4.w = (v.w - mean) * rstd * gv.w + bv.w;
    ((float4*)(y + (size_t)row * DM))[t] = o4;
}

// ---------------- tf32 tensor-core GEMM with fused epilogues ----------------
// C[M,N] = A[M,K] * op(B). Tile 128x128, BK=16 double-buffered, 256 threads,
// 8 warps in a 2x4 grid, each computing a 64x32 warp tile via m16n8k8 tf32 mma.
// M multiple of 128, K multiple of 16, N multiple of 4 (guarded vs tile).
enum { EPI_BIAS = 0, EPI_QKV = 1, EPI_NONE = 2, EPI_OPROJ = 3, EPI_GELU = 4, EPI_FINAL = 5 };

template <int TRANSB, int EPI>
__global__ __launch_bounds__(256) void mgemm(
    const float* __restrict__ A, const float* __restrict__ Bm,
    const float* __restrict__ bias, float* __restrict__ C,
    int M, int N, int K, int lda, int ldb, int ldc,
    long long sA, long long sB, long long sC,
    const float* __restrict__ aux1, const int* __restrict__ auxm,
    int causal_skip, int causal_klim) {
    int z = blockIdx.z;
    A  += (long long)z * sA;
    Bm += (long long)z * sB;
    C  += (long long)z * sC;
    int bn = blockIdx.x * 128;
    int bm = blockIdx.y * 128;
    if (causal_skip && bn >= bm + 128) return;
    int Keff = K;
    if (causal_klim) { int kl = bm + 128; Keff = (K < kl) ? K : kl; }

    // A: [m][k] rows of 20 u32 (16 data + 4 pad) -> bank = (m*20+k)%32, conflict-free frags
    __shared__ uint32_t As[2][128][20];
    // B: TRANSB: [n][k] stride 20; NT: [k][n] stride 136 (bank = k*8+n, conflict-free)
    constexpr int BSY = TRANSB ? 128 : 16;
    constexpr int BSX = TRANSB ? 20 : 136;
    __shared__ uint32_t Bs[2][BSY][BSX];

    int tid = threadIdx.x;
    int lane = tid & 31;
    int w = tid >> 5;
    int wm = (w & 1) * 64;
    int wn = (w >> 1) * 32;

    float acc[4][4][4];
#pragma unroll
    for (int mi = 0; mi < 4; mi++)
#pragma unroll
        for (int ni = 0; ni < 4; ni++)
#pragma unroll
            for (int r = 0; r < 4; r++) acc[mi][ni][r] = 0.0f;

    // ---- staging coordinates ----
    int am = tid >> 2;            // A rows am, am+64; float4 at col (tid&3)*4
    int akq = (tid & 3) * 4;
    const float* Ap0 = A + (size_t)(bm + am) * lda + akq;
    const float* Ap1 = A + (size_t)(bm + am + 64) * lda + akq;

    // B staging
    int bkr = tid >> 5;           // NT: k rows bkr, bkr+8; float4 at col (tid&31)*4
    int bn4 = (tid & 31) * 4;
    int bgc = bn + bn4;
    bool bvalid = (bgc < N);      // N multiple of 4, bgc aligned 4
    const float* BpNT = Bm + (size_t)bkr * ldb + bgc;
    // T: n rows am-style
    const float* BpT0 = Bm + (size_t)(bn + am) * ldb + akq;
    const float* BpT1 = Bm + (size_t)(bn + am + 64) * ldb + akq;

    int ntiles = Keff >> 4;

    float4 av0, av1, bv0, bv1;
    // prologue: load tile 0
    av0 = *(const float4*)(Ap0);
    av1 = *(const float4*)(Ap1);
    if (TRANSB) {
        bv0 = *(const float4*)(BpT0);
        bv1 = *(const float4*)(BpT1);
    } else {
        bv0 = bvalid ? *(const float4*)(BpNT) : make_float4(0.f, 0.f, 0.f, 0.f);
        bv1 = bvalid ? *(const float4*)(BpNT + 8 * (size_t)ldb) : make_float4(0.f, 0.f, 0.f, 0.f);
    }
    {
        *(uint4*)&As[0][am][akq]      = make_uint4(f2tf(av0.x), f2tf(av0.y), f2tf(av0.z), f2tf(av0.w));
        *(uint4*)&As[0][am + 64][akq] = make_uint4(f2tf(av1.x), f2tf(av1.y), f2tf(av1.z), f2tf(av1.w));
        if (TRANSB) {
            *(uint4*)&Bs[0][am][akq]             = make_uint4(f2tf(bv0.x), f2tf(bv0.y), f2tf(bv0.z), f2tf(bv0.w));
            *(uint4*)&Bs[0][(am + 64) % BSY][akq] = make_uint4(f2tf(bv1.x), f2tf(bv1.y), f2tf(bv1.z), f2tf(bv1.w));
        } else {
            *(uint4*)&Bs[0][bkr % BSY][bn4 % BSX]       = make_uint4(f2tf(bv0.x), f2tf(bv0.y), f2tf(bv0.z), f2tf(bv0.w));
            *(uint4*)&Bs[0][(bkr + 8) % BSY][bn4 % BSX] = make_uint4(f2tf(bv1.x), f2tf(bv1.y), f2tf(bv1.z), f2tf(bv1.w));
        }
    }
    __syncthreads();

    int buf = 0;
    for (int kt = 0; kt < ntiles; kt++) {
        bool more = (kt + 1 < ntiles);
        if (more) {
            int k0 = (kt + 1) * 16;
            av0 = *(const float4*)(Ap0 + k0);
            av1 = *(const float4*)(Ap1 + k0);
            if (TRANSB) {
                bv0 = *(const float4*)(BpT0 + k0);
                bv1 = *(const float4*)(BpT1 + k0);
            } else {
                bv0 = bvalid ? *(const float4*)(BpNT + (size_t)k0 * ldb) : make_float4(0.f, 0.f, 0.f, 0.f);
                bv1 = bvalid ? *(const float4*)(BpNT + (size_t)(k0 + 8) * ldb) : make_float4(0.f, 0.f, 0.f, 0.f);
            }
        }

        // compute: 2 k-steps of 8
#pragma unroll
        for (int ks = 0; ks < 2; ks++) {
            int k8 = ks * 8;
            uint32_t afrag[4][4], bfrag[4][2];
            int r = lane >> 2, c = lane & 3;
#pragma unroll
            for (int mi = 0; mi < 4; mi++) {
                int r0 = wm + mi * 16 + r;
                afrag[mi][0] = As[buf][r0][k8 + c];
                afrag[mi][1] = As[buf][r0 + 8][k8 + c];
                afrag[mi][2] = As[buf][r0][k8 + c + 4];
                afrag[mi][3] = As[buf][r0 + 8][k8 + c + 4];
            }
#pragma unroll
            for (int ni = 0; ni < 4; ni++) {
                int nb = wn + ni * 8 + r;
                if (TRANSB) {
                    bfrag[ni][0] = Bs[buf][nb % BSY][(k8 + c) % BSX];
                    bfrag[ni][1] = Bs[buf][nb % BSY][(k8 + c + 4) % BSX];
                } else {
                    bfrag[ni][0] = Bs[buf][(k8 + c) % BSY][nb % BSX];
                    bfrag[ni][1] = Bs[buf][(k8 + c + 4) % BSY][nb % BSX];
                }
            }
#pragma unroll
            for (int mi = 0; mi < 4; mi++)
#pragma unroll
                for (int ni = 0; ni < 4; ni++)
                    mma_tf32(acc[mi][ni], afrag[mi], bfrag[ni]);
        }

        if (more) {
            int nb2 = buf ^ 1;
            *(uint4*)&As[nb2][am][akq]      = make_uint4(f2tf(av0.x), f2tf(av0.y), f2tf(av0.z), f2tf(av0.w));
            *(uint4*)&As[nb2][am + 64][akq] = make_uint4(f2tf(av1.x), f2tf(av1.y), f2tf(av1.z), f2tf(av1.w));
            if (TRANSB) {
                *(uint4*)&Bs[nb2][am][akq]             = make_uint4(f2tf(bv0.x), f2tf(bv0.y), f2tf(bv0.z), f2tf(bv0.w));
                *(uint4*)&Bs[nb2][(am + 64) % BSY][akq] = make_uint4(f2tf(bv1.x), f2tf(bv1.y), f2tf(bv1.z), f2tf(bv1.w));
            } else {
                *(uint4*)&Bs[nb2][bkr % BSY][bn4 % BSX]       = make_uint4(f2tf(bv0.x), f2tf(bv0.y), f2tf(bv0.z), f2tf(bv0.w));
                *(uint4*)&Bs[nb2][(bkr + 8) % BSY][bn4 % BSX] = make_uint4(f2tf(bv1.x), f2tf(bv1.y), f2tf(bv1.z), f2tf(bv1.w));
            }
        }
        __syncthreads();
        buf ^= 1;
    }

    // ---- epilogue ----
    int r = lane >> 2, c = lane & 3;
#pragma unroll
    for (int mi = 0; mi < 4; mi++) {
#pragma unroll
        for (int ni = 0; ni < 4; ni++) {
            int r0 = bm + wm + mi * 16 + r;
            int cn = bn + wn + ni * 8 + c * 2;
#pragma unroll
            for (int h2 = 0; h2 < 2; h2++) {
                int gm = r0 + h2 * 8;
#pragma unroll
                for (int j = 0; j < 2; j++) {
                    int gn = cn + j;
                    if (gn >= N) continue;
                    float v = acc[mi][ni][h2 * 2 + j];
                    if (EPI == EPI_BIAS) {
                        C[(size_t)gm * ldc + gn] = v + bias[gn];
                    } else if (EPI == EPI_NONE) {
                        C[(size_t)gm * ldc + gn] = v;
                    } else if (EPI == EPI_QKV) {
                        int b = gm >> 11, s = gm & (S_LEN - 1);
                        int h = gn >> 6,  dh = gn & 63;
                        C[(((size_t)(b * NH + h) * S_LEN + s) << 6) + dh] = v + bias[gn];
                    } else if (EPI == EPI_OPROJ) {
                        float mk = (float)auxm[gm];
                        C[(size_t)gm * ldc + gn] = aux1[(size_t)gm * ldc + gn] + (v + bias[gn]) * mk;
                    } else if (EPI == EPI_GELU) {
                        float u = v + bias[gn];
                        C[(size_t)gm * ldc + gn] = 0.5f * u * (1.0f + erff(u * 0.70710678118654752f));
                    } else if (EPI == EPI_FINAL) {
                        float mk = (float)auxm[gm];
                        C[(size_t)gm * ldc + gn] = (aux1[(size_t)gm * ldc + gn] + v + bias[gn]) * mk;
                    }
                }
            }
        }
    }
}

// ---------------- fused softmax (single read / single write via smem cache) ----------------
__global__ __launch_bounds__(256) void softmax_kernel(float* __restrict__ sc,
                                                      const float* __restrict__ bt,
                                                      const int* __restrict__ mask) {
    __shared__ float buf[S_LEN];
    __shared__ float red[256];
    int row = blockIdx.x;
    int q = row & (S_LEN - 1);
    int h = (row >> 11) & (NH - 1);
    int b = row >> 15;
    float* sp = sc + (size_t)row * S_LEN;
    const float* btr = bt + h * S_LEN;
    const int* mr = mask + b * S_LEN;
    int t = threadIdx.x;
    const float NEG = __int_as_float(0xff800000);

    float mx = NEG;
    for (int k = t; k <= q; k += 256) {
        float v = mr[k] ? sp[k] * 0.125f + btr[q - k] : NEG;
        buf[k] = v;
        mx = fmaxf(mx, v);
    }
    red[t] = mx;
    __syncthreads();
    for (int o = 128; o > 0; o >>= 1) {
        if (t < o) red[t] = fmaxf(red[t], red[t + o]);
        __syncthreads();
    }
    mx = red[0];
    __syncthreads();

    float sum = 0.0f;
    for (int k = t; k <= q; k += 256) {
        float v = buf[k];
        float e = (v == NEG) ? 0.0f : expf(v - mx);
        buf[k] = e;
        sum += e;
    }
    red[t] = sum;
    __syncthreads();
    for (int o = 128; o > 0; o >>= 1) {
        if (t < o) red[t] += red[t + o];
        __syncthreads();
    }
    float tot = red[0];
    float inv = (tot > 0.0f) ? 1.0f / tot : 0.0f;
    for (int k = t; k < S_LEN; k += 256) {
        sp[k] = (k <= q) ? buf[k] * inv : 0.0f;
    }
}

// ---------------- [B,H,S,DH] -> [B,S,H*DH] merge ----------------
__global__ __launch_bounds__(256) void merge_kernel(const float* __restrict__ att,
                                                    float* __restrict__ out) {
    int idx = blockIdx.x * 256 + threadIdx.x;
    int m = idx >> 8;
    int c = (idx & 255) * 4;
    int b = m >> 11, s = m & (S_LEN - 1);
    int h = c >> 6,  dh = c & 63;
    ((float4*)out)[idx] =
        ((const float4*)(att + (((size_t)(b * NH + h) * S_LEN + s) << 6)))[dh >> 2];
}

// ---------------- launch ----------------
extern "C" void kernel_launch(void* const* d_in, const int* in_sizes, int n_in,
                              void* d_out, int out_size) {
    const float* hidden = (const float*)d_in[0];
    const int*   mask   = (const int*)d_in[1];
    const float* wq = (const float*)d_in[2];  const float* bq = (const float*)d_in[3];
    const float* wk = (const float*)d_in[4];  const float* bk = (const float*)d_in[5];
    const float* wv = (const float*)d_in[6];  const float* bv = (const float*)d_in[7];
    const float* wo = (const float*)d_in[8];  const float* bo = (const float*)d_in[9];
    const float* rb = (const float*)d_in[10];
    const float* ln1g = (const float*)d_in[11]; const float* ln1b = (const float*)d_in[12];
    const float* ln2g = (const float*)d_in[13]; const float* ln2b = (const float*)d_in[14];
    const float* w1 = (const float*)d_in[15]; const float* b1 = (const float*)d_in[16];
    const float* w2 = (const float*)d_in[17]; const float* b2 = (const float*)d_in[18];
    float* out = (float*)d_out;

    float *X, *Q, *K, *V, *SC, *AT, *MG, *H1, *FFb, *BT;
    cudaGetSymbolAddress((void**)&X,  g_X);
    cudaGetSymbolAddress((void**)&Q,  g_Q);
    cudaGetSymbolAddress((void**)&K,  g_K);
    cudaGetSymbolAddress((void**)&V,  g_V);
    cudaGetSymbolAddress((void**)&SC, g_SC);
    cudaGetSymbolAddress((void**)&AT, g_AT);
    cudaGetSymbolAddress((void**)&MG, g_MG);
    cudaGetSymbolAddress((void**)&H1, g_H1);
    cudaGetSymbolAddress((void**)&FFb, g_FF);
    cudaGetSymbolAddress((void**)&BT, g_BT);

    biastab_kernel<<<(NH * S_LEN + 255) / 256, 256>>>(rb, BT);
    ln_kernel<<<ROWS, 256>>>(hidden, ln1g, ln1b, X);

    // QKV projections (scatter into [B,H,S,DH])
    dim3 gProj(DM / 128, ROWS / 128, 1);
    mgemm<0, EPI_QKV><<<gProj, 256>>>(X, wq, bq, Q, ROWS, DM, DM, DM, DM, 0,
                                      0, 0, 0, nullptr, nullptr, 0, 0);
    mgemm<0, EPI_QKV><<<gProj, 256>>>(X, wk, bk, K, ROWS, DM, DM, DM, DM, 0,
                                      0, 0, 0, nullptr, nullptr, 0, 0);
    mgemm<0, EPI_QKV><<<gProj, 256>>>(X, wv, bv, V, ROWS, DM, DM, DM, DM, 0,
                                      0, 0, 0, nullptr, nullptr, 0, 0);

    // scores = Q @ K^T per (b,h); causal tile skip
    dim3 gSc(S_LEN / 128, S_LEN / 128, BATCH * NH);
    mgemm<1, EPI_NONE><<<gSc, 256>>>(Q, K, nullptr, SC, S_LEN, S_LEN, DH, DH, DH, S_LEN,
                                     (long long)S_LEN * DH, (long long)S_LEN * DH,
                                     (long long)S_LEN * S_LEN, nullptr, nullptr, 1, 0);

    softmax_kernel<<<BATCH * NH * S_LEN, 256>>>(SC, BT, mask);

    // attended = attn @ V with causal K-truncation
    dim3 gPV(1, S_LEN / 128, BATCH * NH);
    mgemm<0, EPI_NONE><<<gPV, 256>>>(SC, V, nullptr, AT, S_LEN, DH, S_LEN, S_LEN, DH, DH,
                                     (long long)S_LEN * S_LEN, (long long)S_LEN * DH,
                                     (long long)S_LEN * DH, nullptr, nullptr, 0, 1);

    merge_kernel<<<ROWS * DM / 1024, 256>>>(AT, MG);

    // O projection + mask + residual
    mgemm<0, EPI_OPROJ><<<gProj, 256>>>(MG, wo, bo, H1, ROWS, DM, DM, DM, DM, DM,
                                        0, 0, 0, hidden, mask, 0, 0);

    ln_kernel<<<ROWS, 256>>>(H1, ln2g, ln2b, X);

    // FFN up + exact GELU
    dim3 gF1(DFF / 128, ROWS / 128, 1);
    mgemm<0, EPI_GELU><<<gF1, 256>>>(X, w1, b1, FFb, ROWS, DFF, DM, DM, DFF, DFF,
                                     0, 0, 0, nullptr, nullptr, 0, 0);

    // FFN down + residual + mask
    mgemm<0, EPI_FINAL><<<gProj, 256>>>(FFb, w2, b2, out, ROWS, DM, DFF, DFF, DM, DM,
                                        0, 0, 0, H1, mask, 0, 0);
}

// round 3
// speedup vs baseline: 2.6966x; 1.0366x over previous
#include <cuda_runtime.h>
#include <math.h>
#include <stdint.h>

// ---------------- problem constants (fixed shape) ----------------
#define S_LEN 2048
#define NH    16
#define DH    64
#define DM    1024
#define DFF   4096
#define BATCH 2
#define ROWS  (BATCH * S_LEN)   // 4096

// ---------------- scratch (static device globals; no allocation) ----------------
__device__ float g_X [ROWS * DM];
__device__ float g_Q [BATCH * NH * S_LEN * DH];
__device__ float g_K [BATCH * NH * S_LEN * DH];
__device__ float g_V [BATCH * NH * S_LEN * DH];
__device__ float g_SC[134217728];                     // B*H*S*S scores/attn
__device__ float g_AT[BATCH * NH * S_LEN * DH];
__device__ float g_MG[ROWS * DM];
__device__ float g_H1[ROWS * DM];
__device__ float g_FF[ROWS * DFF];
__device__ float g_BT[NH * S_LEN];

// ---------------- helpers ----------------
__device__ __forceinline__ uint32_t f2tf(float f) {
    uint32_t u;
    asm("cvt.rna.tf32.f32 %0, %1;" : "=r"(u) : "f"(f));
    return u;
}

__device__ __forceinline__ void mma_tf32(float* d, const uint32_t* a, const uint32_t* b) {
    asm volatile(
        "mma.sync.aligned.m16n8k8.row.col.f32.tf32.tf32.f32 "
        "{%0,%1,%2,%3}, {%4,%5,%6,%7}, {%8,%9}, {%0,%1,%2,%3};"
        : "+f"(d[0]), "+f"(d[1]), "+f"(d[2]), "+f"(d[3])
        : "r"(a[0]), "r"(a[1]), "r"(a[2]), "r"(a[3]), "r"(b[0]), "r"(b[1]));
}

// ---------------- relative-position bias table ----------------
__global__ void biastab_kernel(const float* __restrict__ rel_bias,
                               float* __restrict__ tab) {
    int idx = blockIdx.x * blockDim.x + threadIdx.x;
    if (idx >= NH * S_LEN) return;
    int h = idx / S_LEN;
    int d = idx % S_LEN;
    int bucket;
    if (d < 16) {
        bucket = d;
    } else {
        float ratio = logf((float)d * (1.0f / 16.0f)) / logf(8.0f);
        int large = 16 + (int)(ratio * 16.0f);
        bucket = large < 31 ? large : 31;
    }
    tab[h * S_LEN + d] = rel_bias[bucket * NH + h];
}

// ---------------- layernorm ----------------
__global__ __launch_bounds__(256) void ln_kernel(const float* __restrict__ x,
                                                 const float* __restrict__ g,
                                                 const float* __restrict__ bta,
                                                 float* __restrict__ y) {
    int row = blockIdx.x;
    int t = threadIdx.x;
    const float4* xr = (const float4*)(x + (size_t)row * DM);
    float4 v = xr[t];
    float s  = v.x + v.y + v.z + v.w;
    float ss = v.x * v.x + v.y * v.y + v.z * v.z + v.w * v.w;
    __shared__ float sh_s[256], sh_q[256];
    sh_s[t] = s; sh_q[t] = ss;
    __syncthreads();
    for (int o = 128; o > 0; o >>= 1) {
        if (t < o) { sh_s[t] += sh_s[t + o]; sh_q[t] += sh_q[t + o]; }
        __syncthreads();
    }
    float mean = sh_s[0] * (1.0f / DM);
    float var  = sh_q[0] * (1.0f / DM) - mean * mean;
    float rstd = rsqrtf(var + 1e-5f);
    float4 gv = ((const float4*)g)[t];
    float4 bv = ((const float4*)bta)[t];
    float4 o4;
    o4.x = (v.x - mean) * rstd * gv.x + bv.x;
    o4.y = (v.y - mean) * rstd * gv.y + bv.y;
    o4.z = (v.z - mean) * rstd * gv.z + bv.z;
    o4.w = (v.w - mean) * rstd * gv.w + bv.w;
    ((float4*)(y + (size_t)row * DM))[t] = o4;
}

// ---------------- tf32 tensor-core GEMM with fused epilogues ----------------
// C[M,N] = A[M,K] * op(B). Tile 128xBN, BK=16 double-buffered, 256 threads.
// BN=128: 8 warps (2x4), warp tile 64x32. BN=64: 8 warps (2x4), warp tile 64x16.
enum { EPI_BIAS = 0, EPI_QKV = 1, EPI_NONE = 2, EPI_OPROJ = 3, EPI_GELU = 4, EPI_FINAL = 5 };

template <int TRANSB, int EPI, int BN>
__global__ __launch_bounds__(256, 2) void mgemm(
    const float* __restrict__ A, const float* __restrict__ Bm,
    const float* __restrict__ bias, float* __restrict__ C,
    int M, int N, int K, int lda, int ldb, int ldc,
    long long sA, long long sB, long long sC,
    const float* __restrict__ aux1, const int* __restrict__ auxm,
    int causal_skip, int causal_klim) {
    int z = blockIdx.z;
    A  += (long long)z * sA;
    Bm += (long long)z * sB;
    C  += (long long)z * sC;
    int bn = blockIdx.x * BN;
    int bm = blockIdx.y * 128;
    if (causal_skip && bn >= bm + 128) return;
    int Keff = K;
    if (causal_klim) { int kl = bm + 128; Keff = (K < kl) ? K : kl; }

    constexpr int NI = (BN == 128) ? 4 : 2;     // n-tiles per warp (8 cols each)

    // A: [m][k] rows of 20 u32 (16 data + 4 pad): bank=(m*20+k)%32 -> conflict-free frags
    __shared__ uint32_t As[2][128][20];
    // B: TRANSB: [n][k] stride 20; NT: [k][n] stride BN+8 (conflict-free frags)
    constexpr int BSY = TRANSB ? BN : 16;
    constexpr int BSX = TRANSB ? 20 : (BN + 8);
    __shared__ uint32_t Bs[2][BSY][BSX];

    int tid = threadIdx.x;
    int lane = tid & 31;
    int w = tid >> 5;
    int wm = (w & 1) * 64;
    int wn = (w >> 1) * (BN / 4);               // 32 or 16

    float acc[4][NI][4];
#pragma unroll
    for (int mi = 0; mi < 4; mi++)
#pragma unroll
        for (int ni = 0; ni < NI; ni++)
#pragma unroll
            for (int r = 0; r < 4; r++) acc[mi][ni][r] = 0.0f;

    // ---- staging coordinates ----
    int am = tid >> 2;                          // A rows am, am+64
    int akq = (tid & 3) * 4;
    const float* Ap0 = A + (size_t)(bm + am) * lda + akq;
    const float* Ap1 = A + (size_t)(bm + am + 64) * lda + akq;

    // NT-B staging: BN=128: 2 loads (rows tid>>5, +8); BN=64: 1 load (rows tid>>4)
    int bkr = (BN == 128) ? (tid >> 5) : (tid >> 4);
    int bn4 = (BN == 128) ? ((tid & 31) * 4) : ((tid & 15) * 4);
    int bgc = bn + bn4;
    bool bvalid = (bgc < N);
    const float* BpNT = Bm + (size_t)bkr * ldb + bgc;
    // T-B staging (BN==128 only)
    const float* BpT0 = Bm + (size_t)(bn + am) * ldb + akq;
    const float* BpT1 = Bm + (size_t)(bn + am + 64) * ldb + akq;

    int ntiles = Keff >> 4;

    float4 av0, av1, bv0, bv1;
    av0 = *(const float4*)(Ap0);
    av1 = *(const float4*)(Ap1);
    if (TRANSB) {
        bv0 = *(const float4*)(BpT0);
        bv1 = *(const float4*)(BpT1);
    } else if (BN == 128) {
        bv0 = bvalid ? *(const float4*)(BpNT) : make_float4(0.f, 0.f, 0.f, 0.f);
        bv1 = bvalid ? *(const float4*)(BpNT + 8 * (size_t)ldb) : make_float4(0.f, 0.f, 0.f, 0.f);
    } else {
        bv0 = bvalid ? *(const float4*)(BpNT) : make_float4(0.f, 0.f, 0.f, 0.f);
    }
    {
        *(uint4*)&As[0][am][akq]      = make_uint4(f2tf(av0.x), f2tf(av0.y), f2tf(av0.z), f2tf(av0.w));
        *(uint4*)&As[0][am + 64][akq] = make_uint4(f2tf(av1.x), f2tf(av1.y), f2tf(av1.z), f2tf(av1.w));
        if (TRANSB) {
            *(uint4*)&Bs[0][am % BSY][akq % BSX]        = make_uint4(f2tf(bv0.x), f2tf(bv0.y), f2tf(bv0.z), f2tf(bv0.w));
            *(uint4*)&Bs[0][(am + 64) % BSY][akq % BSX] = make_uint4(f2tf(bv1.x), f2tf(bv1.y), f2tf(bv1.z), f2tf(bv1.w));
        } else if (BN == 128) {
            *(uint4*)&Bs[0][bkr % BSY][bn4 % BSX]       = make_uint4(f2tf(bv0.x), f2tf(bv0.y), f2tf(bv0.z), f2tf(bv0.w));
            *(uint4*)&Bs[0][(bkr + 8) % BSY][bn4 % BSX] = make_uint4(f2tf(bv1.x), f2tf(bv1.y), f2tf(bv1.z), f2tf(bv1.w));
        } else {
            *(uint4*)&Bs[0][bkr % BSY][bn4 % BSX]       = make_uint4(f2tf(bv0.x), f2tf(bv0.y), f2tf(bv0.z), f2tf(bv0.w));
        }
    }
    __syncthreads();

    int buf = 0;
    for (int kt = 0; kt < ntiles; kt++) {
        bool more = (kt + 1 < ntiles);
        if (more) {
            int k0 = (kt + 1) * 16;
            av0 = *(const float4*)(Ap0 + k0);
            av1 = *(const float4*)(Ap1 + k0);
            if (TRANSB) {
                bv0 = *(const float4*)(BpT0 + k0);
                bv1 = *(const float4*)(BpT1 + k0);
            } else if (BN == 128) {
                bv0 = bvalid ? *(const float4*)(BpNT + (size_t)k0 * ldb) : make_float4(0.f, 0.f, 0.f, 0.f);
                bv1 = bvalid ? *(const float4*)(BpNT + (size_t)(k0 + 8) * ldb) : make_float4(0.f, 0.f, 0.f, 0.f);
            } else {
                bv0 = bvalid ? *(const float4*)(BpNT + (size_t)k0 * ldb) : make_float4(0.f, 0.f, 0.f, 0.f);
            }
        }

#pragma unroll
        for (int ks = 0; ks < 2; ks++) {
            int k8 = ks * 8;
            uint32_t afrag[4][4], bfrag[NI][2];
            int r = lane >> 2, c = lane & 3;
#pragma unroll
            for (int mi = 0; mi < 4; mi++) {
                int r0 = wm + mi * 16 + r;
                afrag[mi][0] = As[buf][r0][k8 + c];
                afrag[mi][1] = As[buf][r0 + 8][k8 + c];
                afrag[mi][2] = As[buf][r0][k8 + c + 4];
                afrag[mi][3] = As[buf][r0 + 8][k8 + c + 4];
            }
#pragma unroll
            for (int ni = 0; ni < NI; ni++) {
                int nb = wn + ni * 8 + r;
                if (TRANSB) {
                    bfrag[ni][0] = Bs[buf][nb % BSY][(k8 + c) % BSX];
                    bfrag[ni][1] = Bs[buf][nb % BSY][(k8 + c + 4) % BSX];
                } else {
                    bfrag[ni][0] = Bs[buf][(k8 + c) % BSY][nb % BSX];
                    bfrag[ni][1] = Bs[buf][(k8 + c + 4) % BSY][nb % BSX];
                }
            }
#pragma unroll
            for (int mi = 0; mi < 4; mi++)
#pragma unroll
                for (int ni = 0; ni < NI; ni++)
                    mma_tf32(acc[mi][ni], afrag[mi], bfrag[ni]);
        }

        if (more) {
            int nb2 = buf ^ 1;
            *(uint4*)&As[nb2][am][akq]      = make_uint4(f2tf(av0.x), f2tf(av0.y), f2tf(av0.z), f2tf(av0.w));
            *(uint4*)&As[nb2][am + 64][akq] = make_uint4(f2tf(av1.x), f2tf(av1.y), f2tf(av1.z), f2tf(av1.w));
            if (TRANSB) {
                *(uint4*)&Bs[nb2][am % BSY][akq % BSX]        = make_uint4(f2tf(bv0.x), f2tf(bv0.y), f2tf(bv0.z), f2tf(bv0.w));
                *(uint4*)&Bs[nb2][(am + 64) % BSY][akq % BSX] = make_uint4(f2tf(bv1.x), f2tf(bv1.y), f2tf(bv1.z), f2tf(bv1.w));
            } else if (BN == 128) {
                *(uint4*)&Bs[nb2][bkr % BSY][bn4 % BSX]       = make_uint4(f2tf(bv0.x), f2tf(bv0.y), f2tf(bv0.z), f2tf(bv0.w));
                *(uint4*)&Bs[nb2][(bkr + 8) % BSY][bn4 % BSX] = make_uint4(f2tf(bv1.x), f2tf(bv1.y), f2tf(bv1.z), f2tf(bv1.w));
            } else {
                *(uint4*)&Bs[nb2][bkr % BSY][bn4 % BSX]       = make_uint4(f2tf(bv0.x), f2tf(bv0.y), f2tf(bv0.z), f2tf(bv0.w));
            }
        }
        __syncthreads();
        buf ^= 1;
    }

    // ---- epilogue ----
    int r = lane >> 2, c = lane & 3;
#pragma unroll
    for (int mi = 0; mi < 4; mi++) {
#pragma unroll
        for (int ni = 0; ni < NI; ni++) {
            int r0 = bm + wm + mi * 16 + r;
            int cn = bn + wn + ni * 8 + c * 2;
#pragma unroll
            for (int h2 = 0; h2 < 2; h2++) {
                int gm = r0 + h2 * 8;
#pragma unroll
                for (int j = 0; j < 2; j++) {
                    int gn = cn + j;
                    if (gn >= N) continue;
                    float v = acc[mi][ni][h2 * 2 + j];
                    if (EPI == EPI_BIAS) {
                        C[(size_t)gm * ldc + gn] = v + bias[gn];
                    } else if (EPI == EPI_NONE) {
                        C[(size_t)gm * ldc + gn] = v;
                    } else if (EPI == EPI_QKV) {
                        int b = gm >> 11, s = gm & (S_LEN - 1);
                        int h = gn >> 6,  dh = gn & 63;
                        C[(((size_t)(b * NH + h) * S_LEN + s) << 6) + dh] = v + bias[gn];
                    } else if (EPI == EPI_OPROJ) {
                        float mk = (float)auxm[gm];
                        C[(size_t)gm * ldc + gn] = aux1[(size_t)gm * ldc + gn] + (v + bias[gn]) * mk;
                    } else if (EPI == EPI_GELU) {
                        float u = v + bias[gn];
                        C[(size_t)gm * ldc + gn] = 0.5f * u * (1.0f + erff(u * 0.70710678118654752f));
                    } else if (EPI == EPI_FINAL) {
                        float mk = (float)auxm[gm];
                        C[(size_t)gm * ldc + gn] = (aux1[(size_t)gm * ldc + gn] + v + bias[gn]) * mk;
                    }
                }
            }
        }
    }
}

// ---------------- fused softmax (single read / single write via smem cache) ----------------
__global__ __launch_bounds__(256) void softmax_kernel(float* __restrict__ sc,
                                                      const float* __restrict__ bt,
                                                      const int* __restrict__ mask) {
    __shared__ float buf[S_LEN];
    __shared__ float red[256];
    int row = blockIdx.x;
    int q = row & (S_LEN - 1);
    int h = (row >> 11) & (NH - 1);
    int b = row >> 15;
    float* sp = sc + (size_t)row * S_LEN;
    const float* btr = bt + h * S_LEN;
    const int* mr = mask + b * S_LEN;
    int t = threadIdx.x;
    const float NEG = __int_as_float(0xff800000);

    float mx = NEG;
    for (int k = t; k <= q; k += 256) {
        float v = mr[k] ? sp[k] * 0.125f + btr[q - k] : NEG;
        buf[k] = v;
        mx = fmaxf(mx, v);
    }
    red[t] = mx;
    __syncthreads();
    for (int o = 128; o > 0; o >>= 1) {
        if (t < o) red[t] = fmaxf(red[t], red[t + o]);
        __syncthreads();
    }
    mx = red[0];
    __syncthreads();

    float sum = 0.0f;
    for (int k = t; k <= q; k += 256) {
        float v = buf[k];
        float e = (v == NEG) ? 0.0f : expf(v - mx);
        buf[k] = e;
        sum += e;
    }
    red[t] = sum;
    __syncthreads();
    for (int o = 128; o > 0; o >>= 1) {
        if (t < o) red[t] += red[t + o];
        __syncthreads();
    }
    float tot = red[0];
    float inv = (tot > 0.0f) ? 1.0f / tot : 0.0f;
    for (int k = t; k < S_LEN; k += 256) {
        sp[k] = (k <= q) ? buf[k] * inv : 0.0f;
    }
}

// ---------------- [B,H,S,DH] -> [B,S,H*DH] merge ----------------
__global__ __launch_bounds__(256) void merge_kernel(const float* __restrict__ att,
                                                    float* __restrict__ out) {
    int idx = blockIdx.x * 256 + threadIdx.x;
    int m = idx >> 8;
    int c = (idx & 255) * 4;
    int b = m >> 11, s = m & (S_LEN - 1);
    int h = c >> 6,  dh = c & 63;
    ((float4*)out)[idx] =
        ((const float4*)(att + (((size_t)(b * NH + h) * S_LEN + s) << 6)))[dh >> 2];
}

// ---------------- launch ----------------
extern "C" void kernel_launch(void* const* d_in, const int* in_sizes, int n_in,
                              void* d_out, int out_size) {
    const float* hidden = (const float*)d_in[0];
    const int*   mask   = (const int*)d_in[1];
    const float* wq = (const float*)d_in[2];  const float* bq = (const float*)d_in[3];
    const float* wk = (const float*)d_in[4];  const float* bk = (const float*)d_in[5];
    const float* wv = (const float*)d_in[6];  const float* bv = (const float*)d_in[7];
    const float* wo = (const float*)d_in[8];  const float* bo = (const float*)d_in[9];
    const float* rb = (const float*)d_in[10];
    const float* ln1g = (const float*)d_in[11]; const float* ln1b = (const float*)d_in[12];
    const float* ln2g = (const float*)d_in[13]; const float* ln2b = (const float*)d_in[14];
    const float* w1 = (const float*)d_in[15]; const float* b1 = (const float*)d_in[16];
    const float* w2 = (const float*)d_in[17]; const float* b2 = (const float*)d_in[18];
    float* out = (float*)d_out;

    float *X, *Q, *K, *V, *SC, *AT, *MG, *H1, *FFb, *BT;
    cudaGetSymbolAddress((void**)&X,  g_X);
    cudaGetSymbolAddress((void**)&Q,  g_Q);
    cudaGetSymbolAddress((void**)&K,  g_K);
    cudaGetSymbolAddress((void**)&V,  g_V);
    cudaGetSymbolAddress((void**)&SC, g_SC);
    cudaGetSymbolAddress((void**)&AT, g_AT);
    cudaGetSymbolAddress((void**)&MG, g_MG);
    cudaGetSymbolAddress((void**)&H1, g_H1);
    cudaGetSymbolAddress((void**)&FFb, g_FF);
    cudaGetSymbolAddress((void**)&BT, g_BT);

    biastab_kernel<<<(NH * S_LEN + 255) / 256, 256>>>(rb, BT);
    ln_kernel<<<ROWS, 256>>>(hidden, ln1g, ln1b, X);

    // QKV projections (scatter into [B,H,S,DH])
    dim3 gProj(DM / 128, ROWS / 128, 1);
    mgemm<0, EPI_QKV, 128><<<gProj, 256>>>(X, wq, bq, Q, ROWS, DM, DM, DM, DM, 0,
                                           0, 0, 0, nullptr, nullptr, 0, 0);
    mgemm<0, EPI_QKV, 128><<<gProj, 256>>>(X, wk, bk, K, ROWS, DM, DM, DM, DM, 0,
                                           0, 0, 0, nullptr, nullptr, 0, 0);
    mgemm<0, EPI_QKV, 128><<<gProj, 256>>>(X, wv, bv, V, ROWS, DM, DM, DM, DM, 0,
                                           0, 0, 0, nullptr, nullptr, 0, 0);

    // scores = Q @ K^T per (b,h); causal tile skip
    dim3 gSc(S_LEN / 128, S_LEN / 128, BATCH * NH);
    mgemm<1, EPI_NONE, 128><<<gSc, 256>>>(Q, K, nullptr, SC, S_LEN, S_LEN, DH, DH, DH, S_LEN,
                                          (long long)S_LEN * DH, (long long)S_LEN * DH,
                                          (long long)S_LEN * S_LEN, nullptr, nullptr, 1, 0);

    softmax_kernel<<<BATCH * NH * S_LEN, 256>>>(SC, BT, mask);

    // attended = attn @ V with causal K-truncation; BN=64 (no wasted columns)
    dim3 gPV(1, S_LEN / 128, BATCH * NH);
    mgemm<0, EPI_NONE, 64><<<gPV, 256>>>(SC, V, nullptr, AT, S_LEN, DH, S_LEN, S_LEN, DH, DH,
                                         (long long)S_LEN * S_LEN, (long long)S_LEN * DH,
                                         (long long)S_LEN * DH, nullptr, nullptr, 0, 1);

    merge_kernel<<<ROWS * DM / 1024, 256>>>(AT, MG);

    // O projection + mask + residual
    mgemm<0, EPI_OPROJ, 128><<<gProj, 256>>>(MG, wo, bo, H1, ROWS, DM, DM, DM, DM, DM,
                                             0, 0, 0, hidden, mask, 0, 0);

    ln_kernel<<<ROWS, 256>>>(H1, ln2g, ln2b, X);

    // FFN up + exact GELU
    dim3 gF1(DFF / 128, ROWS / 128, 1);
    mgemm<0, EPI_GELU, 128><<<gF1, 256>>>(X, w1, b1, FFb, ROWS, DFF, DM, DM, DFF, DFF,
                                          0, 0, 0, nullptr, nullptr, 0, 0);

    // FFN down + residual + mask
    mgemm<0, EPI_FINAL, 128><<<gProj, 256>>>(FFb, w2, b2, out, ROWS, DM, DFF, DFF, DM, DM,
                                             0, 0, 0, H1, mask, 0, 0);
}

// round 5
// speedup vs baseline: 2.9076x; 1.0783x over previous
#include <cuda_runtime.h>
#include <math.h>
#include <stdint.h>

// ---------------- problem constants ----------------
#define S_LEN 2048
#define NH    16
#define DH    64
#define DM    1024
#define DFF   4096
#define BATCH 2
#define ROWS  (BATCH * S_LEN)   // 4096

// ---------------- scratch ----------------
__device__ float g_X [ROWS * DM];
__device__ float g_Q [BATCH * NH * S_LEN * DH];
__device__ float g_K [BATCH * NH * S_LEN * DH];
__device__ float g_V [BATCH * NH * S_LEN * DH];
__device__ float g_VT[BATCH * NH * S_LEN * DH];
__device__ float g_SC[134217728];
__device__ float g_AT[BATCH * NH * S_LEN * DH];
__device__ float g_MG[ROWS * DM];
__device__ float g_H1[ROWS * DM];
__device__ float g_FF[ROWS * DFF];
__device__ float g_BT[NH * S_LEN];
__device__ float g_WT[12 * 1024 * 1024];   // transposed weights: q,k,v,o @ 0..4M; w1 @4M; w2 @8M

// ---------------- helpers ----------------
__device__ __forceinline__ uint32_t smem_u32(const void* p) {
    uint32_t a;
    asm("{ .reg .u64 t; cvta.to.shared.u64 t, %1; cvt.u32.u64 %0, t; }" : "=r"(a) : "l"(p));
    return a;
}
__device__ __forceinline__ uint32_t f2tf(float f) {
    uint32_t u;
    asm("cvt.rna.tf32.f32 %0, %1;" : "=r"(u) : "f"(f));
    return u;
}
__device__ __forceinline__ void ldsm4(uint32_t* r, uint32_t addr) {
    asm volatile("ldmatrix.sync.aligned.m8n8.x4.shared.b16 {%0,%1,%2,%3}, [%4];"
                 : "=r"(r[0]), "=r"(r[1]), "=r"(r[2]), "=r"(r[3]) : "r"(addr));
}
__device__ __forceinline__ void mma_tf32(float* d, const uint32_t* a, const uint32_t* b) {
    asm volatile(
        "mma.sync.aligned.m16n8k8.row.col.f32.tf32.tf32.f32 "
        "{%0,%1,%2,%3}, {%4,%5,%6,%7}, {%8,%9}, {%0,%1,%2,%3};"
        : "+f"(d[0]), "+f"(d[1]), "+f"(d[2]), "+f"(d[3])
        : "r"(a[0]), "r"(a[1]), "r"(a[2]), "r"(a[3]), "r"(b[0]), "r"(b[1]));
}

enum { EPI_BIAS = 0, EPI_QKV = 1, EPI_NONE = 2, EPI_OPROJ = 3, EPI_GELU = 4, EPI_FINAL = 5 };

// ---------------- weight transpose: W[K,N] -> WT[N,K] ----------------
__global__ __launch_bounds__(256) void wtrans_kernel(const float* __restrict__ W,
                                                     float* __restrict__ WT, int K, int N) {
    __shared__ float t[32][33];
    int n0 = blockIdx.x * 32, k0 = blockIdx.y * 32;
    int tx = threadIdx.x & 31, ty = threadIdx.x >> 5;
#pragma unroll
    for (int j = 0; j < 32; j += 8)
        t[ty + j][tx] = W[(size_t)(k0 + ty + j) * N + n0 + tx];
    __syncthreads();
#pragma unroll
    for (int j = 0; j < 32; j += 8)
        WT[(size_t)(n0 + ty + j) * K + k0 + tx] = t[tx][ty + j];
}

// ---------------- V transpose per (b,h): V[s][d] -> VT[d][s] ----------------
__global__ __launch_bounds__(256) void vtrans_kernel(const float* __restrict__ V,
                                                     float* __restrict__ VT) {
    __shared__ float t[32][33];
    int bh = blockIdx.z;
    int s0 = blockIdx.x * 32, d0 = blockIdx.y * 32;
    const float* src = V + (size_t)bh * S_LEN * DH;
    float* dst = VT + (size_t)bh * S_LEN * DH;
    int tx = threadIdx.x & 31, ty = threadIdx.x >> 5;
#pragma unroll
    for (int j = 0; j < 32; j += 8)
        t[ty + j][tx] = src[(size_t)(s0 + ty + j) * DH + d0 + tx];
    __syncthreads();
#pragma unroll
    for (int j = 0; j < 32; j += 8)
        dst[(size_t)(d0 + ty + j) * S_LEN + s0 + tx] = t[tx][ty + j];
}

// ---------------- relative-position bias table ----------------
__global__ void biastab_kernel(const float* __restrict__ rel_bias,
                               float* __restrict__ tab) {
    int idx = blockIdx.x * blockDim.x + threadIdx.x;
    if (idx >= NH * S_LEN) return;
    int h = idx / S_LEN;
    int d = idx % S_LEN;
    int bucket;
    if (d < 16) {
        bucket = d;
    } else {
        float ratio = logf((float)d * (1.0f / 16.0f)) / logf(8.0f);
        int large = 16 + (int)(ratio * 16.0f);
        bucket = large < 31 ? large : 31;
    }
    tab[h * S_LEN + d] = rel_bias[bucket * NH + h];
}

// ---------------- layernorm ----------------
__global__ __launch_bounds__(256) void ln_kernel(const float* __restrict__ x,
                                                 const float* __restrict__ g,
                                                 const float* __restrict__ bta,
                                                 float* __restrict__ y) {
    int row = blockIdx.x;
    int t = threadIdx.x;
    const float4* xr = (const float4*)(x + (size_t)row * DM);
    float4 v = xr[t];
    float s  = v.x + v.y + v.z + v.w;
    float ss = v.x * v.x + v.y * v.y + v.z * v.z + v.w * v.w;
    __shared__ float sh_s[256], sh_q[256];
    sh_s[t] = s; sh_q[t] = ss;
    __syncthreads();
    for (int o = 128; o > 0; o >>= 1) {
        if (t < o) { sh_s[t] += sh_s[t + o]; sh_q[t] += sh_q[t + o]; }
        __syncthreads();
    }
    float mean = sh_s[0] * (1.0f / DM);
    float var  = sh_q[0] * (1.0f / DM) - mean * mean;
    float rstd = rsqrtf(var + 1e-5f);
    float4 gv = ((const float4*)g)[t];
    float4 bv = ((const float4*)bta)[t];
    float4 o4;
    o4.x = (v.x - mean) * rstd * gv.x + bv.x;
    o4.y = (v.y - mean) * rstd * gv.y + bv.y;
    o4.z = (v.z - mean) * rstd * gv.z + bv.z;
    o4.w = (v.w - mean) * rstd * gv.w + bv.w;
    ((float4*)(y + (size_t)row * DM))[t] = o4;
}

// ---------------- tf32 mma.sync GEMM with ldmatrix fragments ----------------
// C[M,N] = A[M,K] * B^T where B is [N,K] row-major. Tile 128xBN, BK=16 double-buffered.
// 256 threads, 8 warps (2 x 4), warp tile 64 x (BN/4). Fragments loaded via ldmatrix.x4.b16.
template <int EPI, int BN>
__global__ __launch_bounds__(256, 2) void mgemm(
    const float* __restrict__ A, const float* __restrict__ Bm,
    const float* __restrict__ bias, float* __restrict__ C,
    int N, int K, int lda, int ldb, int ldc,
    long long sA, long long sB, long long sC,
    const float* __restrict__ aux1, const int* __restrict__ auxm,
    int causal_skip, int causal_klim) {
    int z = blockIdx.z;
    A  += (long long)z * sA;
    Bm += (long long)z * sB;
    C  += (long long)z * sC;
    int bn = blockIdx.x * BN;
    int bm = blockIdx.y * 128;
    if (causal_skip && bn >= bm + 128) return;
    int Keff = K;
    if (causal_klim) { int kl = bm + 128; Keff = (K < kl) ? K : kl; }

    constexpr int NI = BN / 32;                 // n-frags per warp (8 cols each): 4 or 2
    constexpr int NP = NI / 2;                  // ldmatrix.x4 pairs for B: 2 or 1

    __shared__ __align__(16) uint32_t As[2][128][20];
    __shared__ __align__(16) uint32_t Bs[2][BN][20];

    int tid = threadIdx.x;
    int lane = tid & 31;
    int w = tid >> 5;
    int wm = (w & 1) * 64;
    int wn = (w >> 1) * (BN / 4);

    float acc[4][NI][4];
#pragma unroll
    for (int mi = 0; mi < 4; mi++)
#pragma unroll
        for (int ni = 0; ni < NI; ni++)
#pragma unroll
            for (int r = 0; r < 4; r++) acc[mi][ni][r] = 0.0f;

    // ---- staging coordinates (row-major A and B) ----
    int am = tid >> 2;                          // rows am, am+64
    int akq = (tid & 3) * 4;
    const float* Ap0 = A + (size_t)(bm + am) * lda + akq;
    const float* Ap1 = A + (size_t)(bm + am + 64) * lda + akq;
    const float* Bp0, *Bp1;
    int b64r = tid >> 2, b64c = (tid & 3) * 4;  // BN==64 staging
    if (BN == 128) {
        Bp0 = Bm + (size_t)(bn + am) * ldb + akq;
        Bp1 = Bm + (size_t)(bn + am + 64) * ldb + akq;
    } else {
        Bp0 = Bm + (size_t)(bn + b64r) * ldb + b64c;
        Bp1 = nullptr;
    }

    // ---- ldmatrix per-thread addresses (byte offsets into As/Bs) ----
    uint32_t As_u = smem_u32(As);
    uint32_t Bs_u = smem_u32(Bs);
    // A: matrices (rows0-7,c0-3),(rows8-15,c0-3),(rows0-7,c4-7),(rows8-15,c4-7)
    uint32_t a_addr = As_u + (uint32_t)(((wm + (lane & 15)) * 20 + (lane >> 4) * 4) * 4);
    // B pair: m0..m3 = (n0-7,k0-3),(n0-7,k4-7),(n8-15,k0-3),(n8-15,k4-7)
    uint32_t b_addr = Bs_u + (uint32_t)(((wn + (lane >> 4) * 8 + (lane & 7)) * 20 +
                                         ((lane >> 3) & 1) * 4) * 4);

    int ntiles = Keff >> 4;

    float4 av0, av1, bv0, bv1;
    av0 = *(const float4*)(Ap0);
    av1 = *(const float4*)(Ap1);
    bv0 = *(const float4*)(Bp0);
    if (BN == 128) bv1 = *(const float4*)(Bp1);
    {
        *(uint4*)&As[0][am][akq]      = make_uint4(f2tf(av0.x), f2tf(av0.y), f2tf(av0.z), f2tf(av0.w));
        *(uint4*)&As[0][am + 64][akq] = make_uint4(f2tf(av1.x), f2tf(av1.y), f2tf(av1.z), f2tf(av1.w));
        if (BN == 128) {
            *(uint4*)&Bs[0][am % BN][akq]        = make_uint4(f2tf(bv0.x), f2tf(bv0.y), f2tf(bv0.z), f2tf(bv0.w));
            *(uint4*)&Bs[0][(am + 64) % BN][akq] = make_uint4(f2tf(bv1.x), f2tf(bv1.y), f2tf(bv1.z), f2tf(bv1.w));
        } else {
            *(uint4*)&Bs[0][b64r % BN][b64c]     = make_uint4(f2tf(bv0.x), f2tf(bv0.y), f2tf(bv0.z), f2tf(bv0.w));
        }
    }
    __syncthreads();

    int buf = 0;
    for (int kt = 0; kt < ntiles; kt++) {
        bool more = (kt + 1 < ntiles);
        if (more) {
            int k0 = (kt + 1) * 16;
            av0 = *(const float4*)(Ap0 + k0);
            av1 = *(const float4*)(Ap1 + k0);
            bv0 = *(const float4*)(Bp0 + k0);
            if (BN == 128) bv1 = *(const float4*)(Bp1 + k0);
        }

        uint32_t abase = a_addr + (uint32_t)(buf * 128 * 80);
        uint32_t bbase = b_addr + (uint32_t)(buf * BN * 80);
#pragma unroll
        for (int ks = 0; ks < 2; ks++) {
            uint32_t koff = (uint32_t)(ks * 8 * 4);
            uint32_t afr[4][4], bfr[NP][4];
#pragma unroll
            for (int mi = 0; mi < 4; mi++)
                ldsm4(afr[mi], abase + (uint32_t)(mi * 16 * 80) + koff);
#pragma unroll
            for (int pi = 0; pi < NP; pi++)
                ldsm4(bfr[pi], bbase + (uint32_t)(pi * 16 * 80) + koff);
#pragma unroll
            for (int mi = 0; mi < 4; mi++)
#pragma unroll
                for (int ni = 0; ni < NI; ni++)
                    mma_tf32(acc[mi][ni], afr[mi], &bfr[ni >> 1][(ni & 1) * 2]);
        }

        if (more) {
            int nb2 = buf ^ 1;
            *(uint4*)&As[nb2][am][akq]      = make_uint4(f2tf(av0.x), f2tf(av0.y), f2tf(av0.z), f2tf(av0.w));
            *(uint4*)&As[nb2][am + 64][akq] = make_uint4(f2tf(av1.x), f2tf(av1.y), f2tf(av1.z), f2tf(av1.w));
            if (BN == 128) {
                *(uint4*)&Bs[nb2][am % BN][akq]        = make_uint4(f2tf(bv0.x), f2tf(bv0.y), f2tf(bv0.z), f2tf(bv0.w));
                *(uint4*)&Bs[nb2][(am + 64) % BN][akq] = make_uint4(f2tf(bv1.x), f2tf(bv1.y), f2tf(bv1.z), f2tf(bv1.w));
            } else {
                *(uint4*)&Bs[nb2][b64r % BN][b64c]     = make_uint4(f2tf(bv0.x), f2tf(bv0.y), f2tf(bv0.z), f2tf(bv0.w));
            }
        }
        __syncthreads();
        buf ^= 1;
    }

    // ---- epilogue ----
    int r = lane >> 2, c = lane & 3;
#pragma unroll
    for (int mi = 0; mi < 4; mi++) {
#pragma unroll
        for (int ni = 0; ni < NI; ni++) {
            int r0 = bm + wm + mi * 16 + r;
            int cn = bn + wn + ni * 8 + c * 2;
#pragma unroll
            for (int h2 = 0; h2 < 2; h2++) {
                int gm = r0 + h2 * 8;
#pragma unroll
                for (int j = 0; j < 2; j++) {
                    int gn = cn + j;
                    float v = acc[mi][ni][h2 * 2 + j];
                    if (EPI == EPI_BIAS) {
                        C[(size_t)gm * ldc + gn] = v + bias[gn];
                    } else if (EPI == EPI_NONE) {
                        C[(size_t)gm * ldc + gn] = v;
                    } else if (EPI == EPI_QKV) {
                        int b = gm >> 11, s = gm & (S_LEN - 1);
                        int h = gn >> 6, dh = gn & 63;
                        C[(((size_t)(b * NH + h) * S_LEN + s) << 6) + dh] = v + bias[gn];
                    } else if (EPI == EPI_OPROJ) {
                        float mk = (float)auxm[gm];
                        C[(size_t)gm * ldc + gn] = aux1[(size_t)gm * ldc + gn] + (v + bias[gn]) * mk;
                    } else if (EPI == EPI_GELU) {
                        float u = v + bias[gn];
                        C[(size_t)gm * ldc + gn] = 0.5f * u * (1.0f + erff(u * 0.70710678118654752f));
                    } else if (EPI == EPI_FINAL) {
                        float mk = (float)auxm[gm];
                        C[(size_t)gm * ldc + gn] = (aux1[(size_t)gm * ldc + gn] + v + bias[gn]) * mk;
                    }
                }
            }
        }
    }
}

// ---------------- fused softmax ----------------
__global__ __launch_bounds__(256) void softmax_kernel(float* __restrict__ sc,
                                                      const float* __restrict__ bt,
                                                      const int* __restrict__ mask) {
    __shared__ float buf[S_LEN];
    __shared__ float red[256];
    int row = blockIdx.x;
    int q = row & (S_LEN - 1);
    int h = (row >> 11) & (NH - 1);
    int b = row >> 15;
    float* sp = sc + (size_t)row * S_LEN;
    const float* btr = bt + h * S_LEN;
    const int* mr = mask + b * S_LEN;
    int t = threadIdx.x;
    const float NEG = __int_as_float(0xff800000);

    float mx = NEG;
    for (int k = t; k <= q; k += 256) {
        float v = mr[k] ? sp[k] * 0.125f + btr[q - k] : NEG;
        buf[k] = v;
        mx = fmaxf(mx, v);
    }
    red[t] = mx;
    __syncthreads();
    for (int o = 128; o > 0; o >>= 1) {
        if (t < o) red[t] = fmaxf(red[t], red[t + o]);
        __syncthreads();
    }
    mx = red[0];
    __syncthreads();

    float sum = 0.0f;
    for (int k = t; k <= q; k += 256) {
        float v = buf[k];
        float e = (v == NEG) ? 0.0f : expf(v - mx);
        buf[k] = e;
        sum += e;
    }
    red[t] = sum;
    __syncthreads();
    for (int o = 128; o > 0; o >>= 1) {
        if (t < o) red[t] += red[t + o];
        __syncthreads();
    }
    float tot = red[0];
    float inv = (tot > 0.0f) ? 1.0f / tot : 0.0f;
    for (int k = t; k < S_LEN; k += 256) {
        sp[k] = (k <= q) ? buf[k] * inv : 0.0f;
    }
}

// ---------------- merge heads ----------------
__global__ __launch_bounds__(256) void merge_kernel(const float* __restrict__ att,
                                                    float* __restrict__ out) {
    int idx = blockIdx.x * 256 + threadIdx.x;
    int m = idx >> 8;
    int c = (idx & 255) * 4;
    int b = m >> 11, s = m & (S_LEN - 1);
    int h = c >> 6, dh = c & 63;
    ((float4*)out)[idx] =
        ((const float4*)(att + (((size_t)(b * NH + h) * S_LEN + s) << 6)))[dh >> 2];
}

// ---------------- launch ----------------
extern "C" void kernel_launch(void* const* d_in, const int* in_sizes, int n_in,
                              void* d_out, int out_size) {
    const float* hidden = (const float*)d_in[0];
    const int*   mask   = (const int*)d_in[1];
    const float* wq = (const float*)d_in[2];  const float* bq = (const float*)d_in[3];
    const float* wk = (const float*)d_in[4];  const float* bk = (const float*)d_in[5];
    const float* wv = (const float*)d_in[6];  const float* bv = (const float*)d_in[7];
    const float* wo = (const float*)d_in[8];  const float* bo = (const float*)d_in[9];
    const float* rb = (const float*)d_in[10];
    const float* ln1g = (const float*)d_in[11]; const float* ln1b = (const float*)d_in[12];
    const float* ln2g = (const float*)d_in[13]; const float* ln2b = (const float*)d_in[14];
    const float* w1 = (const float*)d_in[15]; const float* b1 = (const float*)d_in[16];
    const float* w2 = (const float*)d_in[17]; const float* b2 = (const float*)d_in[18];
    float* out = (float*)d_out;

    float *X, *Q, *K, *V, *VT, *SC, *AT, *MG, *H1, *FFb, *BT, *WT;
    cudaGetSymbolAddress((void**)&X,  g_X);
    cudaGetSymbolAddress((void**)&Q,  g_Q);
    cudaGetSymbolAddress((void**)&K,  g_K);
    cudaGetSymbolAddress((void**)&V,  g_V);
    cudaGetSymbolAddress((void**)&VT, g_VT);
    cudaGetSymbolAddress((void**)&SC, g_SC);
    cudaGetSymbolAddress((void**)&AT, g_AT);
    cudaGetSymbolAddress((void**)&MG, g_MG);
    cudaGetSymbolAddress((void**)&H1, g_H1);
    cudaGetSymbolAddress((void**)&FFb, g_FF);
    cudaGetSymbolAddress((void**)&BT, g_BT);
    cudaGetSymbolAddress((void**)&WT, g_WT);

    const size_t M1 = 1024 * 1024;
    // weight transposes: W[K,N] -> WT[N,K]
    wtrans_kernel<<<dim3(32, 32), 256>>>(wq, WT + 0 * M1, DM, DM);
    wtrans_kernel<<<dim3(32, 32), 256>>>(wk, WT + 1 * M1, DM, DM);
    wtrans_kernel<<<dim3(32, 32), 256>>>(wv, WT + 2 * M1, DM, DM);
    wtrans_kernel<<<dim3(32, 32), 256>>>(wo, WT + 3 * M1, DM, DM);
    wtrans_kernel<<<dim3(128, 32), 256>>>(w1, WT + 4 * M1, DM, DFF);
    wtrans_kernel<<<dim3(32, 128), 256>>>(w2, WT + 8 * M1, DFF, DM);

    biastab_kernel<<<(NH * S_LEN + 255) / 256, 256>>>(rb, BT);
    ln_kernel<<<ROWS, 256>>>(hidden, ln1g, ln1b, X);

    // QKV projections (scatter into [B,H,S,DH])
    dim3 gProj(DM / 128, ROWS / 128);
    mgemm<EPI_QKV, 128><<<gProj, 256>>>(X, WT + 0 * M1, bq, Q, DM, DM, DM, DM, 0,
                                        0, 0, 0, nullptr, nullptr, 0, 0);
    mgemm<EPI_QKV, 128><<<gProj, 256>>>(X, WT + 1 * M1, bk, K, DM, DM, DM, DM, 0,
                                        0, 0, 0, nullptr, nullptr, 0, 0);
    mgemm<EPI_QKV, 128><<<gProj, 256>>>(X, WT + 2 * M1, bv, V, DM, DM, DM, DM, 0,
                                        0, 0, 0, nullptr, nullptr, 0, 0);

    // V transpose per (b,h): [s][dh] -> [dh][s]
    vtrans_kernel<<<dim3(S_LEN / 32, DH / 32, BATCH * NH), 256>>>(V, VT);

    // scores = Q @ K^T per (b,h); causal tile skip (K already [n=s][k=dh])
    dim3 gSc(S_LEN / 128, S_LEN / 128, BATCH * NH);
    mgemm<EPI_NONE, 128><<<gSc, 256>>>(Q, K, nullptr, SC, S_LEN, DH, DH, DH, S_LEN,
                                       (long long)S_LEN * DH, (long long)S_LEN * DH,
                                       (long long)S_LEN * S_LEN, nullptr, nullptr, 1, 0);

    softmax_kernel<<<BATCH * NH * S_LEN, 256>>>(SC, BT, mask);

    // attended = attn @ V: B = VT[b,h] is [dh][s]; BN=64; causal K-truncation
    dim3 gPV(1, S_LEN / 128, BATCH * NH);
    mgemm<EPI_NONE, 64><<<gPV, 256>>>(SC, VT, nullptr, AT, DH, S_LEN, S_LEN, S_LEN, DH,
                                      (long long)S_LEN * S_LEN, (long long)S_LEN * DH,
                                      (long long)S_LEN * DH, nullptr, nullptr, 0, 1);

    merge_kernel<<<ROWS * DM / 1024, 256>>>(AT, MG);

    // O projection + mask + residual
    mgemm<EPI_OPROJ, 128><<<gProj, 256>>>(MG, WT + 3 * M1, bo, H1, DM, DM, DM, DM, DM,
                                          0, 0, 0, hidden, mask, 0, 0);

    ln_kernel<<<ROWS, 256>>>(H1, ln2g, ln2b, X);

    // FFN up + exact GELU
    dim3 gF1(DFF / 128, ROWS / 128);
    mgemm<EPI_GELU, 128><<<gF1, 256>>>(X, WT + 4 * M1, b1, FFb, DFF, DM, DM, DM, DFF,
                                       0, 0, 0, nullptr, nullptr, 0, 0);

    // FFN down + residual + mask
    mgemm<EPI_FINAL, 128><<<gProj, 256>>>(FFb, WT + 8 * M1, b2, out, DM, DFF, DFF, DFF, DM,
                                          0, 0, 0, H1, mask, 0, 0);
}

// round 6
// speedup vs baseline: 4.0980x; 1.4094x over previous
#include <cuda_runtime.h>
#include <math.h>
#include <stdint.h>

// ---------------- problem constants ----------------
#define S_LEN 2048
#define NH    16
#define DH    64
#define DM    1024
#define DFF   4096
#define BATCH 2
#define ROWS  (BATCH * S_LEN)   // 4096

// ---------------- scratch ----------------
__device__ float g_X [ROWS * DM];
__device__ float g_Q [BATCH * NH * S_LEN * DH];
__device__ float g_K [BATCH * NH * S_LEN * DH];
__device__ float g_V [BATCH * NH * S_LEN * DH];
__device__ float g_VT[BATCH * NH * S_LEN * DH];
__device__ float g_MG[ROWS * DM];
__device__ float g_H1[ROWS * DM];
__device__ float g_FF[ROWS * DFF];
__device__ float g_BT[NH * S_LEN];
__device__ float g_WT[12 * 1024 * 1024];   // transposed weights: q,k,v,o @ 0..4M; w1 @4M; w2 @8M

// ---------------- helpers ----------------
__device__ __forceinline__ uint32_t smem_u32(const void* p) {
    uint32_t a;
    asm("{ .reg .u64 t; cvta.to.shared.u64 t, %1; cvt.u32.u64 %0, t; }" : "=r"(a) : "l"(p));
    return a;
}
__device__ __forceinline__ uint32_t f2tf(float f) {
    uint32_t u;
    asm("cvt.rna.tf32.f32 %0, %1;" : "=r"(u) : "f"(f));
    return u;
}
__device__ __forceinline__ float tfb(float f) {      // tf32-rounded value as float
    return __uint_as_float(f2tf(f));
}
__device__ __forceinline__ float ex2(float x) {      // 2^x via MUFU
    float y;
    asm("ex2.approx.ftz.f32 %0, %1;" : "=f"(y) : "f"(x));
    return y;
}
__device__ __forceinline__ void ldsm4(uint32_t* r, uint32_t addr) {
    asm volatile("ldmatrix.sync.aligned.m8n8.x4.shared.b16 {%0,%1,%2,%3}, [%4];"
                 : "=r"(r[0]), "=r"(r[1]), "=r"(r[2]), "=r"(r[3]) : "r"(addr));
}
__device__ __forceinline__ void mma_tf32(float* d, const uint32_t* a, const uint32_t* b) {
    asm volatile(
        "mma.sync.aligned.m16n8k8.row.col.f32.tf32.tf32.f32 "
        "{%0,%1,%2,%3}, {%4,%5,%6,%7}, {%8,%9}, {%0,%1,%2,%3};"
        : "+f"(d[0]), "+f"(d[1]), "+f"(d[2]), "+f"(d[3])
        : "r"(a[0]), "r"(a[1]), "r"(a[2]), "r"(a[3]), "r"(b[0]), "r"(b[1]));
}

enum { EPI_BIAS = 0, EPI_QKV = 1, EPI_NONE = 2, EPI_OPROJ = 3, EPI_GELU = 4, EPI_FINAL = 5 };

// ---------------- weight transpose: W[K,N] -> WT[N,K] ----------------
__global__ __launch_bounds__(256) void wtrans_kernel(const float* __restrict__ W,
                                                     float* __restrict__ WT, int K, int N) {
    __shared__ float t[32][33];
    int n0 = blockIdx.x * 32, k0 = blockIdx.y * 32;
    int tx = threadIdx.x & 31, ty = threadIdx.x >> 5;
#pragma unroll
    for (int j = 0; j < 32; j += 8)
        t[ty + j][tx] = W[(size_t)(k0 + ty + j) * N + n0 + tx];
    __syncthreads();
#pragma unroll
    for (int j = 0; j < 32; j += 8)
        WT[(size_t)(n0 + ty + j) * K + k0 + tx] = t[tx][ty + j];
}

// ---------------- V transpose per (b,h): V[s][d] -> VT[d][s] ----------------
__global__ __launch_bounds__(256) void vtrans_kernel(const float* __restrict__ V,
                                                     float* __restrict__ VT) {
    __shared__ float t[32][33];
    int bh = blockIdx.z;
    int s0 = blockIdx.x * 32, d0 = blockIdx.y * 32;
    const float* src = V + (size_t)bh * S_LEN * DH;
    float* dst = VT + (size_t)bh * S_LEN * DH;
    int tx = threadIdx.x & 31, ty = threadIdx.x >> 5;
#pragma unroll
    for (int j = 0; j < 32; j += 8)
        t[ty + j][tx] = src[(size_t)(s0 + ty + j) * DH + d0 + tx];
    __syncthreads();
#pragma unroll
    for (int j = 0; j < 32; j += 8)
        dst[(size_t)(d0 + ty + j) * S_LEN + s0 + tx] = t[tx][ty + j];
}

// ---------------- relative-position bias table (prescaled by log2 e) ----------------
__global__ void biastab_kernel(const float* __restrict__ rel_bias,
                               float* __restrict__ tab) {
    int idx = blockIdx.x * blockDim.x + threadIdx.x;
    if (idx >= NH * S_LEN) return;
    int h = idx / S_LEN;
    int d = idx % S_LEN;
    int bucket;
    if (d < 16) {
        bucket = d;
    } else {
        float ratio = logf((float)d * (1.0f / 16.0f)) / logf(8.0f);
        int large = 16 + (int)(ratio * 16.0f);
        bucket = large < 31 ? large : 31;
    }
    tab[h * S_LEN + d] = rel_bias[bucket * NH + h] * 1.44269504088896340736f;
}

// ---------------- layernorm ----------------
__global__ __launch_bounds__(256) void ln_kernel(const float* __restrict__ x,
                                                 const float* __restrict__ g,
                                                 const float* __restrict__ bta,
                                                 float* __restrict__ y) {
    int row = blockIdx.x;
    int t = threadIdx.x;
    const float4* xr = (const float4*)(x + (size_t)row * DM);
    float4 v = xr[t];
    float s  = v.x + v.y + v.z + v.w;
    float ss = v.x * v.x + v.y * v.y + v.z * v.z + v.w * v.w;
    __shared__ float sh_s[256], sh_q[256];
    sh_s[t] = s; sh_q[t] = ss;
    __syncthreads();
    for (int o = 128; o > 0; o >>= 1) {
        if (t < o) { sh_s[t] += sh_s[t + o]; sh_q[t] += sh_q[t + o]; }
        __syncthreads();
    }
    float mean = sh_s[0] * (1.0f / DM);
    float var  = sh_q[0] * (1.0f / DM) - mean * mean;
    float rstd = rsqrtf(var + 1e-5f);
    float4 gv = ((const float4*)g)[t];
    float4 bv = ((const float4*)bta)[t];
    float4 o4;
    o4.x = (v.x - mean) * rstd * gv.x + bv.x;
    o4.y = (v.y - mean) * rstd * gv.y + bv.y;
    o4.z = (v.z - mean) * rstd * gv.z + bv.z;
    o4.w = (v.w - mean) * rstd * gv.w + bv.w;
    ((float4*)(y + (size_t)row * DM))[t] = o4;
}

// ---------------- tf32 mma.sync GEMM with ldmatrix fragments (projections/FFN) ----------------
template <int EPI>
__global__ __launch_bounds__(256, 2) void mgemm(
    const float* __restrict__ A, const float* __restrict__ Bm,
    const float* __restrict__ bias, float* __restrict__ C,
    int N, int K, int lda, int ldb, int ldc,
    const float* __restrict__ aux1, const int* __restrict__ auxm) {
    int bn = blockIdx.x * 128;
    int bm = blockIdx.y * 128;

    __shared__ __align__(16) uint32_t As[2][128][20];
    __shared__ __align__(16) uint32_t Bs[2][128][20];

    int tid = threadIdx.x;
    int lane = tid & 31;
    int w = tid >> 5;
    int wm = (w & 1) * 64;
    int wn = (w >> 1) * 32;

    float acc[4][4][4];
#pragma unroll
    for (int mi = 0; mi < 4; mi++)
#pragma unroll
        for (int ni = 0; ni < 4; ni++)
#pragma unroll
            for (int r = 0; r < 4; r++) acc[mi][ni][r] = 0.0f;

    int am = tid >> 2;
    int akq = (tid & 3) * 4;
    const float* Ap0 = A + (size_t)(bm + am) * lda + akq;
    const float* Ap1 = A + (size_t)(bm + am + 64) * lda + akq;
    const float* Bp0 = Bm + (size_t)(bn + am) * ldb + akq;
    const float* Bp1 = Bm + (size_t)(bn + am + 64) * ldb + akq;

    uint32_t As_u = smem_u32(As);
    uint32_t Bs_u = smem_u32(Bs);
    uint32_t a_addr = As_u + (uint32_t)(((wm + (lane & 15)) * 20 + (lane >> 4) * 4) * 4);
    uint32_t b_addr = Bs_u + (uint32_t)(((wn + (lane >> 4) * 8 + (lane & 7)) * 20 +
                                         ((lane >> 3) & 1) * 4) * 4);

    int ntiles = K >> 4;

    float4 av0, av1, bv0, bv1;
    av0 = *(const float4*)(Ap0);
    av1 = *(const float4*)(Ap1);
    bv0 = *(const float4*)(Bp0);
    bv1 = *(const float4*)(Bp1);
    {
        *(uint4*)&As[0][am][akq]      = make_uint4(f2tf(av0.x), f2tf(av0.y), f2tf(av0.z), f2tf(av0.w));
        *(uint4*)&As[0][am + 64][akq] = make_uint4(f2tf(av1.x), f2tf(av1.y), f2tf(av1.z), f2tf(av1.w));
        *(uint4*)&Bs[0][am][akq]      = make_uint4(f2tf(bv0.x), f2tf(bv0.y), f2tf(bv0.z), f2tf(bv0.w));
        *(uint4*)&Bs[0][am + 64][akq] = make_uint4(f2tf(bv1.x), f2tf(bv1.y), f2tf(bv1.z), f2tf(bv1.w));
    }
    __syncthreads();

    int buf = 0;
    for (int kt = 0; kt < ntiles; kt++) {
        bool more = (kt + 1 < ntiles);
        if (more) {
            int k0 = (kt + 1) * 16;
            av0 = *(const float4*)(Ap0 + k0);
            av1 = *(const float4*)(Ap1 + k0);
            bv0 = *(const float4*)(Bp0 + k0);
            bv1 = *(const float4*)(Bp1 + k0);
        }

        uint32_t abase = a_addr + (uint32_t)(buf * 128 * 80);
        uint32_t bbase = b_addr + (uint32_t)(buf * 128 * 80);
#pragma unroll
        for (int ks = 0; ks < 2; ks++) {
            uint32_t koff = (uint32_t)(ks * 32);
            uint32_t afr[4][4], bfr[2][4];
#pragma unroll
            for (int mi = 0; mi < 4; mi++)
                ldsm4(afr[mi], abase + (uint32_t)(mi * 16 * 80) + koff);
#pragma unroll
            for (int pi = 0; pi < 2; pi++)
                ldsm4(bfr[pi], bbase + (uint32_t)(pi * 16 * 80) + koff);
#pragma unroll
            for (int mi = 0; mi < 4; mi++)
#pragma unroll
                for (int ni = 0; ni < 4; ni++)
                    mma_tf32(acc[mi][ni], afr[mi], &bfr[ni >> 1][(ni & 1) * 2]);
        }

        if (more) {
            int nb2 = buf ^ 1;
            *(uint4*)&As[nb2][am][akq]      = make_uint4(f2tf(av0.x), f2tf(av0.y), f2tf(av0.z), f2tf(av0.w));
            *(uint4*)&As[nb2][am + 64][akq] = make_uint4(f2tf(av1.x), f2tf(av1.y), f2tf(av1.z), f2tf(av1.w));
            *(uint4*)&Bs[nb2][am][akq]      = make_uint4(f2tf(bv0.x), f2tf(bv0.y), f2tf(bv0.z), f2tf(bv0.w));
            *(uint4*)&Bs[nb2][am + 64][akq] = make_uint4(f2tf(bv1.x), f2tf(bv1.y), f2tf(bv1.z), f2tf(bv1.w));
        }
        __syncthreads();
        buf ^= 1;
    }

    int r = lane >> 2, c = lane & 3;
#pragma unroll
    for (int mi = 0; mi < 4; mi++) {
#pragma unroll
        for (int ni = 0; ni < 4; ni++) {
            int r0 = bm + wm + mi * 16 + r;
            int cn = bn + wn + ni * 8 + c * 2;
#pragma unroll
            for (int h2 = 0; h2 < 2; h2++) {
                int gm = r0 + h2 * 8;
#pragma unroll
                for (int j = 0; j < 2; j++) {
                    int gn = cn + j;
                    float v = acc[mi][ni][h2 * 2 + j];
                    if (EPI == EPI_QKV) {
                        int b = gm >> 11, s = gm & (S_LEN - 1);
                        int h = gn >> 6, dh = gn & 63;
                        C[(((size_t)(b * NH + h) * S_LEN + s) << 6) + dh] = v + bias[gn];
                    } else if (EPI == EPI_OPROJ) {
                        float mk = (float)auxm[gm];
                        C[(size_t)gm * ldc + gn] = aux1[(size_t)gm * ldc + gn] + (v + bias[gn]) * mk;
                    } else if (EPI == EPI_GELU) {
                        float u = v + bias[gn];
                        C[(size_t)gm * ldc + gn] = 0.5f * u * (1.0f + erff(u * 0.70710678118654752f));
                    } else if (EPI == EPI_FINAL) {
                        float mk = (float)auxm[gm];
                        C[(size_t)gm * ldc + gn] = (aux1[(size_t)gm * ldc + gn] + v + bias[gn]) * mk;
                    }
                }
            }
        }
    }
}

// ---------------- fused flash attention ----------------
// One CTA = 128 q-rows of one (b,h); 8 warps x 16 q-rows. K-tiles of 128.
// Output written directly in merged [B,S,D] layout.
#define FL_SMEM 104960

__global__ __launch_bounds__(256, 1) void flash_kernel(
    const float* __restrict__ Qg, const float* __restrict__ Kg,
    const float* __restrict__ VTg, const float* __restrict__ bt2,
    const int* __restrict__ mask, float* __restrict__ outMG) {
    extern __shared__ float fsm[];
    float* Qs = fsm;                 // [128][68]
    float* Ks = fsm + 8704;          // [128][68]
    float* Vs = fsm + 17408;         // [64][132]
    float* bs = fsm + 25856;         // [256]
    float* ms = fsm + 26112;         // [128]

    int bh = blockIdx.x;
    int qt = (int)gridDim.y - 1 - blockIdx.y;      // heavy tiles first
    int b = bh >> 4, h = bh & 15;
    int q0 = qt * 128;
    const float* Qp  = Qg  + (size_t)bh * S_LEN * DH;
    const float* Kp  = Kg  + (size_t)bh * S_LEN * DH;
    const float* VTp = VTg + (size_t)bh * S_LEN * DH;
    const float* btr = bt2 + h * S_LEN;
    const int* mr = mask + b * S_LEN;

    int tid = threadIdx.x, lane = tid & 31, w = tid >> 5;
    int wq0 = w * 16;
    int r = lane >> 2, cq = lane & 3;

    // stage Q once (tf32)
#pragma unroll
    for (int i = 0; i < 8; i++) {
        int idx = tid + 256 * i;
        int row = idx >> 4, c = (idx & 15) * 4;
        float4 v = *(const float4*)(Qp + (size_t)(q0 + row) * DH + c);
        float* d = Qs + row * 68 + c;
        d[0] = tfb(v.x); d[1] = tfb(v.y); d[2] = tfb(v.z); d[3] = tfb(v.w);
    }

    uint32_t aQ = smem_u32(Qs) + (uint32_t)(((wq0 + (lane & 15)) * 68 + (lane >> 4) * 4) * 4);
    uint32_t bK = smem_u32(Ks) + (uint32_t)((((lane >> 4) * 8 + (lane & 7)) * 68 + ((lane >> 3) & 1) * 4) * 4);
    uint32_t bV = smem_u32(Vs) + (uint32_t)((((lane >> 4) * 8 + (lane & 7)) * 132 + ((lane >> 3) & 1) * 4) * 4);

    float m0 = -INFINITY, m1 = -INFINITY, l0 = 0.0f, l1 = 0.0f;
    float o[8][4];
#pragma unroll
    for (int ni = 0; ni < 8; ni++)
#pragma unroll
        for (int j = 0; j < 4; j++) o[ni][j] = 0.0f;

    const float cS = 0.125f * 1.44269504088896340736f;   // scale * log2(e)

    for (int kt = 0; kt <= qt; kt++) {
        int k0 = kt * 128;
        // ---- stage K tile [s][dh] (tf32) ----
#pragma unroll
        for (int i = 0; i < 8; i++) {
            int idx = tid + 256 * i;
            int row = idx >> 4, c = (idx & 15) * 4;
            float4 v = *(const float4*)(Kp + (size_t)(k0 + row) * DH + c);
            float* d = Ks + row * 68 + c;
            d[0] = tfb(v.x); d[1] = tfb(v.y); d[2] = tfb(v.z); d[3] = tfb(v.w);
        }
        // ---- stage VT tile [dh][s] (tf32) ----
#pragma unroll
        for (int i = 0; i < 8; i++) {
            int idx = tid + 256 * i;
            int dh = idx >> 5, sg = (idx & 31) * 4;
            float4 v = *(const float4*)(VTp + (size_t)dh * S_LEN + k0 + sg);
            float* d = Vs + dh * 132 + sg;
            d[0] = tfb(v.x); d[1] = tfb(v.y); d[2] = tfb(v.z); d[3] = tfb(v.w);
        }
        // ---- stage bias slice + pad mask ----
        if (tid < 255) {
            int dd = q0 - k0 - 127 + tid;
            bs[tid] = (dd >= 0) ? btr[dd] : 0.0f;
        }
        if (tid < 128) ms[tid] = mr[k0 + tid] ? 0.0f : -INFINITY;
        __syncthreads();

        // ---- S = Q K^T ----
        float s[16][4];
#pragma unroll
        for (int nt = 0; nt < 16; nt++)
#pragma unroll
            for (int j = 0; j < 4; j++) s[nt][j] = 0.0f;
#pragma unroll
        for (int ks = 0; ks < 8; ks++) {
            uint32_t af[4];
            ldsm4(af, aQ + (uint32_t)(ks * 32));
#pragma unroll
            for (int pi = 0; pi < 8; pi++) {
                uint32_t bf[4];
                ldsm4(bf, bK + (uint32_t)(pi * 16 * 68 * 4) + (uint32_t)(ks * 32));
                mma_tf32(s[pi * 2], af, bf);
                mma_tf32(s[pi * 2 + 1], af, bf + 2);
            }
        }

        // ---- logits (log2 domain) + masks + running max ----
        bool diag = (kt == qt);
        float tmax0 = -INFINITY, tmax1 = -INFINITY;
#pragma unroll
        for (int nt = 0; nt < 16; nt++) {
#pragma unroll
            for (int jj = 0; jj < 2; jj++) {
                int kc = nt * 8 + cq * 2 + jj;
                float mk = ms[kc];
                float v0 = s[nt][jj]     * cS + bs[127 + wq0 + r - kc] + mk;
                float v1 = s[nt][jj + 2] * cS + bs[135 + wq0 + r - kc] + mk;
                if (diag && kc > wq0 + r)     v0 = -INFINITY;
                if (diag && kc > wq0 + r + 8) v1 = -INFINITY;
                s[nt][jj] = v0; s[nt][jj + 2] = v1;
                tmax0 = fmaxf(tmax0, v0); tmax1 = fmaxf(tmax1, v1);
            }
        }
        tmax0 = fmaxf(tmax0, __shfl_xor_sync(0xffffffffu, tmax0, 1));
        tmax0 = fmaxf(tmax0, __shfl_xor_sync(0xffffffffu, tmax0, 2));
        tmax1 = fmaxf(tmax1, __shfl_xor_sync(0xffffffffu, tmax1, 1));
        tmax1 = fmaxf(tmax1, __shfl_xor_sync(0xffffffffu, tmax1, 2));
        float mn0 = fmaxf(m0, tmax0), mn1 = fmaxf(m1, tmax1);
        float f0 = (m0 > -1e37f) ? ex2(m0 - mn0) : 0.0f;
        float f1 = (m1 > -1e37f) ? ex2(m1 - mn1) : 0.0f;

        // ---- P = 2^(l2 - m), tf32-rounded; row sums ----
        float ps0 = 0.0f, ps1 = 0.0f;
#pragma unroll
        for (int nt = 0; nt < 16; nt++) {
#pragma unroll
            for (int jj = 0; jj < 2; jj++) {
                float p0 = (mn0 > -1e37f) ? ex2(s[nt][jj] - mn0)     : 0.0f;
                float p1 = (mn1 > -1e37f) ? ex2(s[nt][jj + 2] - mn1) : 0.0f;
                p0 = tfb(p0); p1 = tfb(p1);
                s[nt][jj] = p0; s[nt][jj + 2] = p1;
                ps0 += p0; ps1 += p1;
            }
        }
        ps0 += __shfl_xor_sync(0xffffffffu, ps0, 1);
        ps0 += __shfl_xor_sync(0xffffffffu, ps0, 2);
        ps1 += __shfl_xor_sync(0xffffffffu, ps1, 1);
        ps1 += __shfl_xor_sync(0xffffffffu, ps1, 2);
        l0 = l0 * f0 + ps0; l1 = l1 * f1 + ps1;
        m0 = mn0; m1 = mn1;

        // ---- rescale O ----
#pragma unroll
        for (int ni = 0; ni < 8; ni++) {
            o[ni][0] *= f0; o[ni][1] *= f0; o[ni][2] *= f1; o[ni][3] *= f1;
        }

        // ---- O += P @ V (A-frags from registers via quad shuffles) ----
        int base = lane & ~3;
        int src1 = base + (cq >> 1), src2 = src1 + 2;
        bool odd = (cq & 1);
#pragma unroll
        for (int ks = 0; ks < 16; ks++) {
            float c0 = s[ks][0], c1 = s[ks][1], c2 = s[ks][2], c3 = s[ks][3];
            float x0 = __shfl_sync(0xffffffffu, c0, src1);
            float x1 = __shfl_sync(0xffffffffu, c1, src1);
            float x2 = __shfl_sync(0xffffffffu, c0, src2);
            float x3 = __shfl_sync(0xffffffffu, c1, src2);
            float y0 = __shfl_sync(0xffffffffu, c2, src1);
            float y1 = __shfl_sync(0xffffffffu, c3, src1);
            float y2 = __shfl_sync(0xffffffffu, c2, src2);
            float y3 = __shfl_sync(0xffffffffu, c3, src2);
            uint32_t af[4];
            af[0] = __float_as_uint(odd ? x1 : x0);   // row r,   k = cq
            af[1] = __float_as_uint(odd ? y1 : y0);   // row r+8, k = cq
            af[2] = __float_as_uint(odd ? x3 : x2);   // row r,   k = cq+4
            af[3] = __float_as_uint(odd ? y3 : y2);   // row r+8, k = cq+4
#pragma unroll
            for (int pi = 0; pi < 4; pi++) {
                uint32_t bf[4];
                ldsm4(bf, bV + (uint32_t)(pi * 16 * 132 * 4) + (uint32_t)(ks * 32));
                mma_tf32(o[pi * 2], af, bf);
                mma_tf32(o[pi * 2 + 1], af, bf + 2);
            }
        }
        __syncthreads();
    }

    // ---- finalize: O /= l, write merged layout ----
    float inv0 = (l0 > 0.0f) ? 1.0f / l0 : 0.0f;
    float inv1 = (l1 > 0.0f) ? 1.0f / l1 : 0.0f;
    int qrow = q0 + wq0 + r;
    size_t row0 = ((size_t)b * S_LEN + qrow) * DM + h * 64;
    size_t row1 = row0 + (size_t)8 * DM;
#pragma unroll
    for (int ni = 0; ni < 8; ni++) {
        int dh = ni * 8 + cq * 2;
        outMG[row0 + dh]     = o[ni][0] * inv0;
        outMG[row0 + dh + 1] = o[ni][1] * inv0;
        outMG[row1 + dh]     = o[ni][2] * inv1;
        outMG[row1 + dh + 1] = o[ni][3] * inv1;
    }
}

// ---------------- launch ----------------
extern "C" void kernel_launch(void* const* d_in, const int* in_sizes, int n_in,
                              void* d_out, int out_size) {
    const float* hidden = (const float*)d_in[0];
    const int*   mask   = (const int*)d_in[1];
    const float* wq = (const float*)d_in[2];  const float* bq = (const float*)d_in[3];
    const float* wk = (const float*)d_in[4];  const float* bk = (const float*)d_in[5];
    const float* wv = (const float*)d_in[6];  const float* bv = (const float*)d_in[7];
    const float* wo = (const float*)d_in[8];  const float* bo = (const float*)d_in[9];
    const float* rb = (const float*)d_in[10];
    const float* ln1g = (const float*)d_in[11]; const float* ln1b = (const float*)d_in[12];
    const float* ln2g = (const float*)d_in[13]; const float* ln2b = (const float*)d_in[14];
    const float* w1 = (const float*)d_in[15]; const float* b1 = (const float*)d_in[16];
    const float* w2 = (const float*)d_in[17]; const float* b2 = (const float*)d_in[18];
    float* out = (float*)d_out;

    float *X, *Q, *K, *V, *VT, *MG, *H1, *FFb, *BT, *WT;
    cudaGetSymbolAddress((void**)&X,  g_X);
    cudaGetSymbolAddress((void**)&Q,  g_Q);
    cudaGetSymbolAddress((void**)&K,  g_K);
    cudaGetSymbolAddress((void**)&V,  g_V);
    cudaGetSymbolAddress((void**)&VT, g_VT);
    cudaGetSymbolAddress((void**)&MG, g_MG);
    cudaGetSymbolAddress((void**)&H1, g_H1);
    cudaGetSymbolAddress((void**)&FFb, g_FF);
    cudaGetSymbolAddress((void**)&BT, g_BT);
    cudaGetSymbolAddress((void**)&WT, g_WT);

    cudaFuncSetAttribute(flash_kernel, cudaFuncAttributeMaxDynamicSharedMemorySize, FL_SMEM);

    const size_t M1 = 1024 * 1024;
    wtrans_kernel<<<dim3(32, 32), 256>>>(wq, WT + 0 * M1, DM, DM);
    wtrans_kernel<<<dim3(32, 32), 256>>>(wk, WT + 1 * M1, DM, DM);
    wtrans_kernel<<<dim3(32, 32), 256>>>(wv, WT + 2 * M1, DM, DM);
    wtrans_kernel<<<dim3(32, 32), 256>>>(wo, WT + 3 * M1, DM, DM);
    wtrans_kernel<<<dim3(128, 32), 256>>>(w1, WT + 4 * M1, DM, DFF);
    wtrans_kernel<<<dim3(32, 128), 256>>>(w2, WT + 8 * M1, DFF, DM);

    biastab_kernel<<<(NH * S_LEN + 255) / 256, 256>>>(rb, BT);
    ln_kernel<<<ROWS, 256>>>(hidden, ln1g, ln1b, X);

    // QKV projections (scatter into [B,H,S,DH])
    dim3 gProj(DM / 128, ROWS / 128);
    mgemm<EPI_QKV><<<gProj, 256>>>(X, WT + 0 * M1, bq, Q, DM, DM, DM, DM, 0, nullptr, nullptr);
    mgemm<EPI_QKV><<<gProj, 256>>>(X, WT + 1 * M1, bk, K, DM, DM, DM, DM, 0, nullptr, nullptr);
    mgemm<EPI_QKV><<<gProj, 256>>>(X, WT + 2 * M1, bv, V, DM, DM, DM, DM, 0, nullptr, nullptr);

    // V transpose per (b,h): [s][dh] -> [dh][s]
    vtrans_kernel<<<dim3(S_LEN / 32, DH / 32, BATCH * NH), 256>>>(V, VT);

    // fused attention -> merged [B,S,D]
    flash_kernel<<<dim3(BATCH * NH, S_LEN / 128), 256, FL_SMEM>>>(Q, K, VT, BT, mask, MG);

    // O projection + mask + residual
    mgemm<EPI_OPROJ><<<gProj, 256>>>(MG, WT + 3 * M1, bo, H1, DM, DM, DM, DM, DM, hidden, mask);

    ln_kernel<<<ROWS, 256>>>(H1, ln2g, ln2b, X);

    // FFN up + exact GELU
    dim3 gF1(DFF / 128, ROWS / 128);
    mgemm<EPI_GELU><<<gF1, 256>>>(X, WT + 4 * M1, b1, FFb, DFF, DM, DM, DM, DFF, nullptr, nullptr);

    // FFN down + residual + mask
    mgemm<EPI_FINAL><<<gProj, 256>>>(FFb, WT + 8 * M1, b2, out, DM, DFF, DFF, DFF, DM, H1, mask);
}

// round 7
// speedup vs baseline: 5.0849x; 1.2408x over previous
#include <cuda_runtime.h>
#include <cuda_fp16.h>
#include <math.h>
#include <stdint.h>

// ---------------- problem constants ----------------
#define S_LEN 2048
#define NH    16
#define DH    64
#define DM    1024
#define DFF   4096
#define BATCH 2
#define ROWS  (BATCH * S_LEN)   // 4096
#define QKVSZ (BATCH * NH * S_LEN * DH)   // 4M

// ---------------- scratch ----------------
__device__ float g_X [ROWS * DM];
__device__ float g_QKV[3 * QKVSZ];
__device__ float g_VT[QKVSZ];
__device__ float g_MG[ROWS * DM];
__device__ float g_H1[ROWS * DM];
__device__ float g_FF[ROWS * DFF];
__device__ float g_BT[NH * S_LEN];
__device__ float g_B3[3 * DM];
__device__ __half g_WTH[12 * 1024 * 1024];  // fp16 transposed weights: qkv @0..3M; o @3M; w1 @4M; w2 @8M

// ---------------- helpers ----------------
__device__ __forceinline__ uint32_t smem_u32(const void* p) {
    uint32_t a;
    asm("{ .reg .u64 t; cvta.to.shared.u64 t, %1; cvt.u32.u64 %0, t; }" : "=r"(a) : "l"(p));
    return a;
}
__device__ __forceinline__ uint32_t f2tf(float f) {
    uint32_t u;
    asm("cvt.rna.tf32.f32 %0, %1;" : "=r"(u) : "f"(f));
    return u;
}
__device__ __forceinline__ float tfb(float f) {
    return __uint_as_float(f2tf(f));
}
__device__ __forceinline__ float ex2(float x) {
    float y;
    asm("ex2.approx.ftz.f32 %0, %1;" : "=f"(y) : "f"(x));
    return y;
}
__device__ __forceinline__ void ldsm4(uint32_t* r, uint32_t addr) {
    asm volatile("ldmatrix.sync.aligned.m8n8.x4.shared.b16 {%0,%1,%2,%3}, [%4];"
                 : "=r"(r[0]), "=r"(r[1]), "=r"(r[2]), "=r"(r[3]) : "r"(addr));
}
__device__ __forceinline__ void mma_tf32(float* d, const uint32_t* a, const uint32_t* b) {
    asm volatile(
        "mma.sync.aligned.m16n8k8.row.col.f32.tf32.tf32.f32 "
        "{%0,%1,%2,%3}, {%4,%5,%6,%7}, {%8,%9}, {%0,%1,%2,%3};"
        : "+f"(d[0]), "+f"(d[1]), "+f"(d[2]), "+f"(d[3])
        : "r"(a[0]), "r"(a[1]), "r"(a[2]), "r"(a[3]), "r"(b[0]), "r"(b[1]));
}
__device__ __forceinline__ void mma_f16(float* d, const uint32_t* a, uint32_t b0, uint32_t b1) {
    asm volatile(
        "mma.sync.aligned.m16n8k16.row.col.f32.f16.f16.f32 "
        "{%0,%1,%2,%3}, {%4,%5,%6,%7}, {%8,%9}, {%0,%1,%2,%3};"
        : "+f"(d[0]), "+f"(d[1]), "+f"(d[2]), "+f"(d[3])
        : "r"(a[0]), "r"(a[1]), "r"(a[2]), "r"(a[3]), "r"(b0), "r"(b1));
}
__device__ __forceinline__ uint32_t pk2h(float a, float b) {
    __half2 h = __floats2half2_rn(a, b);     // x = a (low), y = b (high)
    return *reinterpret_cast<uint32_t*>(&h);
}

enum { EPI_QKV3 = 0, EPI_OPROJ = 3, EPI_GELU = 4, EPI_FINAL = 5 };

// ---------------- weight transpose + fp16 convert: W[K,N] -> WT[N,K] (fp16) ----------------
__global__ __launch_bounds__(256) void wtrans_kernel(const float* __restrict__ W,
                                                     __half* __restrict__ WT, int K, int N) {
    __shared__ float t[32][33];
    int n0 = blockIdx.x * 32, k0 = blockIdx.y * 32;
    int tx = threadIdx.x & 31, ty = threadIdx.x >> 5;
#pragma unroll
    for (int j = 0; j < 32; j += 8)
        t[ty + j][tx] = W[(size_t)(k0 + ty + j) * N + n0 + tx];
    __syncthreads();
#pragma unroll
    for (int j = 0; j < 32; j += 8)
        WT[(size_t)(n0 + ty + j) * K + k0 + tx] = __float2half_rn(t[tx][ty + j]);
}

// ---------------- bias concat for fused QKV ----------------
__global__ void bcat_kernel(const float* __restrict__ bq, const float* __restrict__ bk,
                            const float* __restrict__ bv, float* __restrict__ b3) {
    int i = blockIdx.x * 256 + threadIdx.x;
    if (i >= 3 * DM) return;
    const float* s = (i < DM) ? bq : ((i < 2 * DM) ? bk : bv);
    b3[i] = s[i & (DM - 1)];
}

// ---------------- V transpose per (b,h): V[s][d] -> VT[d][s] ----------------
__global__ __launch_bounds__(256) void vtrans_kernel(const float* __restrict__ V,
                                                     float* __restrict__ VT) {
    __shared__ float t[32][33];
    int bh = blockIdx.z;
    int s0 = blockIdx.x * 32, d0 = blockIdx.y * 32;
    const float* src = V + (size_t)bh * S_LEN * DH;
    float* dst = VT + (size_t)bh * S_LEN * DH;
    int tx = threadIdx.x & 31, ty = threadIdx.x >> 5;
#pragma unroll
    for (int j = 0; j < 32; j += 8)
        t[ty + j][tx] = src[(size_t)(s0 + ty + j) * DH + d0 + tx];
    __syncthreads();
#pragma unroll
    for (int j = 0; j < 32; j += 8)
        dst[(size_t)(d0 + ty + j) * S_LEN + s0 + tx] = t[tx][ty + j];
}

// ---------------- relative-position bias table (prescaled by log2 e) ----------------
__global__ void biastab_kernel(const float* __restrict__ rel_bias,
                               float* __restrict__ tab) {
    int idx = blockIdx.x * blockDim.x + threadIdx.x;
    if (idx >= NH * S_LEN) return;
    int h = idx / S_LEN;
    int d = idx % S_LEN;
    int bucket;
    if (d < 16) {
        bucket = d;
    } else {
        float ratio = logf((float)d * (1.0f / 16.0f)) / logf(8.0f);
        int large = 16 + (int)(ratio * 16.0f);
        bucket = large < 31 ? large : 31;
    }
    tab[h * S_LEN + d] = rel_bias[bucket * NH + h] * 1.44269504088896340736f;
}

// ---------------- layernorm ----------------
__global__ __launch_bounds__(256) void ln_kernel(const float* __restrict__ x,
                                                 const float* __restrict__ g,
                                                 const float* __restrict__ bta,
                                                 float* __restrict__ y) {
    int row = blockIdx.x;
    int t = threadIdx.x;
    const float4* xr = (const float4*)(x + (size_t)row * DM);
    float4 v = xr[t];
    float s  = v.x + v.y + v.z + v.w;
    float ss = v.x * v.x + v.y * v.y + v.z * v.z + v.w * v.w;
    __shared__ float sh_s[256], sh_q[256];
    sh_s[t] = s; sh_q[t] = ss;
    __syncthreads();
    for (int o = 128; o > 0; o >>= 1) {
        if (t < o) { sh_s[t] += sh_s[t + o]; sh_q[t] += sh_q[t + o]; }
        __syncthreads();
    }
    float mean = sh_s[0] * (1.0f / DM);
    float var  = sh_q[0] * (1.0f / DM) - mean * mean;
    float rstd = rsqrtf(var + 1e-5f);
    float4 gv = ((const float4*)g)[t];
    float4 bv = ((const float4*)bta)[t];
    float4 o4;
    o4.x = (v.x - mean) * rstd * gv.x + bv.x;
    o4.y = (v.y - mean) * rstd * gv.y + bv.y;
    o4.z = (v.z - mean) * rstd * gv.z + bv.z;
    o4.w = (v.w - mean) * rstd * gv.w + bv.w;
    ((float4*)(y + (size_t)row * DM))[t] = o4;
}

// ---------------- fp16 mma.sync GEMM (projections/FFN) ----------------
// C[M,N] = A[M,K](fp32) * WT^T, WT[N,K] fp16. Tile 128x128, BK=32 double-buffered.
// 8 warps (2x4), warp tile 64x32, m16n8k16.
template <int EPI>
__global__ __launch_bounds__(256, 2) void hgemm(
    const float* __restrict__ A, const __half* __restrict__ Bm,
    const float* __restrict__ bias, float* __restrict__ C,
    int N, int K, int lda, int ldb, int ldc,
    const float* __restrict__ aux1, const int* __restrict__ auxm) {
    int bn = blockIdx.x * 128;
    int bm = blockIdx.y * 128;

    __shared__ __align__(16) uint32_t As[2][128][20];   // 16 data u32 (32 halves) + 4 pad
    __shared__ __align__(16) uint32_t Bs[2][128][20];

    int tid = threadIdx.x;
    int lane = tid & 31;
    int w = tid >> 5;
    int wm = (w & 1) * 64;
    int wn = (w >> 1) * 32;

    float acc[4][4][4];
#pragma unroll
    for (int mi = 0; mi < 4; mi++)
#pragma unroll
        for (int ni = 0; ni < 4; ni++)
#pragma unroll
            for (int r = 0; r < 4; r++) acc[mi][ni][r] = 0.0f;

    // staging: row = tid>>1 (128 rows), half-row = (tid&1)*16 elements
    int srow = tid >> 1;
    int shalf = (tid & 1);
    const float* Ap = A + (size_t)(bm + srow) * lda + shalf * 16;
    const __half* Bp = Bm + (size_t)(bn + srow) * ldb + shalf * 16;

    uint32_t As_u = smem_u32(As);
    uint32_t Bs_u = smem_u32(Bs);
    // ldmatrix addr: m = (lane&7) + ((lane>>3)&1)*8 ; k-halfoffset (lane>>4)*8 halves = *4 u32
    uint32_t lrow = (uint32_t)((lane & 7) + ((lane >> 3) & 1) * 8);
    uint32_t lk4  = (uint32_t)((lane >> 4) * 4);
    uint32_t a_addr = As_u + ((wm + lrow) * 20 + lk4) * 4;
    uint32_t b_addr = Bs_u + ((wn + lrow) * 20 + lk4) * 4;

    int ntiles = K >> 5;

    float4 a0, a1, a2, a3;
    uint4 bload0, bload1;
    // prologue: tile 0
    a0 = *(const float4*)(Ap);
    a1 = *(const float4*)(Ap + 4);
    a2 = *(const float4*)(Ap + 8);
    a3 = *(const float4*)(Ap + 12);
    bload0 = *(const uint4*)(Bp);
    bload1 = *(const uint4*)(Bp + 8);
    {
        uint32_t* da = &As[0][srow][shalf * 8];
        da[0] = pk2h(a0.x, a0.y); da[1] = pk2h(a0.z, a0.w);
        da[2] = pk2h(a1.x, a1.y); da[3] = pk2h(a1.z, a1.w);
        da[4] = pk2h(a2.x, a2.y); da[5] = pk2h(a2.z, a2.w);
        da[6] = pk2h(a3.x, a3.y); da[7] = pk2h(a3.z, a3.w);
        uint32_t* db = &Bs[0][srow][shalf * 8];
        *(uint4*)db = bload0;
        *(uint4*)(db + 4) = bload1;
    }
    __syncthreads();

    int buf = 0;
    for (int kt = 0; kt < ntiles; kt++) {
        bool more = (kt + 1 < ntiles);
        if (more) {
            int k0 = (kt + 1) * 32;
            a0 = *(const float4*)(Ap + k0);
            a1 = *(const float4*)(Ap + k0 + 4);
            a2 = *(const float4*)(Ap + k0 + 8);
            a3 = *(const float4*)(Ap + k0 + 12);
            bload0 = *(const uint4*)(Bp + k0);
            bload1 = *(const uint4*)(Bp + k0 + 8);
        }

        uint32_t abase = a_addr + (uint32_t)(buf * 10240);
        uint32_t bbase = b_addr + (uint32_t)(buf * 10240);
#pragma unroll
        for (int ks = 0; ks < 2; ks++) {
            uint32_t koff = (uint32_t)(ks * 32);        // 8 u32 = 16 halves
            uint32_t afr[4][4], bfr[2][4];
#pragma unroll
            for (int mi = 0; mi < 4; mi++)
                ldsm4(afr[mi], abase + (uint32_t)(mi * 16 * 80) + koff);
#pragma unroll
            for (int pi = 0; pi < 2; pi++)
                ldsm4(bfr[pi], bbase + (uint32_t)(pi * 16 * 80) + koff);
#pragma unroll
            for (int mi = 0; mi < 4; mi++)
#pragma unroll
                for (int ni = 0; ni < 4; ni++) {
                    int pi = ni >> 1, od = ni & 1;
                    mma_f16(acc[mi][ni], afr[mi], bfr[pi][od], bfr[pi][od + 2]);
                }
        }

        if (more) {
            int nb2 = buf ^ 1;
            uint32_t* da = &As[nb2][srow][shalf * 8];
            da[0] = pk2h(a0.x, a0.y); da[1] = pk2h(a0.z, a0.w);
            da[2] = pk2h(a1.x, a1.y); da[3] = pk2h(a1.z, a1.w);
            da[4] = pk2h(a2.x, a2.y); da[5] = pk2h(a2.z, a2.w);
            da[6] = pk2h(a3.x, a3.y); da[7] = pk2h(a3.z, a3.w);
            uint32_t* db = &Bs[nb2][srow][shalf * 8];
            *(uint4*)db = bload0;
            *(uint4*)(db + 4) = bload1;
        }
        __syncthreads();
        buf ^= 1;
    }

    // ---- epilogue ----
    int r = lane >> 2, c = lane & 3;
#pragma unroll
    for (int mi = 0; mi < 4; mi++) {
#pragma unroll
        for (int ni = 0; ni < 4; ni++) {
            int r0 = bm + wm + mi * 16 + r;
            int cn = bn + wn + ni * 8 + c * 2;
#pragma unroll
            for (int h2 = 0; h2 < 2; h2++) {
                int gm = r0 + h2 * 8;
#pragma unroll
                for (int j = 0; j < 2; j++) {
                    int gn = cn + j;
                    float v = acc[mi][ni][h2 * 2 + j];
                    if (EPI == EPI_QKV3) {
                        int sel = gn >> 10;
                        int col = gn & (DM - 1);
                        int b = gm >> 11, s = gm & (S_LEN - 1);
                        int h = col >> 6, dh = col & 63;
                        C[(size_t)sel * QKVSZ + (((size_t)(b * NH + h) * S_LEN + s) << 6) + dh]
                            = v + bias[gn];
                    } else if (EPI == EPI_OPROJ) {
                        float mk = (float)auxm[gm];
                        C[(size_t)gm * ldc + gn] = aux1[(size_t)gm * ldc + gn] + (v + bias[gn]) * mk;
                    } else if (EPI == EPI_GELU) {
                        float u = v + bias[gn];
                        C[(size_t)gm * ldc + gn] = 0.5f * u * (1.0f + erff(u * 0.70710678118654752f));
                    } else if (EPI == EPI_FINAL) {
                        float mk = (float)auxm[gm];
                        C[(size_t)gm * ldc + gn] = (aux1[(size_t)gm * ldc + gn] + v + bias[gn]) * mk;
                    }
                }
            }
        }
    }
}

// ---------------- fused flash attention (tf32) ----------------
#define FL_SMEM 104960

__global__ __launch_bounds__(256, 1) void flash_kernel(
    const float* __restrict__ Qg, const float* __restrict__ Kg,
    const float* __restrict__ VTg, const float* __restrict__ bt2,
    const int* __restrict__ mask, float* __restrict__ outMG) {
    extern __shared__ float fsm[];
    float* Qs = fsm;                 // [128][68]
    float* Ks = fsm + 8704;          // [128][68]
    float* Vs = fsm + 17408;         // [64][132]
    float* bs = fsm + 25856;         // [256]
    float* ms = fsm + 26112;         // [128]

    int bh = blockIdx.x;
    int qt = (int)gridDim.y - 1 - blockIdx.y;
    int b = bh >> 4, h = bh & 15;
    int q0 = qt * 128;
    const float* Qp  = Qg  + (size_t)bh * S_LEN * DH;
    const float* Kp  = Kg  + (size_t)bh * S_LEN * DH;
    const float* VTp = VTg + (size_t)bh * S_LEN * DH;
    const float* btr = bt2 + h * S_LEN;
    const int* mr = mask + b * S_LEN;

    int tid = threadIdx.x, lane = tid & 31, w = tid >> 5;
    int wq0 = w * 16;
    int r = lane >> 2, cq = lane & 3;

#pragma unroll
    for (int i = 0; i < 8; i++) {
        int idx = tid + 256 * i;
        int row = idx >> 4, c = (idx & 15) * 4;
        float4 v = *(const float4*)(Qp + (size_t)(q0 + row) * DH + c);
        float* d = Qs + row * 68 + c;
        d[0] = tfb(v.x); d[1] = tfb(v.y); d[2] = tfb(v.z); d[3] = tfb(v.w);
    }

    uint32_t aQ = smem_u32(Qs) + (uint32_t)(((wq0 + (lane & 15)) * 68 + (lane >> 4) * 4) * 4);
    uint32_t bK = smem_u32(Ks) + (uint32_t)((((lane >> 4) * 8 + (lane & 7)) * 68 + ((lane >> 3) & 1) * 4) * 4);
    uint32_t bV = smem_u32(Vs) + (uint32_t)((((lane >> 4) * 8 + (lane & 7)) * 132 + ((lane >> 3) & 1) * 4) * 4);

    float m0 = -INFINITY, m1 = -INFINITY, l0 = 0.0f, l1 = 0.0f;
    float o[8][4];
#pragma unroll
    for (int ni = 0; ni < 8; ni++)
#pragma unroll
        for (int j = 0; j < 4; j++) o[ni][j] = 0.0f;

    const float cS = 0.125f * 1.44269504088896340736f;

    for (int kt = 0; kt <= qt; kt++) {
        int k0 = kt * 128;
#pragma unroll
        for (int i = 0; i < 8; i++) {
            int idx = tid + 256 * i;
            int row = idx >> 4, c = (idx & 15) * 4;
            float4 v = *(const float4*)(Kp + (size_t)(k0 + row) * DH + c);
            float* d = Ks + row * 68 + c;
            d[0] = tfb(v.x); d[1] = tfb(v.y); d[2] = tfb(v.z); d[3] = tfb(v.w);
        }
#pragma unroll
        for (int i = 0; i < 8; i++) {
            int idx = tid + 256 * i;
            int dh = idx >> 5, sg = (idx & 31) * 4;
            float4 v = *(const float4*)(VTp + (size_t)dh * S_LEN + k0 + sg);
            float* d = Vs + dh * 132 + sg;
            d[0] = tfb(v.x); d[1] = tfb(v.y); d[2] = tfb(v.z); d[3] = tfb(v.w);
        }
        if (tid < 255) {
            int dd = q0 - k0 - 127 + tid;
            bs[tid] = (dd >= 0) ? btr[dd] : 0.0f;
        }
        if (tid < 128) ms[tid] = mr[k0 + tid] ? 0.0f : -INFINITY;
        __syncthreads();

        float s[16][4];
#pragma unroll
        for (int nt = 0; nt < 16; nt++)
#pragma unroll
            for (int j = 0; j < 4; j++) s[nt][j] = 0.0f;
#pragma unroll
        for (int ks = 0; ks < 8; ks++) {
            uint32_t af[4];
            ldsm4(af, aQ + (uint32_t)(ks * 32));
#pragma unroll
            for (int pi = 0; pi < 8; pi++) {
                uint32_t bf[4];
                ldsm4(bf, bK + (uint32_t)(pi * 16 * 68 * 4) + (uint32_t)(ks * 32));
                mma_tf32(s[pi * 2], af, bf);
                mma_tf32(s[pi * 2 + 1], af, bf + 2);
            }
        }

        bool diag = (kt == qt);
        float tmax0 = -INFINITY, tmax1 = -INFINITY;
#pragma unroll
        for (int nt = 0; nt < 16; nt++) {
#pragma unroll
            for (int jj = 0; jj < 2; jj++) {
                int kc = nt * 8 + cq * 2 + jj;
                float mk = ms[kc];
                float v0 = s[nt][jj]     * cS + bs[127 + wq0 + r - kc] + mk;
                float v1 = s[nt][jj + 2] * cS + bs[135 + wq0 + r - kc] + mk;
                if (diag && kc > wq0 + r)     v0 = -INFINITY;
                if (diag && kc > wq0 + r + 8) v1 = -INFINITY;
                s[nt][jj] = v0; s[nt][jj + 2] = v1;
                tmax0 = fmaxf(tmax0, v0); tmax1 = fmaxf(tmax1, v1);
            }
        }
        tmax0 = fmaxf(tmax0, __shfl_xor_sync(0xffffffffu, tmax0, 1));
        tmax0 = fmaxf(tmax0, __shfl_xor_sync(0xffffffffu, tmax0, 2));
        tmax1 = fmaxf(tmax1, __shfl_xor_sync(0xffffffffu, tmax1, 1));
        tmax1 = fmaxf(tmax1, __shfl_xor_sync(0xffffffffu, tmax1, 2));
        float mn0 = fmaxf(m0, tmax0), mn1 = fmaxf(m1, tmax1);
        float f0 = (m0 > -1e37f) ? ex2(m0 - mn0) : 0.0f;
        float f1 = (m1 > -1e37f) ? ex2(m1 - mn1) : 0.0f;

        float ps0 = 0.0f, ps1 = 0.0f;
#pragma unroll
        for (int nt = 0; nt < 16; nt++) {
#pragma unroll
            for (int jj = 0; jj < 2; jj++) {
                float p0 = (mn0 > -1e37f) ? ex2(s[nt][jj] - mn0)     : 0.0f;
                float p1 = (mn1 > -1e37f) ? ex2(s[nt][jj + 2] - mn1) : 0.0f;
                p0 = tfb(p0); p1 = tfb(p1);
                s[nt][jj] = p0; s[nt][jj + 2] = p1;
                ps0 += p0; ps1 += p1;
            }
        }
        ps0 += __shfl_xor_sync(0xffffffffu, ps0, 1);
        ps0 += __shfl_xor_sync(0xffffffffu, ps0, 2);
        ps1 += __shfl_xor_sync(0xffffffffu, ps1, 1);
        ps1 += __shfl_xor_sync(0xffffffffu, ps1, 2);
        l0 = l0 * f0 + ps0; l1 = l1 * f1 + ps1;
        m0 = mn0; m1 = mn1;

#pragma unroll
        for (int ni = 0; ni < 8; ni++) {
            o[ni][0] *= f0; o[ni][1] *= f0; o[ni][2] *= f1; o[ni][3] *= f1;
        }

        int base = lane & ~3;
        int src1 = base + (cq >> 1), src2 = src1 + 2;
        bool odd = (cq & 1);
#pragma unroll
        for (int ks = 0; ks < 16; ks++) {
            float c0 = s[ks][0], c1 = s[ks][1], c2 = s[ks][2], c3 = s[ks][3];
            float x0 = __shfl_sync(0xffffffffu, c0, src1);
            float x1 = __shfl_sync(0xffffffffu, c1, src1);
            float x2 = __shfl_sync(0xffffffffu, c0, src2);
            float x3 = __shfl_sync(0xffffffffu, c1, src2);
            float y0 = __shfl_sync(0xffffffffu, c2, src1);
            float y1 = __shfl_sync(0xffffffffu, c3, src1);
            float y2 = __shfl_sync(0xffffffffu, c2, src2);
            float y3 = __shfl_sync(0xffffffffu, c3, src2);
            uint32_t af[4];
            af[0] = __float_as_uint(odd ? x1 : x0);
            af[1] = __float_as_uint(odd ? y1 : y0);
            af[2] = __float_as_uint(odd ? x3 : x2);
            af[3] = __float_as_uint(odd ? y3 : y2);
#pragma unroll
            for (int pi = 0; pi < 4; pi++) {
                uint32_t bf[4];
                ldsm4(bf, bV + (uint32_t)(pi * 16 * 132 * 4) + (uint32_t)(ks * 32));
                mma_tf32(o[pi * 2], af, bf);
                mma_tf32(o[pi * 2 + 1], af, bf + 2);
            }
        }
        __syncthreads();
    }

    float inv0 = (l0 > 0.0f) ? 1.0f / l0 : 0.0f;
    float inv1 = (l1 > 0.0f) ? 1.0f / l1 : 0.0f;
    int qrow = q0 + wq0 + r;
    size_t row0 = ((size_t)b * S_LEN + qrow) * DM + h * 64;
    size_t row1 = row0 + (size_t)8 * DM;
#pragma unroll
    for (int ni = 0; ni < 8; ni++) {
        int dh = ni * 8 + cq * 2;
        outMG[row0 + dh]     = o[ni][0] * inv0;
        outMG[row0 + dh + 1] = o[ni][1] * inv0;
        outMG[row1 + dh]     = o[ni][2] * inv1;
        outMG[row1 + dh + 1] = o[ni][3] * inv1;
    }
}

// ---------------- launch ----------------
extern "C" void kernel_launch(void* const* d_in, const int* in_sizes, int n_in,
                              void* d_out, int out_size) {
    const float* hidden = (const float*)d_in[0];
    const int*   mask   = (const int*)d_in[1];
    const float* wq = (const float*)d_in[2];  const float* bq = (const float*)d_in[3];
    const float* wk = (const float*)d_in[4];  const float* bk = (const float*)d_in[5];
    const float* wv = (const float*)d_in[6];  const float* bv = (const float*)d_in[7];
    const float* wo = (const float*)d_in[8];  const float* bo = (const float*)d_in[9];
    const float* rb = (const float*)d_in[10];
    const float* ln1g = (const float*)d_in[11]; const float* ln1b = (const float*)d_in[12];
    const float* ln2g = (const float*)d_in[13]; const float* ln2b = (const float*)d_in[14];
    const float* w1 = (const float*)d_in[15]; const float* b1 = (const float*)d_in[16];
    const float* w2 = (const float*)d_in[17]; const float* b2 = (const float*)d_in[18];
    float* out = (float*)d_out;

    float *X, *QKV, *VT, *MG, *H1, *FFb, *BT, *B3;
    __half* WT;
    cudaGetSymbolAddress((void**)&X,   g_X);
    cudaGetSymbolAddress((void**)&QKV, g_QKV);
    cudaGetSymbolAddress((void**)&VT,  g_VT);
    cudaGetSymbolAddress((void**)&MG,  g_MG);
    cudaGetSymbolAddress((void**)&H1,  g_H1);
    cudaGetSymbolAddress((void**)&FFb, g_FF);
    cudaGetSymbolAddress((void**)&BT,  g_BT);
    cudaGetSymbolAddress((void**)&B3,  g_B3);
    cudaGetSymbolAddress((void**)&WT,  g_WTH);

    cudaFuncSetAttribute(flash_kernel, cudaFuncAttributeMaxDynamicSharedMemorySize, FL_SMEM);

    const size_t M1 = 1024 * 1024;
    float *Q = QKV, *K = QKV + QKVSZ, *V = QKV + 2 * QKVSZ;

    // weight transposes (fp16): qkv rows 0..3071 contiguous
    wtrans_kernel<<<dim3(32, 32), 256>>>(wq, WT + 0 * M1, DM, DM);
    wtrans_kernel<<<dim3(32, 32), 256>>>(wk, WT + 1 * M1, DM, DM);
    wtrans_kernel<<<dim3(32, 32), 256>>>(wv, WT + 2 * M1, DM, DM);
    wtrans_kernel<<<dim3(32, 32), 256>>>(wo, WT + 3 * M1, DM, DM);
    wtrans_kernel<<<dim3(128, 32), 256>>>(w1, WT + 4 * M1, DM, DFF);
    wtrans_kernel<<<dim3(32, 128), 256>>>(w2, WT + 8 * M1, DFF, DM);

    bcat_kernel<<<(3 * DM + 255) / 256, 256>>>(bq, bk, bv, B3);
    biastab_kernel<<<(NH * S_LEN + 255) / 256, 256>>>(rb, BT);
    ln_kernel<<<ROWS, 256>>>(hidden, ln1g, ln1b, X);

    // fused QKV projection (N=3072), scatter into [3][B,H,S,DH]
    dim3 gQKV(3 * DM / 128, ROWS / 128);
    hgemm<EPI_QKV3><<<gQKV, 256>>>(X, WT, B3, QKV, 3 * DM, DM, DM, DM, 0, nullptr, nullptr);

    // V transpose per (b,h)
    vtrans_kernel<<<dim3(S_LEN / 32, DH / 32, BATCH * NH), 256>>>(V, VT);

    // fused attention -> merged [B,S,D]
    flash_kernel<<<dim3(BATCH * NH, S_LEN / 128), 256, FL_SMEM>>>(Q, K, VT, BT, mask, MG);

    // O projection + mask + residual
    dim3 gProj(DM / 128, ROWS / 128);
    hgemm<EPI_OPROJ><<<gProj, 256>>>(MG, WT + 3 * M1, bo, H1, DM, DM, DM, DM, DM, hidden, mask);

    ln_kernel<<<ROWS, 256>>>(H1, ln2g, ln2b, X);

    // FFN up + exact GELU
    dim3 gF1(DFF / 128, ROWS / 128);
    hgemm<EPI_GELU><<<gF1, 256>>>(X, WT + 4 * M1, b1, FFb, DFF, DM, DM, DM, DFF, nullptr, nullptr);

    // FFN down + residual + mask
    hgemm<EPI_FINAL><<<gProj, 256>>>(FFb, WT + 8 * M1, b2, out, DM, DFF, DFF, DFF, DM, H1, mask);
}

// round 8
// speedup vs baseline: 5.8705x; 1.1545x over previous
#include <cuda_runtime.h>
#include <cuda_fp16.h>
#include <math.h>
#include <stdint.h>

// ---------------- problem constants ----------------
#define S_LEN 2048
#define NH    16
#define DH    64
#define DM    1024
#define DFF   4096
#define BATCH 2
#define ROWS  (BATCH * S_LEN)   // 4096
#define QKVSZ (BATCH * NH * S_LEN * DH)   // 4M

// ---------------- scratch ----------------
__device__ __half g_Xh [ROWS * DM];
__device__ __half g_QKVh[3 * QKVSZ];
__device__ __half g_VTh[QKVSZ];
__device__ __half g_MGh[ROWS * DM];
__device__ __half g_FFh[ROWS * DFF];
__device__ float  g_H1[ROWS * DM];
__device__ float  g_BT[NH * S_LEN];
__device__ float  g_B3[3 * DM];
__device__ __half g_WTH[12 * 1024 * 1024];  // fp16 transposed weights: qkv @0..3M; o @3M; w1 @4M; w2 @8M

// ---------------- helpers ----------------
__device__ __forceinline__ uint32_t smem_u32(const void* p) {
    uint32_t a;
    asm("{ .reg .u64 t; cvta.to.shared.u64 t, %1; cvt.u32.u64 %0, t; }" : "=r"(a) : "l"(p));
    return a;
}
__device__ __forceinline__ float ex2(float x) {
    float y;
    asm("ex2.approx.ftz.f32 %0, %1;" : "=f"(y) : "f"(x));
    return y;
}
__device__ __forceinline__ void ldsm4(uint32_t* r, uint32_t addr) {
    asm volatile("ldmatrix.sync.aligned.m8n8.x4.shared.b16 {%0,%1,%2,%3}, [%4];"
                 : "=r"(r[0]), "=r"(r[1]), "=r"(r[2]), "=r"(r[3]) : "r"(addr));
}
__device__ __forceinline__ void mma_f16(float* d, const uint32_t* a, uint32_t b0, uint32_t b1) {
    asm volatile(
        "mma.sync.aligned.m16n8k16.row.col.f32.f16.f16.f32 "
        "{%0,%1,%2,%3}, {%4,%5,%6,%7}, {%8,%9}, {%0,%1,%2,%3};"
        : "+f"(d[0]), "+f"(d[1]), "+f"(d[2]), "+f"(d[3])
        : "r"(a[0]), "r"(a[1]), "r"(a[2]), "r"(a[3]), "r"(b0), "r"(b1));
}
__device__ __forceinline__ uint32_t pk2h(float a, float b) {
    __half2 h = __floats2half2_rn(a, b);
    return *reinterpret_cast<uint32_t*>(&h);
}

enum { EPI_QKV3 = 0, EPI_OPROJ = 3, EPI_GELU = 4, EPI_FINAL = 5 };

// ---------------- weight transpose + fp16 convert: W[K,N] -> WT[N,K] (fp16) ----------------
__global__ __launch_bounds__(256) void wtrans_kernel(const float* __restrict__ W,
                                                     __half* __restrict__ WT, int K, int N) {
    __shared__ float t[32][33];
    int n0 = blockIdx.x * 32, k0 = blockIdx.y * 32;
    int tx = threadIdx.x & 31, ty = threadIdx.x >> 5;
#pragma unroll
    for (int j = 0; j < 32; j += 8)
        t[ty + j][tx] = W[(size_t)(k0 + ty + j) * N + n0 + tx];
    __syncthreads();
#pragma unroll
    for (int j = 0; j < 32; j += 8)
        WT[(size_t)(n0 + ty + j) * K + k0 + tx] = __float2half_rn(t[tx][ty + j]);
}

// ---------------- bias concat for fused QKV ----------------
__global__ void bcat_kernel(const float* __restrict__ bq, const float* __restrict__ bk,
                            const float* __restrict__ bv, float* __restrict__ b3) {
    int i = blockIdx.x * 256 + threadIdx.x;
    if (i >= 3 * DM) return;
    const float* s = (i < DM) ? bq : ((i < 2 * DM) ? bk : bv);
    b3[i] = s[i & (DM - 1)];
}

// ---------------- V transpose per (b,h): V[s][d] -> VT[d][s] (fp16) ----------------
__global__ __launch_bounds__(256) void vtrans_kernel(const __half* __restrict__ V,
                                                     __half* __restrict__ VT) {
    __shared__ __half t[32][34];
    int bh = blockIdx.z;
    int s0 = blockIdx.x * 32, d0 = blockIdx.y * 32;
    const __half* src = V + (size_t)bh * S_LEN * DH;
    __half* dst = VT + (size_t)bh * S_LEN * DH;
    int tx = threadIdx.x & 31, ty = threadIdx.x >> 5;
#pragma unroll
    for (int j = 0; j < 32; j += 8)
        t[ty + j][tx] = src[(size_t)(s0 + ty + j) * DH + d0 + tx];
    __syncthreads();
#pragma unroll
    for (int j = 0; j < 32; j += 8)
        dst[(size_t)(d0 + ty + j) * S_LEN + s0 + tx] = t[tx][ty + j];
}

// ---------------- relative-position bias table (prescaled by log2 e) ----------------
__global__ void biastab_kernel(const float* __restrict__ rel_bias,
                               float* __restrict__ tab) {
    int idx = blockIdx.x * blockDim.x + threadIdx.x;
    if (idx >= NH * S_LEN) return;
    int h = idx / S_LEN;
    int d = idx % S_LEN;
    int bucket;
    if (d < 16) {
        bucket = d;
    } else {
        float ratio = logf((float)d * (1.0f / 16.0f)) / logf(8.0f);
        int large = 16 + (int)(ratio * 16.0f);
        bucket = large < 31 ? large : 31;
    }
    tab[h * S_LEN + d] = rel_bias[bucket * NH + h] * 1.44269504088896340736f;
}

// ---------------- layernorm (fp32 in, fp16 out) ----------------
__global__ __launch_bounds__(256) void ln_kernel(const float* __restrict__ x,
                                                 const float* __restrict__ g,
                                                 const float* __restrict__ bta,
                                                 __half* __restrict__ y) {
    int row = blockIdx.x;
    int t = threadIdx.x;
    const float4* xr = (const float4*)(x + (size_t)row * DM);
    float4 v = xr[t];
    float s  = v.x + v.y + v.z + v.w;
    float ss = v.x * v.x + v.y * v.y + v.z * v.z + v.w * v.w;
    __shared__ float sh_s[256], sh_q[256];
    sh_s[t] = s; sh_q[t] = ss;
    __syncthreads();
    for (int o = 128; o > 0; o >>= 1) {
        if (t < o) { sh_s[t] += sh_s[t + o]; sh_q[t] += sh_q[t + o]; }
        __syncthreads();
    }
    float mean = sh_s[0] * (1.0f / DM);
    float var  = sh_q[0] * (1.0f / DM) - mean * mean;
    float rstd = rsqrtf(var + 1e-5f);
    float4 gv = ((const float4*)g)[t];
    float4 bv = ((const float4*)bta)[t];
    __half2* yr = (__half2*)(y + (size_t)row * DM);
    yr[t * 2]     = __floats2half2_rn((v.x - mean) * rstd * gv.x + bv.x,
                                      (v.y - mean) * rstd * gv.y + bv.y);
    yr[t * 2 + 1] = __floats2half2_rn((v.z - mean) * rstd * gv.z + bv.z,
                                      (v.w - mean) * rstd * gv.w + bv.w);
}

// ---------------- fp16 mma.sync GEMM (projections/FFN), fp16 A and B ----------------
// C = A[M,K] * WT^T, WT[N,K]. Tile 128x128, BK=32 double-buffered, 8 warps, m16n8k16.
template <int EPI>
__global__ __launch_bounds__(256, 2) void hgemm(
    const __half* __restrict__ A, const __half* __restrict__ Bm,
    const float* __restrict__ bias, float* __restrict__ Cf, __half* __restrict__ Ch,
    int N, int K, int lda, int ldb, int ldc,
    const float* __restrict__ aux1, const int* __restrict__ auxm) {
    int bn = blockIdx.x * 128;
    int bm = blockIdx.y * 128;

    __shared__ __align__(16) uint32_t As[2][128][20];
    __shared__ __align__(16) uint32_t Bs[2][128][20];

    int tid = threadIdx.x;
    int lane = tid & 31;
    int w = tid >> 5;
    int wm = (w & 1) * 64;
    int wn = (w >> 1) * 32;

    float acc[4][4][4];
#pragma unroll
    for (int mi = 0; mi < 4; mi++)
#pragma unroll
        for (int ni = 0; ni < 4; ni++)
#pragma unroll
            for (int r = 0; r < 4; r++) acc[mi][ni][r] = 0.0f;

    int srow = tid >> 1;
    int shalf = (tid & 1);
    const __half* Ap = A + (size_t)(bm + srow) * lda + shalf * 16;
    const __half* Bp = Bm + (size_t)(bn + srow) * ldb + shalf * 16;

    uint32_t As_u = smem_u32(As);
    uint32_t Bs_u = smem_u32(Bs);
    uint32_t lrow = (uint32_t)((lane & 7) + ((lane >> 3) & 1) * 8);
    uint32_t lk4  = (uint32_t)((lane >> 4) * 4);
    uint32_t a_addr = As_u + ((wm + lrow) * 20 + lk4) * 4;
    uint32_t b_addr = Bs_u + ((wn + lrow) * 20 + lk4) * 4;

    int ntiles = K >> 5;

    uint4 aload0, aload1, bload0, bload1;
    aload0 = *(const uint4*)(Ap);
    aload1 = *(const uint4*)(Ap + 8);
    bload0 = *(const uint4*)(Bp);
    bload1 = *(const uint4*)(Bp + 8);
    {
        uint32_t* da = &As[0][srow][shalf * 8];
        *(uint4*)da = aload0; *(uint4*)(da + 4) = aload1;
        uint32_t* db = &Bs[0][srow][shalf * 8];
        *(uint4*)db = bload0; *(uint4*)(db + 4) = bload1;
    }
    __syncthreads();

    int buf = 0;
    for (int kt = 0; kt < ntiles; kt++) {
        bool more = (kt + 1 < ntiles);
        if (more) {
            int k0 = (kt + 1) * 32;
            aload0 = *(const uint4*)(Ap + k0);
            aload1 = *(const uint4*)(Ap + k0 + 8);
            bload0 = *(const uint4*)(Bp + k0);
            bload1 = *(const uint4*)(Bp + k0 + 8);
        }

        uint32_t abase = a_addr + (uint32_t)(buf * 10240);
        uint32_t bbase = b_addr + (uint32_t)(buf * 10240);
#pragma unroll
        for (int ks = 0; ks < 2; ks++) {
            uint32_t koff = (uint32_t)(ks * 32);
            uint32_t afr[4][4], bfr[2][4];
#pragma unroll
            for (int mi = 0; mi < 4; mi++)
                ldsm4(afr[mi], abase + (uint32_t)(mi * 16 * 80) + koff);
#pragma unroll
            for (int pi = 0; pi < 2; pi++)
                ldsm4(bfr[pi], bbase + (uint32_t)(pi * 16 * 80) + koff);
#pragma unroll
            for (int mi = 0; mi < 4; mi++)
#pragma unroll
                for (int ni = 0; ni < 4; ni++) {
                    int pi = ni >> 1, od = ni & 1;
                    mma_f16(acc[mi][ni], afr[mi], bfr[pi][od], bfr[pi][od + 2]);
                }
        }

        if (more) {
            int nb2 = buf ^ 1;
            uint32_t* da = &As[nb2][srow][shalf * 8];
            *(uint4*)da = aload0; *(uint4*)(da + 4) = aload1;
            uint32_t* db = &Bs[nb2][srow][shalf * 8];
            *(uint4*)db = bload0; *(uint4*)(db + 4) = bload1;
        }
        __syncthreads();
        buf ^= 1;
    }

    // ---- epilogue ----
    int r = lane >> 2, c = lane & 3;
#pragma unroll
    for (int mi = 0; mi < 4; mi++) {
#pragma unroll
        for (int ni = 0; ni < 4; ni++) {
            int r0 = bm + wm + mi * 16 + r;
            int cn = bn + wn + ni * 8 + c * 2;
#pragma unroll
            for (int h2 = 0; h2 < 2; h2++) {
                int gm = r0 + h2 * 8;
#pragma unroll
                for (int j = 0; j < 2; j++) {
                    int gn = cn + j;
                    float v = acc[mi][ni][h2 * 2 + j];
                    if (EPI == EPI_QKV3) {
                        int sel = gn >> 10;
                        int col = gn & (DM - 1);
                        int b = gm >> 11, s = gm & (S_LEN - 1);
                        int h = col >> 6, dh = col & 63;
                        Ch[(size_t)sel * QKVSZ + (((size_t)(b * NH + h) * S_LEN + s) << 6) + dh]
                            = __float2half_rn(v + bias[gn]);
                    } else if (EPI == EPI_OPROJ) {
                        float mk = (float)auxm[gm];
                        Cf[(size_t)gm * ldc + gn] = aux1[(size_t)gm * ldc + gn] + (v + bias[gn]) * mk;
                    } else if (EPI == EPI_GELU) {
                        float u = v + bias[gn];
                        Ch[(size_t)gm * ldc + gn] =
                            __float2half_rn(0.5f * u * (1.0f + erff(u * 0.70710678118654752f)));
                    } else if (EPI == EPI_FINAL) {
                        float mk = (float)auxm[gm];
                        Cf[(size_t)gm * ldc + gn] = (aux1[(size_t)gm * ldc + gn] + v + bias[gn]) * mk;
                    }
                }
            }
        }
    }
}

// ---------------- fused flash attention (fp16 mma) ----------------
// Qs/Ks: [128 rows][36 u32] (64 halves + pad); Vs: [64 rows][68 u32] (128 halves + pad)
#define FL_QS   0
#define FL_KS   18432
#define FL_VS   36864
#define FL_BS   54272
#define FL_MS   55296
#define FL_SMEM 55808

__global__ __launch_bounds__(256, 1) void flash_kernel(
    const __half* __restrict__ Qg, const __half* __restrict__ Kg,
    const __half* __restrict__ VTg, const float* __restrict__ bt2,
    const int* __restrict__ mask, __half* __restrict__ outMG) {
    extern __shared__ char fsm[];
    uint32_t* Qs = (uint32_t*)(fsm + FL_QS);
    uint32_t* Ks = (uint32_t*)(fsm + FL_KS);
    uint32_t* Vs = (uint32_t*)(fsm + FL_VS);
    float* bs = (float*)(fsm + FL_BS);
    float* ms = (float*)(fsm + FL_MS);

    int bh = blockIdx.x;
    int qt = (int)gridDim.y - 1 - blockIdx.y;      // heavy tiles first
    int b = bh >> 4, h = bh & 15;
    int q0 = qt * 128;
    const __half* Qp  = Qg  + (size_t)bh * S_LEN * DH;
    const __half* Kp  = Kg  + (size_t)bh * S_LEN * DH;
    const __half* VTp = VTg + (size_t)bh * S_LEN * DH;
    const float* btr = bt2 + h * S_LEN;
    const int* mr = mask + b * S_LEN;

    int tid = threadIdx.x, lane = tid & 31, w = tid >> 5;
    int wq0 = w * 16;
    int r = lane >> 2, cq = lane & 3;

    // stage Q once: row = tid>>1 (128 rows), half-row 32 halves
    {
        int row = tid >> 1, hf = tid & 1;
        const uint4* src = (const uint4*)(Qp + (size_t)(q0 + row) * DH + hf * 32);
        uint32_t* d = Qs + row * 36 + hf * 16;
        ((uint4*)d)[0] = src[0]; ((uint4*)d)[1] = src[1];
        ((uint4*)d)[2] = src[2]; ((uint4*)d)[3] = src[3];
    }

    uint32_t lrow = (uint32_t)((lane & 7) + ((lane >> 3) & 1) * 8);
    uint32_t lk4  = (uint32_t)((lane >> 4) * 4);
    uint32_t aQ = smem_u32(Qs) + ((wq0 + lrow) * 36 + lk4) * 4;
    uint32_t bK = smem_u32(Ks) + (lrow * 36 + lk4) * 4;
    uint32_t bV = smem_u32(Vs) + (lrow * 68 + lk4) * 4;

    float m0 = -INFINITY, m1 = -INFINITY, l0 = 0.0f, l1 = 0.0f;
    float o[8][4];
#pragma unroll
    for (int ni = 0; ni < 8; ni++)
#pragma unroll
        for (int j = 0; j < 4; j++) o[ni][j] = 0.0f;

    const float cS = 0.125f * 1.44269504088896340736f;

    for (int kt = 0; kt <= qt; kt++) {
        int k0 = kt * 128;
        // ---- stage K tile [s][dh] ----
        {
            int row = tid >> 1, hf = tid & 1;
            const uint4* src = (const uint4*)(Kp + (size_t)(k0 + row) * DH + hf * 32);
            uint32_t* d = Ks + row * 36 + hf * 16;
            ((uint4*)d)[0] = src[0]; ((uint4*)d)[1] = src[1];
            ((uint4*)d)[2] = src[2]; ((uint4*)d)[3] = src[3];
        }
        // ---- stage VT tile [dh][s] ----
        {
            int row = tid >> 2, sg = (tid & 3) * 32;
            const uint4* src = (const uint4*)(VTp + (size_t)row * S_LEN + k0 + sg);
            uint32_t* d = Vs + row * 68 + sg / 2;
            ((uint4*)d)[0] = src[0]; ((uint4*)d)[1] = src[1];
            ((uint4*)d)[2] = src[2]; ((uint4*)d)[3] = src[3];
        }
        // ---- stage bias slice + pad mask ----
        if (tid < 255) {
            int dd = q0 - k0 - 127 + tid;
            bs[tid] = (dd >= 0) ? btr[dd] : 0.0f;
        }
        if (tid < 128) ms[tid] = mr[k0 + tid] ? 0.0f : -INFINITY;
        __syncthreads();

        // ---- S = Q K^T (fp16 mma, 4 k-steps) ----
        float s[16][4];
#pragma unroll
        for (int nt = 0; nt < 16; nt++)
#pragma unroll
            for (int j = 0; j < 4; j++) s[nt][j] = 0.0f;
#pragma unroll
        for (int ks = 0; ks < 4; ks++) {
            uint32_t af[4];
            ldsm4(af, aQ + (uint32_t)(ks * 32));
#pragma unroll
            for (int pi = 0; pi < 8; pi++) {
                uint32_t bf[4];
                ldsm4(bf, bK + (uint32_t)(pi * 16 * 36 * 4) + (uint32_t)(ks * 32));
                mma_f16(s[pi * 2], af, bf[0], bf[2]);
                mma_f16(s[pi * 2 + 1], af, bf[1], bf[3]);
            }
        }

        // ---- logits (log2 domain) + masks + running max ----
        bool diag = (kt == qt);
        float tmax0 = -INFINITY, tmax1 = -INFINITY;
#pragma unroll
        for (int nt = 0; nt < 16; nt++) {
#pragma unroll
            for (int jj = 0; jj < 2; jj++) {
                int kc = nt * 8 + cq * 2 + jj;
                float mk = ms[kc];
                float v0 = s[nt][jj]     * cS + bs[127 + wq0 + r - kc] + mk;
                float v1 = s[nt][jj + 2] * cS + bs[135 + wq0 + r - kc] + mk;
                if (diag && kc > wq0 + r)     v0 = -INFINITY;
                if (diag && kc > wq0 + r + 8) v1 = -INFINITY;
                s[nt][jj] = v0; s[nt][jj + 2] = v1;
                tmax0 = fmaxf(tmax0, v0); tmax1 = fmaxf(tmax1, v1);
            }
        }
        tmax0 = fmaxf(tmax0, __shfl_xor_sync(0xffffffffu, tmax0, 1));
        tmax0 = fmaxf(tmax0, __shfl_xor_sync(0xffffffffu, tmax0, 2));
        tmax1 = fmaxf(tmax1, __shfl_xor_sync(0xffffffffu, tmax1, 1));
        tmax1 = fmaxf(tmax1, __shfl_xor_sync(0xffffffffu, tmax1, 2));
        float mn0 = fmaxf(m0, tmax0), mn1 = fmaxf(m1, tmax1);
        float f0 = (m0 > -1e37f) ? ex2(m0 - mn0) : 0.0f;
        float f1 = (m1 > -1e37f) ? ex2(m1 - mn1) : 0.0f;

        // ---- P = 2^(l2 - m); row sums ----
        float ps0 = 0.0f, ps1 = 0.0f;
#pragma unroll
        for (int nt = 0; nt < 16; nt++) {
#pragma unroll
            for (int jj = 0; jj < 2; jj++) {
                float p0 = (mn0 > -1e37f) ? ex2(s[nt][jj] - mn0)     : 0.0f;
                float p1 = (mn1 > -1e37f) ? ex2(s[nt][jj + 2] - mn1) : 0.0f;
                s[nt][jj] = p0; s[nt][jj + 2] = p1;
                ps0 += p0; ps1 += p1;
            }
        }
        ps0 += __shfl_xor_sync(0xffffffffu, ps0, 1);
        ps0 += __shfl_xor_sync(0xffffffffu, ps0, 2);
        ps1 += __shfl_xor_sync(0xffffffffu, ps1, 1);
        ps1 += __shfl_xor_sync(0xffffffffu, ps1, 2);
        l0 = l0 * f0 + ps0; l1 = l1 * f1 + ps1;
        m0 = mn0; m1 = mn1;

        // ---- rescale O ----
#pragma unroll
        for (int ni = 0; ni < 8; ni++) {
            o[ni][0] *= f0; o[ni][1] *= f0; o[ni][2] *= f1; o[ni][3] *= f1;
        }

        // ---- O += P @ V: C-layout of S == fp16 A-frag layout (no shuffles!) ----
#pragma unroll
        for (int t = 0; t < 8; t++) {
            uint32_t af[4];
            af[0] = pk2h(s[2 * t][0],     s[2 * t][1]);       // row r,   k 16t+2cq,+1
            af[1] = pk2h(s[2 * t][2],     s[2 * t][3]);       // row r+8
            af[2] = pk2h(s[2 * t + 1][0], s[2 * t + 1][1]);   // row r,   k 16t+8+2cq,+1
            af[3] = pk2h(s[2 * t + 1][2], s[2 * t + 1][3]);   // row r+8
#pragma unroll
            for (int pi = 0; pi < 4; pi++) {
                uint32_t bf[4];
                ldsm4(bf, bV + (uint32_t)(pi * 16 * 68 * 4) + (uint32_t)(t * 32));
                mma_f16(o[pi * 2], af, bf[0], bf[2]);
                mma_f16(o[pi * 2 + 1], af, bf[1], bf[3]);
            }
        }
        __syncthreads();
    }

    // ---- finalize: O /= l, write merged [B,S,D] fp16 ----
    float inv0 = (l0 > 0.0f) ? 1.0f / l0 : 0.0f;
    float inv1 = (l1 > 0.0f) ? 1.0f / l1 : 0.0f;
    int qrow = q0 + wq0 + r;
    size_t row0 = ((size_t)b * S_LEN + qrow) * DM + h * 64;
    size_t row1 = row0 + (size_t)8 * DM;
#pragma unroll
    for (int ni = 0; ni < 8; ni++) {
        int dh = ni * 8 + cq * 2;
        *(__half2*)(outMG + row0 + dh) = __floats2half2_rn(o[ni][0] * inv0, o[ni][1] * inv0);
        *(__half2*)(outMG + row1 + dh) = __floats2half2_rn(o[ni][2] * inv1, o[ni][3] * inv1);
    }
}

// ---------------- launch ----------------
extern "C" void kernel_launch(void* const* d_in, const int* in_sizes, int n_in,
                              void* d_out, int out_size) {
    const float* hidden = (const float*)d_in[0];
    const int*   mask   = (const int*)d_in[1];
    const float* wq = (const float*)d_in[2];  const float* bq = (const float*)d_in[3];
    const float* wk = (const float*)d_in[4];  const float* bk = (const float*)d_in[5];
    const float* wv = (const float*)d_in[6];  const float* bv = (const float*)d_in[7];
    const float* wo = (const float*)d_in[8];  const float* bo = (const float*)d_in[9];
    const float* rb = (const float*)d_in[10];
    const float* ln1g = (const float*)d_in[11]; const float* ln1b = (const float*)d_in[12];
    const float* ln2g = (const float*)d_in[13]; const float* ln2b = (const float*)d_in[14];
    const float* w1 = (const float*)d_in[15]; const float* b1 = (const float*)d_in[16];
    const float* w2 = (const float*)d_in[17]; const float* b2 = (const float*)d_in[18];
    float* out = (float*)d_out;

    __half *Xh, *QKVh, *VTh, *MGh, *FFh, *WT;
    float *H1, *BT, *B3;
    cudaGetSymbolAddress((void**)&Xh,   g_Xh);
    cudaGetSymbolAddress((void**)&QKVh, g_QKVh);
    cudaGetSymbolAddress((void**)&VTh,  g_VTh);
    cudaGetSymbolAddress((void**)&MGh,  g_MGh);
    cudaGetSymbolAddress((void**)&FFh,  g_FFh);
    cudaGetSymbolAddress((void**)&H1,   g_H1);
    cudaGetSymbolAddress((void**)&BT,   g_BT);
    cudaGetSymbolAddress((void**)&B3,   g_B3);
    cudaGetSymbolAddress((void**)&WT,   g_WTH);

    cudaFuncSetAttribute(flash_kernel, cudaFuncAttributeMaxDynamicSharedMemorySize, FL_SMEM);

    const size_t M1 = 1024 * 1024;
    __half *Q = QKVh, *K = QKVh + QKVSZ, *V = QKVh + 2 * QKVSZ;

    wtrans_kernel<<<dim3(32, 32), 256>>>(wq, WT + 0 * M1, DM, DM);
    wtrans_kernel<<<dim3(32, 32), 256>>>(wk, WT + 1 * M1, DM, DM);
    wtrans_kernel<<<dim3(32, 32), 256>>>(wv, WT + 2 * M1, DM, DM);
    wtrans_kernel<<<dim3(32, 32), 256>>>(wo, WT + 3 * M1, DM, DM);
    wtrans_kernel<<<dim3(128, 32), 256>>>(w1, WT + 4 * M1, DM, DFF);
    wtrans_kernel<<<dim3(32, 128), 256>>>(w2, WT + 8 * M1, DFF, DM);

    bcat_kernel<<<(3 * DM + 255) / 256, 256>>>(bq, bk, bv, B3);
    biastab_kernel<<<(NH * S_LEN + 255) / 256, 256>>>(rb, BT);
    ln_kernel<<<ROWS, 256>>>(hidden, ln1g, ln1b, Xh);

    // fused QKV projection (N=3072), scatter fp16 into [3][B,H,S,DH]
    dim3 gQKV(3 * DM / 128, ROWS / 128);
    hgemm<EPI_QKV3><<<gQKV, 256>>>(Xh, WT, B3, nullptr, QKVh, 3 * DM, DM, DM, DM, 0,
                                   nullptr, nullptr);

    // V transpose per (b,h)
    vtrans_kernel<<<dim3(S_LEN / 32, DH / 32, BATCH * NH), 256>>>(V, VTh);

    // fused fp16 flash attention -> merged [B,S,D] fp16
    flash_kernel<<<dim3(BATCH * NH, S_LEN / 128), 256, FL_SMEM>>>(Q, K, VTh, BT, mask, MGh);

    // O projection + mask + residual (fp32 out)
    dim3 gProj(DM / 128, ROWS / 128);
    hgemm<EPI_OPROJ><<<gProj, 256>>>(MGh, WT + 3 * M1, bo, H1, nullptr, DM, DM, DM, DM, DM,
                                     hidden, mask);

    ln_kernel<<<ROWS, 256>>>(H1, ln2g, ln2b, Xh);

    // FFN up + exact GELU -> fp16
    dim3 gF1(DFF / 128, ROWS / 128);
    hgemm<EPI_GELU><<<gF1, 256>>>(Xh, WT + 4 * M1, b1, nullptr, FFh, DFF, DM, DM, DM, DFF,
                                  nullptr, nullptr);

    // FFN down + residual + mask -> fp32 out
    hgemm<EPI_FINAL><<<gProj, 256>>>(FFh, WT + 8 * M1, b2, out, nullptr, DM, DFF, DFF, DFF, DM,
                                     H1, mask);
}

// round 9
// speedup vs baseline: 5.9257x; 1.0094x over previous
#include <cuda_runtime.h>
#include <cuda_fp16.h>
#include <math.h>
#include <stdint.h>

// ---------------- problem constants ----------------
#define S_LEN 2048
#define NH    16
#define DH    64
#define DM    1024
#define DFF   4096
#define BATCH 2
#define ROWS  (BATCH * S_LEN)   // 4096
#define QKVSZ (BATCH * NH * S_LEN * DH)   // 4M

// ---------------- scratch ----------------
__device__ __half g_Xh [ROWS * DM];
__device__ __half g_QKVh[3 * QKVSZ];
__device__ __half g_VTh[QKVSZ];
__device__ __half g_MGh[ROWS * DM];
__device__ __half g_FFh[ROWS * DFF];
__device__ float  g_H1[ROWS * DM];
__device__ float  g_BT[NH * S_LEN];
__device__ float  g_B3[3 * DM];
__device__ __half g_WTH[12 * 1024 * 1024];  // fp16 transposed weights

// ---------------- helpers ----------------
__device__ __forceinline__ uint32_t smem_u32(const void* p) {
    uint32_t a;
    asm("{ .reg .u64 t; cvta.to.shared.u64 t, %1; cvt.u32.u64 %0, t; }" : "=r"(a) : "l"(p));
    return a;
}
__device__ __forceinline__ float ex2(float x) {
    float y;
    asm("ex2.approx.ftz.f32 %0, %1;" : "=f"(y) : "f"(x));
    return y;
}
__device__ __forceinline__ void ldsm4(uint32_t* r, uint32_t addr) {
    asm volatile("ldmatrix.sync.aligned.m8n8.x4.shared.b16 {%0,%1,%2,%3}, [%4];"
                 : "=r"(r[0]), "=r"(r[1]), "=r"(r[2]), "=r"(r[3]) : "r"(addr));
}
__device__ __forceinline__ void mma_f16(float* d, const uint32_t* a, uint32_t b0, uint32_t b1) {
    asm volatile(
        "mma.sync.aligned.m16n8k16.row.col.f32.f16.f16.f32 "
        "{%0,%1,%2,%3}, {%4,%5,%6,%7}, {%8,%9}, {%0,%1,%2,%3};"
        : "+f"(d[0]), "+f"(d[1]), "+f"(d[2]), "+f"(d[3])
        : "r"(a[0]), "r"(a[1]), "r"(a[2]), "r"(a[3]), "r"(b0), "r"(b1));
}
__device__ __forceinline__ uint32_t pk2h(float a, float b) {
    __half2 h = __floats2half2_rn(a, b);
    return *reinterpret_cast<uint32_t*>(&h);
}
__device__ __forceinline__ void cpa16(uint32_t dst, const void* src) {
    asm volatile("cp.async.cg.shared.global [%0], [%1], 16;" :: "r"(dst), "l"(src));
}
#define CP_COMMIT() asm volatile("cp.async.commit_group;" ::: "memory")
#define CP_WAIT(n)  asm volatile("cp.async.wait_group %0;" :: "n"(n) : "memory")

enum { EPI_QKV3 = 0, EPI_OPROJ = 3, EPI_GELU = 4, EPI_FINAL = 5 };

// ---------------- weight transpose + fp16 convert ----------------
__global__ __launch_bounds__(256) void wtrans_kernel(const float* __restrict__ W,
                                                     __half* __restrict__ WT, int K, int N) {
    __shared__ float t[32][33];
    int n0 = blockIdx.x * 32, k0 = blockIdx.y * 32;
    int tx = threadIdx.x & 31, ty = threadIdx.x >> 5;
#pragma unroll
    for (int j = 0; j < 32; j += 8)
        t[ty + j][tx] = W[(size_t)(k0 + ty + j) * N + n0 + tx];
    __syncthreads();
#pragma unroll
    for (int j = 0; j < 32; j += 8)
        WT[(size_t)(n0 + ty + j) * K + k0 + tx] = __float2half_rn(t[tx][ty + j]);
}

// ---------------- bias concat ----------------
__global__ void bcat_kernel(const float* __restrict__ bq, const float* __restrict__ bk,
                            const float* __restrict__ bv, float* __restrict__ b3) {
    int i = blockIdx.x * 256 + threadIdx.x;
    if (i >= 3 * DM) return;
    const float* s = (i < DM) ? bq : ((i < 2 * DM) ? bk : bv);
    b3[i] = s[i & (DM - 1)];
}

// ---------------- V transpose per (b,h) ----------------
__global__ __launch_bounds__(256) void vtrans_kernel(const __half* __restrict__ V,
                                                     __half* __restrict__ VT) {
    __shared__ __half t[32][34];
    int bh = blockIdx.z;
    int s0 = blockIdx.x * 32, d0 = blockIdx.y * 32;
    const __half* src = V + (size_t)bh * S_LEN * DH;
    __half* dst = VT + (size_t)bh * S_LEN * DH;
    int tx = threadIdx.x & 31, ty = threadIdx.x >> 5;
#pragma unroll
    for (int j = 0; j < 32; j += 8)
        t[ty + j][tx] = src[(size_t)(s0 + ty + j) * DH + d0 + tx];
    __syncthreads();
#pragma unroll
    for (int j = 0; j < 32; j += 8)
        dst[(size_t)(d0 + ty + j) * S_LEN + s0 + tx] = t[tx][ty + j];
}

// ---------------- relative-position bias table ----------------
__global__ void biastab_kernel(const float* __restrict__ rel_bias,
                               float* __restrict__ tab) {
    int idx = blockIdx.x * blockDim.x + threadIdx.x;
    if (idx >= NH * S_LEN) return;
    int h = idx / S_LEN;
    int d = idx % S_LEN;
    int bucket;
    if (d < 16) {
        bucket = d;
    } else {
        float ratio = logf((float)d * (1.0f / 16.0f)) / logf(8.0f);
        int large = 16 + (int)(ratio * 16.0f);
        bucket = large < 31 ? large : 31;
    }
    tab[h * S_LEN + d] = rel_bias[bucket * NH + h] * 1.44269504088896340736f;
}

// ---------------- layernorm (fp32 in, fp16 out) ----------------
__global__ __launch_bounds__(256) void ln_kernel(const float* __restrict__ x,
                                                 const float* __restrict__ g,
                                                 const float* __restrict__ bta,
                                                 __half* __restrict__ y) {
    int row = blockIdx.x;
    int t = threadIdx.x;
    const float4* xr = (const float4*)(x + (size_t)row * DM);
    float4 v = xr[t];
    float s  = v.x + v.y + v.z + v.w;
    float ss = v.x * v.x + v.y * v.y + v.z * v.z + v.w * v.w;
    __shared__ float sh_s[256], sh_q[256];
    sh_s[t] = s; sh_q[t] = ss;
    __syncthreads();
    for (int o = 128; o > 0; o >>= 1) {
        if (t < o) { sh_s[t] += sh_s[t + o]; sh_q[t] += sh_q[t + o]; }
        __syncthreads();
    }
    float mean = sh_s[0] * (1.0f / DM);
    float var  = sh_q[0] * (1.0f / DM) - mean * mean;
    float rstd = rsqrtf(var + 1e-5f);
    float4 gv = ((const float4*)g)[t];
    float4 bv = ((const float4*)bta)[t];
    __half2* yr = (__half2*)(y + (size_t)row * DM);
    yr[t * 2]     = __floats2half2_rn((v.x - mean) * rstd * gv.x + bv.x,
                                      (v.y - mean) * rstd * gv.y + bv.y);
    yr[t * 2 + 1] = __floats2half2_rn((v.z - mean) * rstd * gv.z + bv.z,
                                      (v.w - mean) * rstd * gv.w + bv.w);
}

// ---------------- fp16 mma.sync GEMM with 3-stage cp.async pipeline ----------------
// C = A[M,K] * WT^T, WT[N,K]. Tile 128x128, BK=32, 3-stage ring, 8 warps, m16n8k16.
#define HG_STAGE_B 20480                         // As (10240) + Bs (10240) per stage
#define HG_SMEM    (3 * HG_STAGE_B)

template <int EPI>
__global__ __launch_bounds__(256, 2) void hgemm(
    const __half* __restrict__ A, const __half* __restrict__ Bm,
    const float* __restrict__ bias, float* __restrict__ Cf, __half* __restrict__ Ch,
    int N, int K, int lda, int ldb, int ldc,
    const float* __restrict__ aux1, const int* __restrict__ auxm) {
    extern __shared__ char hsm[];
    uint32_t base = smem_u32(hsm);
    int bn = blockIdx.x * 128;
    int bm = blockIdx.y * 128;

    int tid = threadIdx.x;
    int lane = tid & 31;
    int w = tid >> 5;
    int wm = (w & 1) * 64;
    int wn = (w >> 1) * 32;

    float acc[4][4][4];
#pragma unroll
    for (int mi = 0; mi < 4; mi++)
#pragma unroll
        for (int ni = 0; ni < 4; ni++)
#pragma unroll
            for (int r = 0; r < 4; r++) acc[mi][ni][r] = 0.0f;

    // staging coords: row = tid>>1, half-row = (tid&1)*16 halves (32B)
    int srow = tid >> 1;
    int shalf = (tid & 1);
    const __half* Ap = A + (size_t)(bm + srow) * lda + shalf * 16;
    const __half* Bp = Bm + (size_t)(bn + srow) * ldb + shalf * 16;
    uint32_t stoff = (uint32_t)((srow * 20 + shalf * 8) * 4);   // byte offset in stage

    // ldmatrix per-thread offsets
    uint32_t lrow = (uint32_t)((lane & 7) + ((lane >> 3) & 1) * 8);
    uint32_t lk4  = (uint32_t)((lane >> 4) * 4);
    uint32_t aoffc = ((wm + lrow) * 20 + lk4) * 4;
    uint32_t boffc = 10240 + ((wn + lrow) * 20 + lk4) * 4;

    int ntiles = K >> 5;

#define HG_STAGE(st, kt) do {                                           \
        uint32_t sb = base + (uint32_t)(st) * HG_STAGE_B;               \
        const __half* a_ = Ap + (kt) * 32;                              \
        const __half* b_ = Bp + (kt) * 32;                              \
        cpa16(sb + stoff, a_);                                          \
        cpa16(sb + stoff + 16, a_ + 8);                                 \
        cpa16(sb + 10240 + stoff, b_);                                  \
        cpa16(sb + 10240 + stoff + 16, b_ + 8);                         \
        CP_COMMIT();                                                    \
    } while (0)

    HG_STAGE(0, 0);
    HG_STAGE(1, 1);

    int cur = 0;
    for (int kt = 0; kt < ntiles; kt++) {
        if (kt + 1 < ntiles) { CP_WAIT(1); } else { CP_WAIT(0); }
        __syncthreads();
        if (kt + 2 < ntiles) {
            int fill = cur + 2; if (fill >= 3) fill -= 3;
            HG_STAGE(fill, kt + 2);
        }

        uint32_t sb = base + (uint32_t)cur * HG_STAGE_B;
        uint32_t abase = sb + aoffc;
        uint32_t bbase = sb + boffc;
#pragma unroll
        for (int ks = 0; ks < 2; ks++) {
            uint32_t koff = (uint32_t)(ks * 32);
            uint32_t afr[4][4], bfr[2][4];
#pragma unroll
            for (int mi = 0; mi < 4; mi++)
                ldsm4(afr[mi], abase + (uint32_t)(mi * 16 * 80) + koff);
#pragma unroll
            for (int pi = 0; pi < 2; pi++)
                ldsm4(bfr[pi], bbase + (uint32_t)(pi * 16 * 80) + koff);
#pragma unroll
            for (int mi = 0; mi < 4; mi++)
#pragma unroll
                for (int ni = 0; ni < 4; ni++) {
                    int pi = ni >> 1, od = ni & 1;
                    mma_f16(acc[mi][ni], afr[mi], bfr[pi][od], bfr[pi][od + 2]);
                }
        }
        cur++; if (cur == 3) cur = 0;
    }

    // ---- epilogue ----
    int r = lane >> 2, c = lane & 3;
#pragma unroll
    for (int mi = 0; mi < 4; mi++) {
#pragma unroll
        for (int ni = 0; ni < 4; ni++) {
            int r0 = bm + wm + mi * 16 + r;
            int cn = bn + wn + ni * 8 + c * 2;
#pragma unroll
            for (int h2 = 0; h2 < 2; h2++) {
                int gm = r0 + h2 * 8;
#pragma unroll
                for (int j = 0; j < 2; j++) {
                    int gn = cn + j;
                    float v = acc[mi][ni][h2 * 2 + j];
                    if (EPI == EPI_QKV3) {
                        int sel = gn >> 10;
                        int col = gn & (DM - 1);
                        int b = gm >> 11, s = gm & (S_LEN - 1);
                        int h = col >> 6, dh = col & 63;
                        Ch[(size_t)sel * QKVSZ + (((size_t)(b * NH + h) * S_LEN + s) << 6) + dh]
                            = __float2half_rn(v + bias[gn]);
                    } else if (EPI == EPI_OPROJ) {
                        float mk = (float)auxm[gm];
                        Cf[(size_t)gm * ldc + gn] = aux1[(size_t)gm * ldc + gn] + (v + bias[gn]) * mk;
                    } else if (EPI == EPI_GELU) {
                        float u = v + bias[gn];
                        Ch[(size_t)gm * ldc + gn] =
                            __float2half_rn(0.5f * u * (1.0f + erff(u * 0.70710678118654752f)));
                    } else if (EPI == EPI_FINAL) {
                        float mk = (float)auxm[gm];
                        Cf[(size_t)gm * ldc + gn] = (aux1[(size_t)gm * ldc + gn] + v + bias[gn]) * mk;
                    }
                }
            }
        }
    }
}

// ---------------- fused flash attention (fp16 mma, double-buffered cp.async K/V) ----------------
// dyn smem layout (bytes):
//   Qs @0            : 128*36*4 = 18432
//   Ks[2] @18432     : 2*18432 = 36864
//   Vs[2] @55296     : 2*17408 = 34816
//   bs @90112        : 1024
//   ms @91136        : 512
#define FL_SMEM 91648

__global__ __launch_bounds__(256, 1) void flash_kernel(
    const __half* __restrict__ Qg, const __half* __restrict__ Kg,
    const __half* __restrict__ VTg, const float* __restrict__ bt2,
    const int* __restrict__ mask, __half* __restrict__ outMG) {
    extern __shared__ char fsm[];
    uint32_t base = smem_u32(fsm);
    uint32_t* Qs = (uint32_t*)(fsm);
    float* bs = (float*)(fsm + 90112);
    float* ms = (float*)(fsm + 91136);

    int bh = blockIdx.x;
    int qt = (int)gridDim.y - 1 - blockIdx.y;      // heavy tiles first
    int b = bh >> 4, h = bh & 15;
    int q0 = qt * 128;
    const __half* Qp  = Qg  + (size_t)bh * S_LEN * DH;
    const __half* Kp  = Kg  + (size_t)bh * S_LEN * DH;
    const __half* VTp = VTg + (size_t)bh * S_LEN * DH;
    const float* btr = bt2 + h * S_LEN;
    const int* mr = mask + b * S_LEN;

    int tid = threadIdx.x, lane = tid & 31, w = tid >> 5;
    int wq0 = w * 16;
    int r = lane >> 2, cq = lane & 3;

    // stage Q once (regular stores; covered by first barrier)
    {
        int row = tid >> 1, hf = tid & 1;
        const uint4* src = (const uint4*)(Qp + (size_t)(q0 + row) * DH + hf * 32);
        uint32_t* d = Qs + row * 36 + hf * 16;
        ((uint4*)d)[0] = src[0]; ((uint4*)d)[1] = src[1];
        ((uint4*)d)[2] = src[2]; ((uint4*)d)[3] = src[3];
    }

    // staging coords
    int krow = tid >> 1, khf = tid & 1;
    uint32_t kdst = (uint32_t)((krow * 36 + khf * 16) * 4);
    int vrow = tid >> 2, vsg = (tid & 3) * 32;
    uint32_t vdst = (uint32_t)((vrow * 68 + vsg / 2) * 4);

#define FL_STAGE(buf, kt) do {                                                   \
        uint32_t kb = base + 18432u + (uint32_t)(buf) * 18432u + kdst;           \
        const __half* ks_ = Kp + (size_t)((kt) * 128 + krow) * DH + khf * 32;    \
        cpa16(kb, ks_);  cpa16(kb + 16, ks_ + 8);                                \
        cpa16(kb + 32, ks_ + 16); cpa16(kb + 48, ks_ + 24);                      \
        uint32_t vb = base + 55296u + (uint32_t)(buf) * 17408u + vdst;           \
        const __half* vs_ = VTp + (size_t)vrow * S_LEN + (kt) * 128 + vsg;       \
        cpa16(vb, vs_);  cpa16(vb + 16, vs_ + 8);                                \
        cpa16(vb + 32, vs_ + 16); cpa16(vb + 48, vs_ + 24);                      \
        CP_COMMIT();                                                             \
    } while (0)

    FL_STAGE(0, 0);

    uint32_t lrow = (uint32_t)((lane & 7) + ((lane >> 3) & 1) * 8);
    uint32_t lk4  = (uint32_t)((lane >> 4) * 4);
    uint32_t aQ = base + ((wq0 + lrow) * 36 + lk4) * 4;
    uint32_t koffK = (lrow * 36 + lk4) * 4;
    uint32_t koffV = (lrow * 68 + lk4) * 4;

    float m0 = -INFINITY, m1 = -INFINITY, l0 = 0.0f, l1 = 0.0f;
    float o[8][4];
#pragma unroll
    for (int ni = 0; ni < 8; ni++)
#pragma unroll
        for (int j = 0; j < 4; j++) o[ni][j] = 0.0f;

    const float cS = 0.125f * 1.44269504088896340736f;

    int buf = 0;
    for (int kt = 0; kt <= qt; kt++) {
        int k0 = kt * 128;
        if (kt + 1 <= qt) FL_STAGE(buf ^ 1, kt + 1);
        // bias slice + pad mask (regular; prev compute done via trailing sync)
        if (tid < 255) {
            int dd = q0 - k0 - 127 + tid;
            bs[tid] = (dd >= 0) ? btr[dd] : 0.0f;
        }
        if (tid < 128) ms[tid] = mr[k0 + tid] ? 0.0f : -INFINITY;
        if (kt + 1 <= qt) { CP_WAIT(1); } else { CP_WAIT(0); }
        __syncthreads();

        uint32_t bK = base + 18432u + (uint32_t)buf * 18432u + koffK;
        uint32_t bV = base + 55296u + (uint32_t)buf * 17408u + koffV;

        // ---- S = Q K^T ----
        float s[16][4];
#pragma unroll
        for (int nt = 0; nt < 16; nt++)
#pragma unroll
            for (int j = 0; j < 4; j++) s[nt][j] = 0.0f;
#pragma unroll
        for (int ks = 0; ks < 4; ks++) {
            uint32_t af[4];
            ldsm4(af, aQ + (uint32_t)(ks * 32));
#pragma unroll
            for (int pi = 0; pi < 8; pi++) {
                uint32_t bf[4];
                ldsm4(bf, bK + (uint32_t)(pi * 16 * 36 * 4) + (uint32_t)(ks * 32));
                mma_f16(s[pi * 2], af, bf[0], bf[2]);
                mma_f16(s[pi * 2 + 1], af, bf[1], bf[3]);
            }
        }

        // ---- logits + masks + running max ----
        bool diag = (kt == qt);
        float tmax0 = -INFINITY, tmax1 = -INFINITY;
#pragma unroll
        for (int nt = 0; nt < 16; nt++) {
#pragma unroll
            for (int jj = 0; jj < 2; jj++) {
                int kc = nt * 8 + cq * 2 + jj;
                float mk = ms[kc];
                float v0 = s[nt][jj]     * cS + bs[127 + wq0 + r - kc] + mk;
                float v1 = s[nt][jj + 2] * cS + bs[135 + wq0 + r - kc] + mk;
                if (diag && kc > wq0 + r)     v0 = -INFINITY;
                if (diag && kc > wq0 + r + 8) v1 = -INFINITY;
                s[nt][jj] = v0; s[nt][jj + 2] = v1;
                tmax0 = fmaxf(tmax0, v0); tmax1 = fmaxf(tmax1, v1);
            }
        }
        tmax0 = fmaxf(tmax0, __shfl_xor_sync(0xffffffffu, tmax0, 1));
        tmax0 = fmaxf(tmax0, __shfl_xor_sync(0xffffffffu, tmax0, 2));
        tmax1 = fmaxf(tmax1, __shfl_xor_sync(0xffffffffu, tmax1, 1));
        tmax1 = fmaxf(tmax1, __shfl_xor_sync(0xffffffffu, tmax1, 2));
        float mn0 = fmaxf(m0, tmax0), mn1 = fmaxf(m1, tmax1);
        float f0 = (m0 > -1e37f) ? ex2(m0 - mn0) : 0.0f;
        float f1 = (m1 > -1e37f) ? ex2(m1 - mn1) : 0.0f;

        // ---- P + row sums ----
        float ps0 = 0.0f, ps1 = 0.0f;
#pragma unroll
        for (int nt = 0; nt < 16; nt++) {
#pragma unroll
            for (int jj = 0; jj < 2; jj++) {
                float p0 = (mn0 > -1e37f) ? ex2(s[nt][jj] - mn0)     : 0.0f;
                float p1 = (mn1 > -1e37f) ? ex2(s[nt][jj + 2] - mn1) : 0.0f;
                s[nt][jj] = p0; s[nt][jj + 2] = p1;
                ps0 += p0; ps1 += p1;
            }
        }
        ps0 += __shfl_xor_sync(0xffffffffu, ps0, 1);
        ps0 += __shfl_xor_sync(0xffffffffu, ps0, 2);
        ps1 += __shfl_xor_sync(0xffffffffu, ps1, 1);
        ps1 += __shfl_xor_sync(0xffffffffu, ps1, 2);
        l0 = l0 * f0 + ps0; l1 = l1 * f1 + ps1;
        m0 = mn0; m1 = mn1;

        // ---- rescale O ----
#pragma unroll
        for (int ni = 0; ni < 8; ni++) {
            o[ni][0] *= f0; o[ni][1] *= f0; o[ni][2] *= f1; o[ni][3] *= f1;
        }

        // ---- O += P @ V (S C-layout == fp16 A-frag layout) ----
#pragma unroll
        for (int t = 0; t < 8; t++) {
            uint32_t af[4];
            af[0] = pk2h(s[2 * t][0],     s[2 * t][1]);
            af[1] = pk2h(s[2 * t][2],     s[2 * t][3]);
            af[2] = pk2h(s[2 * t + 1][0], s[2 * t + 1][1]);
            af[3] = pk2h(s[2 * t + 1][2], s[2 * t + 1][3]);
#pragma unroll
            for (int pi = 0; pi < 4; pi++) {
                uint32_t bf[4];
                ldsm4(bf, bV + (uint32_t)(pi * 16 * 68 * 4) + (uint32_t)(t * 32));
                mma_f16(o[pi * 2], af, bf[0], bf[2]);
                mma_f16(o[pi * 2 + 1], af, bf[1], bf[3]);
            }
        }
        __syncthreads();
        buf ^= 1;
    }

    // ---- finalize ----
    float inv0 = (l0 > 0.0f) ? 1.0f / l0 : 0.0f;
    float inv1 = (l1 > 0.0f) ? 1.0f / l1 : 0.0f;
    int qrow = q0 + wq0 + r;
    size_t row0 = ((size_t)b * S_LEN + qrow) * DM + h * 64;
    size_t row1 = row0 + (size_t)8 * DM;
#pragma unroll
    for (int ni = 0; ni < 8; ni++) {
        int dh = ni * 8 + cq * 2;
        *(__half2*)(outMG + row0 + dh) = __floats2half2_rn(o[ni][0] * inv0, o[ni][1] * inv0);
        *(__half2*)(outMG + row1 + dh) = __floats2half2_rn(o[ni][2] * inv1, o[ni][3] * inv1);
    }
}

// ---------------- launch ----------------
extern "C" void kernel_launch(void* const* d_in, const int* in_sizes, int n_in,
                              void* d_out, int out_size) {
    const float* hidden = (const float*)d_in[0];
    const int*   mask   = (const int*)d_in[1];
    const float* wq = (const float*)d_in[2];  const float* bq = (const float*)d_in[3];
    const float* wk = (const float*)d_in[4];  const float* bk = (const float*)d_in[5];
    const float* wv = (const float*)d_in[6];  const float* bv = (const float*)d_in[7];
    const float* wo = (const float*)d_in[8];  const float* bo = (const float*)d_in[9];
    const float* rb = (const float*)d_in[10];
    const float* ln1g = (const float*)d_in[11]; const float* ln1b = (const float*)d_in[12];
    const float* ln2g = (const float*)d_in[13]; const float* ln2b = (const float*)d_in[14];
    const float* w1 = (const float*)d_in[15]; const float* b1 = (const float*)d_in[16];
    const float* w2 = (const float*)d_in[17]; const float* b2 = (const float*)d_in[18];
    float* out = (float*)d_out;

    __half *Xh, *QKVh, *VTh, *MGh, *FFh, *WT;
    float *H1, *BT, *B3;
    cudaGetSymbolAddress((void**)&Xh,   g_Xh);
    cudaGetSymbolAddress((void**)&QKVh, g_QKVh);
    cudaGetSymbolAddress((void**)&VTh,  g_VTh);
    cudaGetSymbolAddress((void**)&MGh,  g_MGh);
    cudaGetSymbolAddress((void**)&FFh,  g_FFh);
    cudaGetSymbolAddress((void**)&H1,   g_H1);
    cudaGetSymbolAddress((void**)&BT,   g_BT);
    cudaGetSymbolAddress((void**)&B3,   g_B3);
    cudaGetSymbolAddress((void**)&WT,   g_WTH);

    cudaFuncSetAttribute(flash_kernel, cudaFuncAttributeMaxDynamicSharedMemorySize, FL_SMEM);
    cudaFuncSetAttribute(hgemm<EPI_QKV3>,  cudaFuncAttributeMaxDynamicSharedMemorySize, HG_SMEM);
    cudaFuncSetAttribute(hgemm<EPI_OPROJ>, cudaFuncAttributeMaxDynamicSharedMemorySize, HG_SMEM);
    cudaFuncSetAttribute(hgemm<EPI_GELU>,  cudaFuncAttributeMaxDynamicSharedMemorySize, HG_SMEM);
    cudaFuncSetAttribute(hgemm<EPI_FINAL>, cudaFuncAttributeMaxDynamicSharedMemorySize, HG_SMEM);

    const size_t M1 = 1024 * 1024;
    __half *Q = QKVh, *K = QKVh + QKVSZ, *V = QKVh + 2 * QKVSZ;

    wtrans_kernel<<<dim3(32, 32), 256>>>(wq, WT + 0 * M1, DM, DM);
    wtrans_kernel<<<dim3(32, 32), 256>>>(wk, WT + 1 * M1, DM, DM);
    wtrans_kernel<<<dim3(32, 32), 256>>>(wv, WT + 2 * M1, DM, DM);
    wtrans_kernel<<<dim3(32, 32), 256>>>(wo, WT + 3 * M1, DM, DM);
    wtrans_kernel<<<dim3(128, 32), 256>>>(w1, WT + 4 * M1, DM, DFF);
    wtrans_kernel<<<dim3(32, 128), 256>>>(w2, WT + 8 * M1, DFF, DM);

    bcat_kernel<<<(3 * DM + 255) / 256, 256>>>(bq, bk, bv, B3);
    biastab_kernel<<<(NH * S_LEN + 255) / 256, 256>>>(rb, BT);
    ln_kernel<<<ROWS, 256>>>(hidden, ln1g, ln1b, Xh);

    // fused QKV projection (N=3072)
    dim3 gQKV(3 * DM / 128, ROWS / 128);
    hgemm<EPI_QKV3><<<gQKV, 256, HG_SMEM>>>(Xh, WT, B3, nullptr, QKVh, 3 * DM, DM, DM, DM, 0,
                                            nullptr, nullptr);

    // V transpose per (b,h)
    vtrans_kernel<<<dim3(S_LEN / 32, DH / 32, BATCH * NH), 256>>>(V, VTh);

    // fused fp16 flash attention -> merged [B,S,D] fp16
    flash_kernel<<<dim3(BATCH * NH, S_LEN / 128), 256, FL_SMEM>>>(Q, K, VTh, BT, mask, MGh);

    // O projection + mask + residual (fp32 out)
    dim3 gProj(DM / 128, ROWS / 128);
    hgemm<EPI_OPROJ><<<gProj, 256, HG_SMEM>>>(MGh, WT + 3 * M1, bo, H1, nullptr, DM, DM, DM, DM, DM,
                                              hidden, mask);

    ln_kernel<<<ROWS, 256>>>(H1, ln2g, ln2b, Xh);

    // FFN up + exact GELU -> fp16
    dim3 gF1(DFF / 128, ROWS / 128);
    hgemm<EPI_GELU><<<gF1, 256, HG_SMEM>>>(Xh, WT + 4 * M1, b1, nullptr, FFh, DFF, DM, DM, DM, DFF,
                                           nullptr, nullptr);

    // FFN down + residual + mask -> fp32 out
    hgemm<EPI_FINAL><<<gProj, 256, HG_SMEM>>>(FFh, WT + 8 * M1, b2, out, nullptr, DM, DFF, DFF, DFF, DM,
                                              H1, mask);
}

// round 10
// speedup vs baseline: 6.0858x; 1.0270x over previous
#include <cuda_runtime.h>
#include <cuda_fp16.h>
#include <math.h>
#include <stdint.h>

// ---------------- problem constants ----------------
#define S_LEN 2048
#define NH    16
#define DH    64
#define DM    1024
#define DFF   4096
#define BATCH 2
#define ROWS  (BATCH * S_LEN)   // 4096
#define QKVSZ (BATCH * NH * S_LEN * DH)   // 4M

// ---------------- scratch ----------------
__device__ __half g_Xh [ROWS * DM];
__device__ __half g_QKVh[3 * QKVSZ];
__device__ __half g_MGh[ROWS * DM];
__device__ __half g_FFh[ROWS * DFF];
__device__ float  g_H1[ROWS * DM];
__device__ float  g_BT[NH * S_LEN];
__device__ float  g_B3[3 * DM];
__device__ __half g_WTH[12 * 1024 * 1024];  // fp16 transposed weights

// ---------------- helpers ----------------
__device__ __forceinline__ uint32_t smem_u32(const void* p) {
    uint32_t a;
    asm("{ .reg .u64 t; cvta.to.shared.u64 t, %1; cvt.u32.u64 %0, t; }" : "=r"(a) : "l"(p));
    return a;
}
__device__ __forceinline__ float ex2(float x) {
    float y;
    asm("ex2.approx.ftz.f32 %0, %1;" : "=f"(y) : "f"(x));
    return y;
}
__device__ __forceinline__ uint32_t ex2h2(uint32_t x) {
    uint32_t y;
    asm("ex2.approx.f16x2 %0, %1;" : "=r"(y) : "r"(x));
    return y;
}
__device__ __forceinline__ void ldsm4(uint32_t* r, uint32_t addr) {
    asm volatile("ldmatrix.sync.aligned.m8n8.x4.shared.b16 {%0,%1,%2,%3}, [%4];"
                 : "=r"(r[0]), "=r"(r[1]), "=r"(r[2]), "=r"(r[3]) : "r"(addr));
}
__device__ __forceinline__ void ldsm4t(uint32_t* r, uint32_t addr) {
    asm volatile("ldmatrix.sync.aligned.m8n8.x4.trans.shared.b16 {%0,%1,%2,%3}, [%4];"
                 : "=r"(r[0]), "=r"(r[1]), "=r"(r[2]), "=r"(r[3]) : "r"(addr));
}
__device__ __forceinline__ void mma_f16(float* d, const uint32_t* a, uint32_t b0, uint32_t b1) {
    asm volatile(
        "mma.sync.aligned.m16n8k16.row.col.f32.f16.f16.f32 "
        "{%0,%1,%2,%3}, {%4,%5,%6,%7}, {%8,%9}, {%0,%1,%2,%3};"
        : "+f"(d[0]), "+f"(d[1]), "+f"(d[2]), "+f"(d[3])
        : "r"(a[0]), "r"(a[1]), "r"(a[2]), "r"(a[3]), "r"(b0), "r"(b1));
}
__device__ __forceinline__ uint32_t pk2h(float a, float b) {
    __half2 h = __floats2half2_rn(a, b);
    return *reinterpret_cast<uint32_t*>(&h);
}
__device__ __forceinline__ void cpa16(uint32_t dst, const void* src) {
    asm volatile("cp.async.cg.shared.global [%0], [%1], 16;" :: "r"(dst), "l"(src));
}
#define CP_COMMIT() asm volatile("cp.async.commit_group;" ::: "memory")
#define CP_WAIT(n)  asm volatile("cp.async.wait_group %0;" :: "n"(n) : "memory")

enum { EPI_QKV3 = 0, EPI_OPROJ = 3, EPI_GELU = 4, EPI_FINAL = 5 };

// ---------------- all weight transposes in one kernel ----------------
// tiles: [0,1024) wq, [1024,2048) wk, [2048,3072) wv, [3072,4096) wo,
//        [4096,8192) w1 (K=1024,N=4096), [8192,12288) w2 (K=4096,N=1024)
__global__ __launch_bounds__(256) void wtrans_all(
    const float* __restrict__ wq, const float* __restrict__ wk,
    const float* __restrict__ wv, const float* __restrict__ wo,
    const float* __restrict__ w1, const float* __restrict__ w2,
    __half* __restrict__ WT) {
    __shared__ float t[32][33];
    const size_t M1 = 1024 * 1024;
    int tile = blockIdx.x;
    const float* W;
    __half* D;
    int K, N, lt;
    if (tile < 4096) {
        int seg = tile >> 10;
        lt = tile & 1023;
        W = (seg == 0) ? wq : (seg == 1) ? wk : (seg == 2) ? wv : wo;
        D = WT + (size_t)seg * M1;
        K = DM; N = DM;
    } else if (tile < 8192) {
        lt = tile - 4096;
        W = w1; D = WT + 4 * M1; K = DM; N = DFF;
    } else {
        lt = tile - 8192;
        W = w2; D = WT + 8 * M1; K = DFF; N = DM;
    }
    int ntile = N >> 5;
    int n0 = (lt % ntile) * 32, k0 = (lt / ntile) * 32;
    int tx = threadIdx.x & 31, ty = threadIdx.x >> 5;
#pragma unroll
    for (int j = 0; j < 32; j += 8)
        t[ty + j][tx] = W[(size_t)(k0 + ty + j) * N + n0 + tx];
    __syncthreads();
#pragma unroll
    for (int j = 0; j < 32; j += 8)
        D[(size_t)(n0 + ty + j) * K + k0 + tx] = __float2half_rn(t[tx][ty + j]);
}

// ---------------- prep: bias table + bias concat ----------------
__global__ void prep_kernel(const float* __restrict__ rel_bias, float* __restrict__ tab,
                            const float* __restrict__ bq, const float* __restrict__ bk,
                            const float* __restrict__ bv, float* __restrict__ b3) {
    int idx = blockIdx.x * 256 + threadIdx.x;
    if (idx < NH * S_LEN) {
        int h = idx / S_LEN;
        int d = idx % S_LEN;
        int bucket;
        if (d < 16) {
            bucket = d;
        } else {
            float ratio = logf((float)d * (1.0f / 16.0f)) / logf(8.0f);
            int large = 16 + (int)(ratio * 16.0f);
            bucket = large < 31 ? large : 31;
        }
        tab[h * S_LEN + d] = rel_bias[bucket * NH + h] * 1.44269504088896340736f;
    } else {
        int i = idx - NH * S_LEN;
        if (i < 3 * DM) {
            const float* s = (i < DM) ? bq : ((i < 2 * DM) ? bk : bv);
            b3[i] = s[i & (DM - 1)];
        }
    }
}

// ---------------- layernorm (fp32 in, fp16 out) ----------------
__global__ __launch_bounds__(256) void ln_kernel(const float* __restrict__ x,
                                                 const float* __restrict__ g,
                                                 const float* __restrict__ bta,
                                                 __half* __restrict__ y) {
    int row = blockIdx.x;
    int t = threadIdx.x;
    const float4* xr = (const float4*)(x + (size_t)row * DM);
    float4 v = xr[t];
    float s  = v.x + v.y + v.z + v.w;
    float ss = v.x * v.x + v.y * v.y + v.z * v.z + v.w * v.w;
    __shared__ float sh_s[256], sh_q[256];
    sh_s[t] = s; sh_q[t] = ss;
    __syncthreads();
    for (int o = 128; o > 0; o >>= 1) {
        if (t < o) { sh_s[t] += sh_s[t + o]; sh_q[t] += sh_q[t + o]; }
        __syncthreads();
    }
    float mean = sh_s[0] * (1.0f / DM);
    float var  = sh_q[0] * (1.0f / DM) - mean * mean;
    float rstd = rsqrtf(var + 1e-5f);
    float4 gv = ((const float4*)g)[t];
    float4 bv = ((const float4*)bta)[t];
    __half2* yr = (__half2*)(y + (size_t)row * DM);
    yr[t * 2]     = __floats2half2_rn((v.x - mean) * rstd * gv.x + bv.x,
                                      (v.y - mean) * rstd * gv.y + bv.y);
    yr[t * 2 + 1] = __floats2half2_rn((v.z - mean) * rstd * gv.z + bv.z,
                                      (v.w - mean) * rstd * gv.w + bv.w);
}

// ---------------- fp16 mma.sync GEMM with 3-stage cp.async pipeline ----------------
#define HG_STAGE_B 20480
#define HG_SMEM    (3 * HG_STAGE_B)

template <int EPI>
__global__ __launch_bounds__(256, 2) void hgemm(
    const __half* __restrict__ A, const __half* __restrict__ Bm,
    const float* __restrict__ bias, float* __restrict__ Cf, __half* __restrict__ Ch,
    int N, int K, int lda, int ldb, int ldc,
    const float* __restrict__ aux1, const int* __restrict__ auxm) {
    extern __shared__ char hsm[];
    uint32_t base = smem_u32(hsm);
    int bn = blockIdx.x * 128;
    int bm = blockIdx.y * 128;

    int tid = threadIdx.x;
    int lane = tid & 31;
    int w = tid >> 5;
    int wm = (w & 1) * 64;
    int wn = (w >> 1) * 32;

    float acc[4][4][4];
#pragma unroll
    for (int mi = 0; mi < 4; mi++)
#pragma unroll
        for (int ni = 0; ni < 4; ni++)
#pragma unroll
            for (int r = 0; r < 4; r++) acc[mi][ni][r] = 0.0f;

    int srow = tid >> 1;
    int shalf = (tid & 1);
    const __half* Ap = A + (size_t)(bm + srow) * lda + shalf * 16;
    const __half* Bp = Bm + (size_t)(bn + srow) * ldb + shalf * 16;
    uint32_t stoff = (uint32_t)((srow * 20 + shalf * 8) * 4);

    uint32_t lrow = (uint32_t)((lane & 7) + ((lane >> 3) & 1) * 8);
    uint32_t lk4  = (uint32_t)((lane >> 4) * 4);
    uint32_t aoffc = ((wm + lrow) * 20 + lk4) * 4;
    uint32_t boffc = 10240 + ((wn + lrow) * 20 + lk4) * 4;

    int ntiles = K >> 5;

#define HG_STAGE(st, kt) do {                                           \
        uint32_t sb = base + (uint32_t)(st) * HG_STAGE_B;               \
        const __half* a_ = Ap + (kt) * 32;                              \
        const __half* b_ = Bp + (kt) * 32;                              \
        cpa16(sb + stoff, a_);                                          \
        cpa16(sb + stoff + 16, a_ + 8);                                 \
        cpa16(sb + 10240 + stoff, b_);                                  \
        cpa16(sb + 10240 + stoff + 16, b_ + 8);                         \
        CP_COMMIT();                                                    \
    } while (0)

    HG_STAGE(0, 0);
    HG_STAGE(1, 1);

    int cur = 0;
    for (int kt = 0; kt < ntiles; kt++) {
        if (kt + 1 < ntiles) { CP_WAIT(1); } else { CP_WAIT(0); }
        __syncthreads();
        if (kt + 2 < ntiles) {
            int fill = cur + 2; if (fill >= 3) fill -= 3;
            HG_STAGE(fill, kt + 2);
        }

        uint32_t sb = base + (uint32_t)cur * HG_STAGE_B;
        uint32_t abase = sb + aoffc;
        uint32_t bbase = sb + boffc;
#pragma unroll
        for (int ks = 0; ks < 2; ks++) {
            uint32_t koff = (uint32_t)(ks * 32);
            uint32_t afr[4][4], bfr[2][4];
#pragma unroll
            for (int mi = 0; mi < 4; mi++)
                ldsm4(afr[mi], abase + (uint32_t)(mi * 16 * 80) + koff);
#pragma unroll
            for (int pi = 0; pi < 2; pi++)
                ldsm4(bfr[pi], bbase + (uint32_t)(pi * 16 * 80) + koff);
#pragma unroll
            for (int mi = 0; mi < 4; mi++)
#pragma unroll
                for (int ni = 0; ni < 4; ni++) {
                    int pi = ni >> 1, od = ni & 1;
                    mma_f16(acc[mi][ni], afr[mi], bfr[pi][od], bfr[pi][od + 2]);
                }
        }
        cur++; if (cur == 3) cur = 0;
    }

    // ---- epilogue ----
    int r = lane >> 2, c = lane & 3;
#pragma unroll
    for (int mi = 0; mi < 4; mi++) {
#pragma unroll
        for (int ni = 0; ni < 4; ni++) {
            int r0 = bm + wm + mi * 16 + r;
            int cn = bn + wn + ni * 8 + c * 2;
#pragma unroll
            for (int h2 = 0; h2 < 2; h2++) {
                int gm = r0 + h2 * 8;
#pragma unroll
                for (int j = 0; j < 2; j++) {
                    int gn = cn + j;
                    float v = acc[mi][ni][h2 * 2 + j];
                    if (EPI == EPI_QKV3) {
                        int sel = gn >> 10;
                        int col = gn & (DM - 1);
                        int b = gm >> 11, s = gm & (S_LEN - 1);
                        int h = col >> 6, dh = col & 63;
                        Ch[(size_t)sel * QKVSZ + (((size_t)(b * NH + h) * S_LEN + s) << 6) + dh]
                            = __float2half_rn(v + bias[gn]);
                    } else if (EPI == EPI_OPROJ) {
                        float mk = (float)auxm[gm];
                        Cf[(size_t)gm * ldc + gn] = aux1[(size_t)gm * ldc + gn] + (v + bias[gn]) * mk;
                    } else if (EPI == EPI_GELU) {
                        float u = v + bias[gn];
                        Ch[(size_t)gm * ldc + gn] =
                            __float2half_rn(0.5f * u * (1.0f + erff(u * 0.70710678118654752f)));
                    } else if (EPI == EPI_FINAL) {
                        float mk = (float)auxm[gm];
                        Cf[(size_t)gm * ldc + gn] = (aux1[(size_t)gm * ldc + gn] + v + bias[gn]) * mk;
                    }
                }
            }
        }
    }
}

// ---------------- fused flash attention (fp16 mma, f16x2 exp, ones-column l) ----------------
// smem bytes: Qs @0 (18432) | Ks[2] @18432 (2x18432) | Vs[2] @55296 (2x18432)
//             bs @92160 (1024) | ms @93184 (512)
#define FL_SMEM 93696

__global__ __launch_bounds__(256, 1) void flash_kernel(
    const __half* __restrict__ Qg, const __half* __restrict__ Kg,
    const __half* __restrict__ Vg, const float* __restrict__ bt2,
    const int* __restrict__ mask, __half* __restrict__ outMG) {
    extern __shared__ char fsm[];
    uint32_t base = smem_u32(fsm);
    uint32_t* Qs = (uint32_t*)(fsm);
    float* bs = (float*)(fsm + 92160);
    float* ms = (float*)(fsm + 93184);

    int bh = blockIdx.x;
    int qt = (int)gridDim.y - 1 - blockIdx.y;      // heavy tiles first
    int b = bh >> 4, h = bh & 15;
    int q0 = qt * 128;
    const __half* Qp = Qg + (size_t)bh * S_LEN * DH;
    const __half* Kp = Kg + (size_t)bh * S_LEN * DH;
    const __half* Vp = Vg + (size_t)bh * S_LEN * DH;
    const float* btr = bt2 + h * S_LEN;
    const int* mr = mask + b * S_LEN;

    int tid = threadIdx.x, lane = tid & 31, w = tid >> 5;
    int wq0 = w * 16;
    int r = lane >> 2, cq = lane & 3;

    // stage Q once
    {
        int row = tid >> 1, hf = tid & 1;
        const uint4* src = (const uint4*)(Qp + (size_t)(q0 + row) * DH + hf * 32);
        uint32_t* d = Qs + row * 36 + hf * 16;
        ((uint4*)d)[0] = src[0]; ((uint4*)d)[1] = src[1];
        ((uint4*)d)[2] = src[2]; ((uint4*)d)[3] = src[3];
    }

    // staging coords (K and V identical shape: 128 rows x 64 halves, stride 36 u32)
    int krow = tid >> 1, khf = tid & 1;
    uint32_t sdst = (uint32_t)((krow * 36 + khf * 16) * 4);

#define FL_STAGE(buf, kt) do {                                                   \
        uint32_t kb = base + 18432u + (uint32_t)(buf) * 18432u + sdst;           \
        const __half* ks_ = Kp + (size_t)((kt) * 128 + krow) * DH + khf * 32;    \
        cpa16(kb, ks_);  cpa16(kb + 16, ks_ + 8);                                \
        cpa16(kb + 32, ks_ + 16); cpa16(kb + 48, ks_ + 24);                      \
        uint32_t vb = base + 55296u + (uint32_t)(buf) * 18432u + sdst;           \
        const __half* vs_ = Vp + (size_t)((kt) * 128 + krow) * DH + khf * 32;    \
        cpa16(vb, vs_);  cpa16(vb + 16, vs_ + 8);                                \
        cpa16(vb + 32, vs_ + 16); cpa16(vb + 48, vs_ + 24);                      \
        CP_COMMIT();                                                             \
    } while (0)

    FL_STAGE(0, 0);

    uint32_t lrow = (uint32_t)((lane & 7) + ((lane >> 3) & 1) * 8);
    uint32_t lk4  = (uint32_t)((lane >> 4) * 4);
    uint32_t aQ = base + ((wq0 + lrow) * 36 + lk4) * 4;
    uint32_t koffK = (lrow * 36 + lk4) * 4;
    // trans-ldmatrix V offset: rows = s (within 16-group), col pairs of 8 dh
    uint32_t voff = (uint32_t)(((lane & 7) + ((lane >> 3) & 1) * 8) * 144 +
                               ((lane >> 4) & 1) * 16);

    float m0 = -INFINITY, m1 = -INFINITY;
    float o[8][4], lac[4];
#pragma unroll
    for (int ni = 0; ni < 8; ni++)
#pragma unroll
        for (int j = 0; j < 4; j++) o[ni][j] = 0.0f;
#pragma unroll
    for (int j = 0; j < 4; j++) lac[j] = 0.0f;

    const float cS = 0.125f * 1.44269504088896340736f;
    const uint32_t ONES2 = 0x3C003C00u;

    int buf = 0;
    for (int kt = 0; kt <= qt; kt++) {
        int k0 = kt * 128;
        if (kt + 1 <= qt) FL_STAGE(buf ^ 1, kt + 1);
        if (tid < 255) {
            int dd = q0 - k0 - 127 + tid;
            bs[tid] = (dd >= 0) ? btr[dd] : 0.0f;
        }
        if (tid < 128) ms[tid] = mr[k0 + tid] ? 0.0f : -INFINITY;
        if (kt + 1 <= qt) { CP_WAIT(1); } else { CP_WAIT(0); }
        __syncthreads();

        uint32_t bK = base + 18432u + (uint32_t)buf * 18432u + koffK;
        uint32_t bV = base + 55296u + (uint32_t)buf * 18432u + voff;

        // ---- S = Q K^T ----
        float s[16][4];
#pragma unroll
        for (int nt = 0; nt < 16; nt++)
#pragma unroll
            for (int j = 0; j < 4; j++) s[nt][j] = 0.0f;
#pragma unroll
        for (int ks = 0; ks < 4; ks++) {
            uint32_t af[4];
            ldsm4(af, aQ + (uint32_t)(ks * 32));
#pragma unroll
            for (int pi = 0; pi < 8; pi++) {
                uint32_t bf[4];
                ldsm4(bf, bK + (uint32_t)(pi * 16 * 36 * 4) + (uint32_t)(ks * 32));
                mma_f16(s[pi * 2], af, bf[0], bf[2]);
                mma_f16(s[pi * 2 + 1], af, bf[1], bf[3]);
            }
        }

        // ---- logits + masks + running max ----
        bool diag = (kt == qt);
        float tmax0 = -INFINITY, tmax1 = -INFINITY;
#pragma unroll
        for (int nt = 0; nt < 16; nt++) {
#pragma unroll
            for (int jj = 0; jj < 2; jj++) {
                int kc = nt * 8 + cq * 2 + jj;
                float mk = ms[kc];
                float v0 = s[nt][jj]     * cS + bs[127 + wq0 + r - kc] + mk;
                float v1 = s[nt][jj + 2] * cS + bs[135 + wq0 + r - kc] + mk;
                if (diag && kc > wq0 + r)     v0 = -INFINITY;
                if (diag && kc > wq0 + r + 8) v1 = -INFINITY;
                s[nt][jj] = v0; s[nt][jj + 2] = v1;
                tmax0 = fmaxf(tmax0, v0); tmax1 = fmaxf(tmax1, v1);
            }
        }
        tmax0 = fmaxf(tmax0, __shfl_xor_sync(0xffffffffu, tmax0, 1));
        tmax0 = fmaxf(tmax0, __shfl_xor_sync(0xffffffffu, tmax0, 2));
        tmax1 = fmaxf(tmax1, __shfl_xor_sync(0xffffffffu, tmax1, 1));
        tmax1 = fmaxf(tmax1, __shfl_xor_sync(0xffffffffu, tmax1, 2));
        float mn0 = fmaxf(m0, tmax0), mn1 = fmaxf(m1, tmax1);
        float mnc0 = fmaxf(mn0, -1e30f), mnc1 = fmaxf(mn1, -1e30f);
        float f0 = ex2(fmaxf(m0, -1e30f) - mnc0);
        float f1 = ex2(fmaxf(m1, -1e30f) - mnc1);
        m0 = mn0; m1 = mn1;

        // ---- P = 2^(s-m) packed to half2 directly (A-frag layout) ----
        uint32_t P32[32];
#pragma unroll
        for (int nt = 0; nt < 16; nt++) {
            P32[2 * nt]     = ex2h2(pk2h(s[nt][0] - mnc0, s[nt][1] - mnc0));
            P32[2 * nt + 1] = ex2h2(pk2h(s[nt][2] - mnc1, s[nt][3] - mnc1));
        }

        // ---- rescale O and l ----
#pragma unroll
        for (int ni = 0; ni < 8; ni++) {
            o[ni][0] *= f0; o[ni][1] *= f0; o[ni][2] *= f1; o[ni][3] *= f1;
        }
        lac[0] *= f0; lac[1] *= f0; lac[2] *= f1; lac[3] *= f1;

        // ---- O += P @ V (trans ldmatrix); l += P @ 1 (constant frag) ----
#pragma unroll
        for (int t = 0; t < 8; t++) {
            const uint32_t* af = P32 + 4 * t;
            mma_f16(lac, af, ONES2, ONES2);
#pragma unroll
            for (int pi = 0; pi < 4; pi++) {
                uint32_t bf[4];
                ldsm4t(bf, bV + (uint32_t)(t * 2304) + (uint32_t)(pi * 32));
                mma_f16(o[pi * 2], af, bf[0], bf[1]);
                mma_f16(o[pi * 2 + 1], af, bf[2], bf[3]);
            }
        }
        __syncthreads();
        buf ^= 1;
    }

    // ---- finalize ----
    float l0 = lac[0], l1 = lac[2];
    float inv0 = (l0 > 0.0f) ? 1.0f / l0 : 0.0f;
    float inv1 = (l1 > 0.0f) ? 1.0f / l1 : 0.0f;
    int qrow = q0 + wq0 + r;
    size_t row0 = ((size_t)b * S_LEN + qrow) * DM + h * 64;
    size_t row1 = row0 + (size_t)8 * DM;
#pragma unroll
    for (int ni = 0; ni < 8; ni++) {
        int dh = ni * 8 + cq * 2;
        *(__half2*)(outMG + row0 + dh) = __floats2half2_rn(o[ni][0] * inv0, o[ni][1] * inv0);
        *(__half2*)(outMG + row1 + dh) = __floats2half2_rn(o[ni][2] * inv1, o[ni][3] * inv1);
    }
}

// ---------------- launch ----------------
extern "C" void kernel_launch(void* const* d_in, const int* in_sizes, int n_in,
                              void* d_out, int out_size) {
    const float* hidden = (const float*)d_in[0];
    const int*   mask   = (const int*)d_in[1];
    const float* wq = (const float*)d_in[2];  const float* bq = (const float*)d_in[3];
    const float* wk = (const float*)d_in[4];  const float* bk = (const float*)d_in[5];
    const float* wv = (const float*)d_in[6];  const float* bv = (const float*)d_in[7];
    const float* wo = (const float*)d_in[8];  const float* bo = (const float*)d_in[9];
    const float* rb = (const float*)d_in[10];
    const float* ln1g = (const float*)d_in[11]; const float* ln1b = (const float*)d_in[12];
    const float* ln2g = (const float*)d_in[13]; const float* ln2b = (const float*)d_in[14];
    const float* w1 = (const float*)d_in[15]; const float* b1 = (const float*)d_in[16];
    const float* w2 = (const float*)d_in[17]; const float* b2 = (const float*)d_in[18];
    float* out = (float*)d_out;

    __half *Xh, *QKVh, *MGh, *FFh, *WT;
    float *H1, *BT, *B3;
    cudaGetSymbolAddress((void**)&Xh,   g_Xh);
    cudaGetSymbolAddress((void**)&QKVh, g_QKVh);
    cudaGetSymbolAddress((void**)&MGh,  g_MGh);
    cudaGetSymbolAddress((void**)&FFh,  g_FFh);
    cudaGetSymbolAddress((void**)&H1,   g_H1);
    cudaGetSymbolAddress((void**)&BT,   g_BT);
    cudaGetSymbolAddress((void**)&B3,   g_B3);
    cudaGetSymbolAddress((void**)&WT,   g_WTH);

    cudaFuncSetAttribute(flash_kernel, cudaFuncAttributeMaxDynamicSharedMemorySize, FL_SMEM);
    cudaFuncSetAttribute(hgemm<EPI_QKV3>,  cudaFuncAttributeMaxDynamicSharedMemorySize, HG_SMEM);
    cudaFuncSetAttribute(hgemm<EPI_OPROJ>, cudaFuncAttributeMaxDynamicSharedMemorySize, HG_SMEM);
    cudaFuncSetAttribute(hgemm<EPI_GELU>,  cudaFuncAttributeMaxDynamicSharedMemorySize, HG_SMEM);
    cudaFuncSetAttribute(hgemm<EPI_FINAL>, cudaFuncAttributeMaxDynamicSharedMemorySize, HG_SMEM);

    const size_t M1 = 1024 * 1024;
    __half *Q = QKVh, *K = QKVh + QKVSZ, *V = QKVh + 2 * QKVSZ;

    // all weight transposes in one launch
    wtrans_all<<<12288, 256>>>(wq, wk, wv, wo, w1, w2, WT);
    // bias table + bias concat
    prep_kernel<<<(NH * S_LEN + 3 * DM + 255) / 256, 256>>>(rb, BT, bq, bk, bv, B3);
    ln_kernel<<<ROWS, 256>>>(hidden, ln1g, ln1b, Xh);

    // fused QKV projection (N=3072)
    dim3 gQKV(3 * DM / 128, ROWS / 128);
    hgemm<EPI_QKV3><<<gQKV, 256, HG_SMEM>>>(Xh, WT, B3, nullptr, QKVh, 3 * DM, DM, DM, DM, 0,
                                            nullptr, nullptr);

    // fused fp16 flash attention -> merged [B,S,D] fp16 (V in natural layout)
    flash_kernel<<<dim3(BATCH * NH, S_LEN / 128), 256, FL_SMEM>>>(Q, K, V, BT, mask, MGh);

    // O projection + mask + residual (fp32 out)
    dim3 gProj(DM / 128, ROWS / 128);
    hgemm<EPI_OPROJ><<<gProj, 256, HG_SMEM>>>(MGh, WT + 3 * M1, bo, H1, nullptr, DM, DM, DM, DM, DM,
                                              hidden, mask);

    ln_kernel<<<ROWS, 256>>>(H1, ln2g, ln2b, Xh);

    // FFN up + exact GELU -> fp16
    dim3 gF1(DFF / 128, ROWS / 128);
    hgemm<EPI_GELU><<<gF1, 256, HG_SMEM>>>(Xh, WT + 4 * M1, b1, nullptr, FFh, DFF, DM, DM, DM, DFF,
                                           nullptr, nullptr);

    // FFN down + residual + mask -> fp32 out
    hgemm<EPI_FINAL><<<gProj, 256, HG_SMEM>>>(FFh, WT + 8 * M1, b2, out, nullptr, DM, DFF, DFF, DFF, DM,
                                              H1, mask);
}